// round 10
// baseline (speedup 1.0000x reference)
#include <cuda_runtime.h>
#include <math.h>
#include <stdint.h>
#include <stddef.h>

#define R_RAYS 1024
static constexpr size_t NPTS = 131072;

// ---- scratch layout (floats). float2 regions hold interleaved (hi,lo). ----
constexpr size_t O_Z      = 0;
constexpr size_t O_SDF    = O_Z + NPTS;
constexpr size_t O_ZT     = O_SDF + NPTS;
constexpr size_t O_SDFT   = O_ZT + NPTS;
constexpr size_t O_ZNEW   = O_SDFT + NPTS;
constexpr size_t O_SDFNEW = O_ZNEW + 16384;
constexpr size_t O_PTS    = O_SDFNEW + 16384;
constexpr size_t O_DIST   = O_PTS + NPTS * 3;
constexpr size_t O_E      = O_DIST + NPTS;            // float2 x39
constexpr size_t O_H0     = O_E + NPTS * 78;          // float2 x256
constexpr size_t O_H1     = O_H0 + NPTS * 512;
constexpr size_t O_H2     = O_H1 + NPTS * 512;
constexpr size_t O_H3     = O_H2 + NPTS * 512;        // float2 x217
constexpr size_t O_H4     = O_H3 + NPTS * 434;        // float2 x256
constexpr size_t O_H5     = O_H4 + NPTS * 512;
constexpr size_t O_H6     = O_H5 + NPTS * 512;
constexpr size_t O_H7     = O_H6 + NPTS * 512;
constexpr size_t O_OUT8   = O_H7 + NPTS * 512;        // f32 x257
constexpr size_t O_B0     = O_OUT8 + NPTS * 257;      // float2 x265
constexpr size_t O_B1     = O_B0 + NPTS * 530;        // float2 x265
constexpr size_t O_GE     = O_B1 + NPTS * 530;        // f32 x39
constexpr size_t O_GRAD   = O_GE + NPTS * 39;
constexpr size_t O_ALPHA  = O_GRAD + NPTS * 3;
constexpr size_t O_WT     = O_ALPHA + NPTS;
constexpr size_t O_RGBS   = O_WT + NPTS;

constexpr size_t WSZ[12] = {
    39*256, 256*256, 256*256, 256*217, 256*256, 256*256,
    256*256, 256*256, 256*257, 265*256, 256*256, 256*3
};
constexpr size_t woff(int i) { size_t o = 0; for (int j = 0; j < i; j++) o += WSZ[j]; return o; }
constexpr size_t WTOT = woff(12);
constexpr size_t O_W2 = O_RGBS + NPTS * 3;            // float2 weights pool
constexpr size_t SCRATCH_TOTAL = O_W2 + WTOT * 2;

__device__ __align__(256) float d_SCRATCH[SCRATCH_TOTAL];

__device__ __forceinline__ float sigmoidf_(float x) { return 1.0f / (1.0f + expf(-x)); }

// truncation split: hi keeps top 19 bits (what tf32 MMA reads); lo = v-hi exact.
__device__ __forceinline__ float2 fsplit(float v) {
    uint32_t hu = __float_as_uint(v) & 0xffffe000u;
    float h = __uint_as_float(hu);
    return make_float2(h, v - h);
}
__device__ __forceinline__ float fjoin(float2 p) { return p.x + p.y; }

__device__ __forceinline__ uint32_t s2u(const void* p) {
    return (uint32_t)__cvta_generic_to_shared(p);
}
__device__ __forceinline__ void cpa16(uint32_t d, const void* s, int sz) {
    asm volatile("cp.async.ca.shared.global [%0], [%1], 16, %2;" :: "r"(d), "l"(s), "r"(sz));
}
__device__ __forceinline__ void cpa8(uint32_t d, const void* s, int sz) {
    asm volatile("cp.async.ca.shared.global [%0], [%1], 8, %2;" :: "r"(d), "l"(s), "r"(sz));
}
#define CP_COMMIT() asm volatile("cp.async.commit_group;")
#define CP_WAIT1()  asm volatile("cp.async.wait_group 1;")

// weight pre-split: interleaved float2(hi, lo)
__global__ void k_wsplit2(const float* __restrict__ W, float2* __restrict__ W2, int n)
{
    int i = blockIdx.x * blockDim.x + threadIdx.x;
    if (i < n) W2[i] = fsplit(W[i]);
}

// ============================================================================
// TF32x3 GEMM on PRE-SPLIT operands. A2/B2 are interleaved (hi,lo) float2.
// C = epi(A @ B + bias). TRB=0: B[K,N]; TRB=1: B[N,K] (C = A @ B^T).
// EPI: 0 lin, 1 softplus(100x)/100, 2 relu, 3 *(-expm1(-100*join(Hm2))).
// OSPLIT: 1 -> C is float2 (hi,lo); 0 -> C is f32.
// kTile=16, 2-stage cp.async; CTA 128x128; 8 warps 4x2; 2 CTAs/SM pinned.
// SMEM: A[2][128][18] float2 + B[2][128][18] float2 (B stored [n][k]).
// ============================================================================
template <int EPI, int TRB, int OSPLIT>
__global__ void __launch_bounds__(256, 2) gemm_tc(
    const float2* __restrict__ A2, const float2* __restrict__ B2,
    const float* __restrict__ bias, const float2* __restrict__ Hm2,
    void* __restrict__ Cout, int M, int N, int K)
{
    extern __shared__ float2 sm2[];
    constexpr int P = 18;              // pitch in float2 (16 + 2 pad); 144B rows
    constexpr int TILE = 128 * P;      // 2304 float2
    float2* As0 = sm2;
    float2* As1 = sm2 + TILE;
    float2* Bs0 = sm2 + 2 * TILE;
    float2* Bs1 = sm2 + 3 * TILE;

    const int tid  = threadIdx.x;
    const int wid  = tid >> 5;
    const int lane = tid & 31;
    const int wm = wid & 3;
    const int wn = wid >> 2;
    const int m0 = blockIdx.y * 128;
    const int n0 = blockIdx.x * 128;
    const int r  = lane >> 2;
    const int cq = lane & 3;
    const bool evK = (K & 1) == 0;

    float acc[2][8][4] = {};
    const int nsteps = (K + 15) >> 4;

    auto load_stage = [&](float2* Asx, float2* Bsx, int k0) {
        // ---- A: 128 rows x 16 k (float2 each)
        if (evK) {
            int row = tid >> 1;
            int c0  = (tid & 1) * 8;
            int gm  = m0 + row;
            const float2* src = A2 + ((gm < M) ? ((size_t)gm * K + k0 + c0) : 0);
            float2* dst = Asx + row * P + c0;
#pragma unroll
            for (int c = 0; c < 8; c += 2) {
                int rem = (gm < M) ? (K - (k0 + c0 + c)) : 0;
                rem = rem > 2 ? 2 : (rem < 0 ? 0 : rem);
                cpa16(s2u(dst + c), src + c, rem * 8);
            }
        } else {
#pragma unroll
            for (int e = 0; e < 8; e++) {
                int idx = tid + e * 256;           // 0..2047
                int row = idx >> 4, kk = idx & 15;
                int gm = m0 + row;
                int ok = (gm < M && (k0 + kk) < K) ? 8 : 0;
                cpa8(s2u(Asx + row * P + kk), A2 + (size_t)(gm < M ? gm : 0) * K + k0 + kk, ok);
            }
        }
        // ---- B -> Bs[n][k]
        if (TRB == 1 && evK) {
            int nn = tid >> 1;
            int c0 = (tid & 1) * 8;
            int gn = n0 + nn;
            const float2* src = B2 + ((gn < N) ? ((size_t)gn * K + k0 + c0) : 0);
            float2* dst = Bsx + nn * P + c0;
#pragma unroll
            for (int c = 0; c < 8; c += 2) {
                int rem = (gn < N) ? (K - (k0 + c0 + c)) : 0;
                rem = rem > 2 ? 2 : (rem < 0 ? 0 : rem);
                cpa16(s2u(dst + c), src + c, rem * 8);
            }
        } else if (TRB == 1) {
#pragma unroll
            for (int e = 0; e < 8; e++) {
                int idx = tid + e * 256;
                int nn = idx >> 4, kk = idx & 15;
                int gn = n0 + nn;
                int ok = (gn < N && (k0 + kk) < K) ? 8 : 0;
                cpa8(s2u(Bsx + nn * P + kk), B2 + (size_t)(gn < N ? gn : 0) * K + k0 + kk, ok);
            }
        } else {
            // TRB=0: global [K,N], transpose into [n][k] via 8B copies
#pragma unroll
            for (int e = 0; e < 8; e++) {
                int idx = tid + e * 256;
                int kk = idx >> 7, nn = idx & 127;
                int gk = k0 + kk, gn = n0 + nn;
                int ok = (gk < K && gn < N) ? 8 : 0;
                cpa8(s2u(Bsx + nn * P + kk), B2 + (size_t)(gk < K ? gk : 0) * N + (gn < N ? gn : 0), ok);
            }
        }
    };

    load_stage(As0, Bs0, 0);
    CP_COMMIT();

    for (int s = 0; s < nsteps; s++) {
        if (s + 1 < nsteps)
            load_stage(((s + 1) & 1) ? As1 : As0, ((s + 1) & 1) ? Bs1 : Bs0, (s + 1) * 16);
        CP_COMMIT();
        CP_WAIT1();
        __syncthreads();

        const float2* Ast = (s & 1) ? As1 : As0;
        const float2* Bst = (s & 1) ? Bs1 : Bs0;

#pragma unroll
        for (int k8 = 0; k8 < 16; k8 += 8) {
            uint32_t aH[2][4], aL[2][4];
#pragma unroll
            for (int i = 0; i < 2; i++) {
                int rb = wm * 32 + i * 16 + r;
                float2 t0 = Ast[rb * P + k8 + cq];
                float2 t1 = Ast[(rb + 8) * P + k8 + cq];
                float2 t2 = Ast[rb * P + k8 + cq + 4];
                float2 t3 = Ast[(rb + 8) * P + k8 + cq + 4];
                aH[i][0] = __float_as_uint(t0.x); aL[i][0] = __float_as_uint(t0.y);
                aH[i][1] = __float_as_uint(t1.x); aL[i][1] = __float_as_uint(t1.y);
                aH[i][2] = __float_as_uint(t2.x); aL[i][2] = __float_as_uint(t2.y);
                aH[i][3] = __float_as_uint(t3.x); aL[i][3] = __float_as_uint(t3.y);
            }
#pragma unroll
            for (int j = 0; j < 8; j++) {
                int cb = wn * 64 + j * 8 + r;
                float2 b0 = Bst[cb * P + k8 + cq];
                float2 b1 = Bst[cb * P + k8 + cq + 4];
                uint32_t bH0 = __float_as_uint(b0.x), bL0 = __float_as_uint(b0.y);
                uint32_t bH1 = __float_as_uint(b1.x), bL1 = __float_as_uint(b1.y);
#pragma unroll
                for (int i = 0; i < 2; i++) {
                    asm volatile(
                        "mma.sync.aligned.m16n8k8.row.col.f32.tf32.tf32.f32 "
                        "{%0,%1,%2,%3}, {%4,%5,%6,%7}, {%8,%9}, {%0,%1,%2,%3};"
                        : "+f"(acc[i][j][0]), "+f"(acc[i][j][1]),
                          "+f"(acc[i][j][2]), "+f"(acc[i][j][3])
                        : "r"(aH[i][0]), "r"(aH[i][1]), "r"(aH[i][2]), "r"(aH[i][3]),
                          "r"(bL0), "r"(bL1));
                    asm volatile(
                        "mma.sync.aligned.m16n8k8.row.col.f32.tf32.tf32.f32 "
                        "{%0,%1,%2,%3}, {%4,%5,%6,%7}, {%8,%9}, {%0,%1,%2,%3};"
                        : "+f"(acc[i][j][0]), "+f"(acc[i][j][1]),
                          "+f"(acc[i][j][2]), "+f"(acc[i][j][3])
                        : "r"(aL[i][0]), "r"(aL[i][1]), "r"(aL[i][2]), "r"(aL[i][3]),
                          "r"(bH0), "r"(bH1));
                    asm volatile(
                        "mma.sync.aligned.m16n8k8.row.col.f32.tf32.tf32.f32 "
                        "{%0,%1,%2,%3}, {%4,%5,%6,%7}, {%8,%9}, {%0,%1,%2,%3};"
                        : "+f"(acc[i][j][0]), "+f"(acc[i][j][1]),
                          "+f"(acc[i][j][2]), "+f"(acc[i][j][3])
                        : "r"(aH[i][0]), "r"(aH[i][1]), "r"(aH[i][2]), "r"(aH[i][3]),
                          "r"(bH0), "r"(bH1));
                }
            }
        }
        __syncthreads();
    }

    // ---- epilogue
#pragma unroll
    for (int i = 0; i < 2; i++) {
        int row0 = m0 + wm * 32 + i * 16 + r;
#pragma unroll
        for (int j = 0; j < 8; j++) {
            int col0 = n0 + wn * 64 + j * 8 + cq * 2;
#pragma unroll
            for (int t = 0; t < 4; t++) {
                int row = row0 + (t >> 1) * 8;
                int col = col0 + (t & 1);
                if (row < M && col < N) {
                    float v = acc[i][j][t];
                    if (bias) v += bias[col];
                    if (EPI == 1) {
                        float s = 100.0f * v;
                        v = (fmaxf(s, 0.0f) + log1pf(expf(-fabsf(s)))) * 0.01f;
                    } else if (EPI == 2) {
                        v = fmaxf(v, 0.0f);
                    } else if (EPI == 3) {
                        v = v * (-expm1f(-100.0f * fjoin(Hm2[(size_t)row * N + col])));
                    }
                    if (OSPLIT) ((float2*)Cout)[(size_t)row * N + col] = fsplit(v);
                    else        ((float*)Cout)[(size_t)row * N + col] = v;
                }
            }
        }
    }
}

// ===================== small kernels =====================

__global__ void k_ray_init(const float* __restrict__ ro, const float* __restrict__ rd,
                           float* __restrict__ Z)
{
    int r = blockIdx.x * blockDim.x + threadIdx.x;
    if (r >= R_RAYS) return;
    float ox = ro[r*3], oy = ro[r*3+1], oz = ro[r*3+2];
    float dx = rd[r*3], dy = rd[r*3+1], dz = rd[r*3+2];
    float a = dx*dx + dy*dy + dz*dz;
    float b = 2.0f * (ox*dx + oy*dy + oz*dz);
    float mid = -b / (2.0f * a);
    float nv = fmaxf(mid - 1.0f, 0.05f);
    float fv = mid + 1.0f;
    for (int s = 0; s < 64; s++)
        Z[r*64 + s] = nv + (fv - nv) * ((float)s * (1.0f/63.0f));
}

__global__ void k_pts(const float* __restrict__ Z, const float* __restrict__ ro,
                      const float* __restrict__ rd, float* __restrict__ P, int S, int M)
{
    int m = blockIdx.x * blockDim.x + threadIdx.x;
    if (m >= M) return;
    int r = m / S;
    float z = Z[m];
#pragma unroll
    for (int j = 0; j < 3; j++)
        P[(size_t)m*3 + j] = fmaf(rd[r*3+j], z, ro[r*3+j]);
}

__global__ void k_dist_mid_pts(const float* __restrict__ Z, const float* __restrict__ ro,
                               const float* __restrict__ rd, float* __restrict__ P,
                               float* __restrict__ D)
{
    int m = blockIdx.x * blockDim.x + threadIdx.x;
    if (m >= (int)NPTS) return;
    int s = m & 127, r = m >> 7;
    float z = Z[m];
    float d = (s < 127) ? (Z[m+1] - z) : 0.03125f;
    D[m] = d;
    float mz = fmaf(0.5f, d, z);
#pragma unroll
    for (int j = 0; j < 3; j++)
        P[(size_t)m*3 + j] = fmaf(rd[r*3+j], mz, ro[r*3+j]);
}

__global__ void k_embed(const float* __restrict__ P, float2* __restrict__ E2, int M)
{
    int m = blockIdx.x * blockDim.x + threadIdx.x;
    if (m >= M) return;
    float p0 = P[(size_t)m*3], p1 = P[(size_t)m*3+1], p2 = P[(size_t)m*3+2];
    float2* e = E2 + (size_t)m*39;
    e[0] = fsplit(p0); e[1] = fsplit(p1); e[2] = fsplit(p2);
    float f = 1.0f;
#pragma unroll
    for (int k = 0; k < 6; k++) {
        float s0,c0,s1,c1,s2,c2;
        sincosf(f*p0,&s0,&c0); sincosf(f*p1,&s1,&c1); sincosf(f*p2,&s2,&c2);
        e[3+6*k+0]=fsplit(s0); e[3+6*k+1]=fsplit(s1); e[3+6*k+2]=fsplit(s2);
        e[3+6*k+3]=fsplit(c0); e[3+6*k+4]=fsplit(c1); e[3+6*k+5]=fsplit(c2);
        f *= 2.0f;
    }
}

__global__ void k_concat(const float2* __restrict__ H3, const float2* __restrict__ E2,
                         float2* __restrict__ O2, int M)
{
    int idx = blockIdx.x * blockDim.x + threadIdx.x;
    if (idx >= M * 256) return;
    int m = idx >> 8, c = idx & 255;
    float v = (c < 217) ? fjoin(H3[(size_t)m*217 + c]) : fjoin(E2[(size_t)m*39 + (c-217)]);
    O2[idx] = fsplit(v * 0.7071067811865476f);
}

__global__ void k_sdf_head(const float2* __restrict__ H2, const float* __restrict__ W8,
                           const float* __restrict__ b8, float* __restrict__ out, int M)
{
    int gw = (blockIdx.x * blockDim.x + threadIdx.x) >> 5;
    int lane = threadIdx.x & 31;
    if (gw >= M) return;
    const float2* h = H2 + (size_t)gw * 256;
    float s = 0.0f;
#pragma unroll
    for (int k = lane; k < 256; k += 32) s = fmaf(fjoin(h[k]), W8[(size_t)k*257], s);
#pragma unroll
    for (int o = 16; o; o >>= 1) s += __shfl_xor_sync(0xffffffffu, s, o);
    if (!lane) out[gw] = s + b8[0];
}

__global__ void k_upsample(const float* __restrict__ ro, const float* __restrict__ rd,
                           const float* __restrict__ Z, const float* __restrict__ SD,
                           float* __restrict__ ZN, int S, float inv_s)
{
    int r = blockIdx.x * blockDim.x + threadIdx.x;
    if (r >= R_RAYS) return;
    float ox = ro[r*3], oy = ro[r*3+1], oz = ro[r*3+2];
    float dx = rd[r*3], dy = rd[r*3+1], dz = rd[r*3+2];
    const float* zr = Z + (size_t)r * S;
    const float* sr = SD + (size_t)r * S;

    float w[128], cdf[129];
    float prev_raw = 0.0f, T = 1.0f, wsum = 0.0f;
    float z_i = zr[0];
    float px = fmaf(dx,z_i,ox), py = fmaf(dy,z_i,oy), pz = fmaf(dz,z_i,oz);
    float rad_i = sqrtf(px*px + py*py + pz*pz);
    float sdf_i = sr[0];

    for (int i = 0; i < S - 1; i++) {
        float z_n = zr[i+1], sdf_n = sr[i+1];
        float qx = fmaf(dx,z_n,ox), qy = fmaf(dy,z_n,oy), qz = fmaf(dz,z_n,oz);
        float rad_n = sqrtf(qx*qx + qy*qy + qz*qz);
        bool inside = (rad_i < 1.0f) || (rad_n < 1.0f);
        float mid_sdf = 0.5f * (sdf_i + sdf_n);
        float raw = (sdf_n - sdf_i) / (z_n - z_i + 1e-5f);
        float cosv = fminf(raw, prev_raw);
        prev_raw = raw;
        cosv = fminf(fmaxf(cosv, -1000.0f), 0.0f);
        if (!inside) cosv = 0.0f;
        float dist = z_n - z_i;
        float pc = sigmoidf_((mid_sdf - cosv*dist*0.5f) * inv_s);
        float nc = sigmoidf_((mid_sdf + cosv*dist*0.5f) * inv_s);
        float alpha = (pc - nc + 1e-5f) / (pc + 1e-5f);
        float wi = alpha * T;
        T *= (1.0f - alpha + 1e-7f);
        wi += 1e-5f;
        w[i] = wi; wsum += wi;
        z_i = z_n; rad_i = rad_n; sdf_i = sdf_n;
    }

    cdf[0] = 0.0f;
    float invsum = 1.0f / wsum;
    for (int i = 0; i < S - 1; i++) cdf[i+1] = cdf[i] + w[i] * invsum;

    for (int j = 0; j < 16; j++) {
        float u = 0.03125f + (float)j * 0.0625f;
        int lo = 0, hi = S;
        while (lo < hi) { int md = (lo + hi) >> 1; if (cdf[md] <= u) lo = md + 1; else hi = md; }
        int below = lo - 1; if (below < 0) below = 0; if (below > S-1) below = S-1;
        int above = lo;     if (above > S-1) above = S-1;
        float c0 = cdf[below], c1 = cdf[above];
        float b0 = zr[below],  b1 = zr[above];
        float den = (c1 - c0) < 1e-5f ? 1.0f : (c1 - c0);
        ZN[r*16 + j] = b0 + (u - c0) / den * (b1 - b0);
    }
}

__global__ void k_merge(const float* __restrict__ Z, const float* __restrict__ SD,
                        const float* __restrict__ ZN, const float* __restrict__ SN,
                        float* __restrict__ ZT, float* __restrict__ ST, int S)
{
    int r = blockIdx.x * blockDim.x + threadIdx.x;
    if (r >= R_RAYS) return;
    const float* zo = Z + (size_t)r*S;  const float* so = SD + (size_t)r*S;
    const float* zn = ZN + r*16;        const float* sn = SN + r*16;
    float* zt = ZT + (size_t)r*(S+16);  float* st = ST + (size_t)r*(S+16);
    int i = 0, j = 0;
    for (int k = 0; k < S + 16; k++) {
        bool useOld = (i < S) && ((j >= 16) || (zo[i] <= zn[j]));
        if (useOld) { zt[k] = zo[i]; st[k] = so[i]; i++; }
        else        { zt[k] = zn[j]; st[k] = sn[j]; j++; }
    }
}

__global__ void k_copy(float* __restrict__ dst, const float* __restrict__ src, int n)
{
    int i = blockIdx.x * blockDim.x + threadIdx.x;
    if (i < n) dst[i] = src[i];
}

__global__ void k_bwinit(const float2* __restrict__ H7, const float* __restrict__ W8,
                         float2* __restrict__ G2, int M)
{
    int idx = blockIdx.x * blockDim.x + threadIdx.x;
    if (idx >= M * 256) return;
    int c = idx & 255;
    G2[idx] = fsplit(W8[(size_t)c * 257] * (-expm1f(-100.0f * fjoin(H7[idx]))));
}

__global__ void k_split(const float2* __restrict__ Gin4, const float2* __restrict__ H3,
                        float2* __restrict__ Gz3, float* __restrict__ GE, int M)
{
    int idx = blockIdx.x * blockDim.x + threadIdx.x;
    if (idx >= M * 256) return;
    int m = idx >> 8, c = idx & 255;
    float v = fjoin(Gin4[idx]) * 0.7071067811865476f;
    if (c < 217)
        Gz3[(size_t)m*217 + c] = fsplit(v * (-expm1f(-100.0f * fjoin(H3[(size_t)m*217 + c]))));
    else
        GE[(size_t)m*39 + (c - 217)] = v;
}

__global__ void k_gradpts(const float2* __restrict__ GEm, const float* __restrict__ GEs,
                          const float* __restrict__ P, float* __restrict__ GR, int M)
{
    int m = blockIdx.x * blockDim.x + threadIdx.x;
    if (m >= M) return;
    const float2* ga = GEm + (size_t)m*39;
    const float* gb = GEs + (size_t)m*39;
    float p[3] = {P[(size_t)m*3], P[(size_t)m*3+1], P[(size_t)m*3+2]};
    float g[3];
#pragma unroll
    for (int j = 0; j < 3; j++) g[j] = fjoin(ga[j]) + gb[j];
    float f = 1.0f;
#pragma unroll
    for (int k = 0; k < 6; k++) {
#pragma unroll
        for (int j = 0; j < 3; j++) {
            float s, c;
            sincosf(f * p[j], &s, &c);
            float gs = fjoin(ga[3+6*k+j])   + gb[3+6*k+j];
            float gc = fjoin(ga[3+6*k+3+j]) + gb[3+6*k+3+j];
            g[j] = fmaf( f * c, gs, g[j]);
            g[j] = fmaf(-f * s, gc, g[j]);
        }
        f *= 2.0f;
    }
#pragma unroll
    for (int j = 0; j < 3; j++) GR[(size_t)m*3 + j] = g[j];
}

__global__ void k_alpha(const float* __restrict__ OUT8, const float* __restrict__ GR,
                        const float* __restrict__ D, const float* __restrict__ rd,
                        const float* __restrict__ var, float* __restrict__ A, int M)
{
    int m = blockIdx.x * blockDim.x + threadIdx.x;
    if (m >= M) return;
    int r = m >> 7;
    float tc = rd[r*3]*GR[(size_t)m*3] + rd[r*3+1]*GR[(size_t)m*3+1] + rd[r*3+2]*GR[(size_t)m*3+2];
    float ic = fminf(tc, 0.0f);
    float sdf = OUT8[(size_t)m * 257];
    float dist = D[m];
    float inv_s = fminf(fmaxf(expf(10.0f * var[0]), 1e-6f), 1e6f);
    float pc = sigmoidf_((sdf - ic*dist*0.5f) * inv_s);
    float nc = sigmoidf_((sdf + ic*dist*0.5f) * inv_s);
    float a = (pc - nc + 1e-5f) / (pc + 1e-5f);
    A[m] = fminf(fmaxf(a, 0.0f), 1.0f);
}

__global__ void k_ray_weights(const float* __restrict__ A, float* __restrict__ W)
{
    int r = blockIdx.x * blockDim.x + threadIdx.x;
    if (r >= R_RAYS) return;
    float T = 1.0f;
    for (int s = 0; s < 128; s++) {
        int m = r*128 + s;
        float a = A[m];
        W[m] = a * T;
        T *= (1.0f - a + 1e-7f);
    }
}

__global__ void k_cin(const float* __restrict__ P, const float* __restrict__ rd,
                      const float* __restrict__ GR, const float* __restrict__ OUT8,
                      float2* __restrict__ CIN2, int M)
{
    int idx = blockIdx.x * blockDim.x + threadIdx.x;
    if (idx >= M * 265) return;
    int m = idx / 265, c = idx % 265;
    float v;
    if (c < 3) v = P[(size_t)m*3 + c];
    else if (c < 6) { int r = m >> 7; v = rd[r*3 + (c-3)]; }
    else if (c < 9) {
        float g0 = GR[(size_t)m*3], g1 = GR[(size_t)m*3+1], g2 = GR[(size_t)m*3+2];
        float n = fmaxf(sqrtf(g0*g0 + g1*g1 + g2*g2), 1e-6f);
        v = GR[(size_t)m*3 + (c-6)] / n;
    } else v = OUT8[(size_t)m*257 + 1 + (c-9)];
    CIN2[idx] = fsplit(v);
}

__global__ void k_color_head(const float2* __restrict__ H2, const float* __restrict__ W,
                             const float* __restrict__ b, float* __restrict__ rgbs, int M)
{
    int gw = (blockIdx.x * blockDim.x + threadIdx.x) >> 5;
    int lane = threadIdx.x & 31;
    if (gw >= M) return;
    const float2* h = H2 + (size_t)gw * 256;
    float a0 = 0.f, a1 = 0.f, a2 = 0.f;
#pragma unroll
    for (int k = lane; k < 256; k += 32) {
        float hv = fjoin(h[k]);
        a0 = fmaf(hv, W[k*3+0], a0);
        a1 = fmaf(hv, W[k*3+1], a1);
        a2 = fmaf(hv, W[k*3+2], a2);
    }
#pragma unroll
    for (int o = 16; o; o >>= 1) {
        a0 += __shfl_xor_sync(0xffffffffu, a0, o);
        a1 += __shfl_xor_sync(0xffffffffu, a1, o);
        a2 += __shfl_xor_sync(0xffffffffu, a2, o);
    }
    if (!lane) {
        rgbs[(size_t)gw*3+0] = sigmoidf_(a0 + b[0]);
        rgbs[(size_t)gw*3+1] = sigmoidf_(a1 + b[1]);
        rgbs[(size_t)gw*3+2] = sigmoidf_(a2 + b[2]);
    }
}

__global__ void k_reduce(const float* __restrict__ W, const float* __restrict__ rgbs,
                         float* __restrict__ out)
{
    int r = blockIdx.x * blockDim.x + threadIdx.x;
    if (r >= R_RAYS) return;
    float s0 = 0.f, s1 = 0.f, s2 = 0.f;
    for (int s = 0; s < 128; s++) {
        int m = r*128 + s;
        float w = W[m];
        s0 = fmaf(w, rgbs[(size_t)m*3+0], s0);
        s1 = fmaf(w, rgbs[(size_t)m*3+1], s1);
        s2 = fmaf(w, rgbs[(size_t)m*3+2], s2);
    }
    out[r*3+0] = s0; out[r*3+1] = s1; out[r*3+2] = s2;
}

// ===================== host orchestration =====================

static const int GEMM_SHM = 73728;

template <int EPI, int TRB, int OSPLIT>
static void launch_one(const float2* A2, const float2* B2, const float* bias,
                       const float2* Hm2, void* C, int M, int N, int K)
{
    dim3 g((N + 127) / 128, (M + 127) / 128);
    cudaFuncSetAttribute(gemm_tc<EPI,TRB,OSPLIT>,
                         cudaFuncAttributeMaxDynamicSharedMemorySize, GEMM_SHM);
    gemm_tc<EPI,TRB,OSPLIT><<<g, 256, GEMM_SHM>>>(A2, B2, bias, Hm2, C, M, N, K);
}

struct Ctx {
    float2* W2[12];
    const float* sb[9];
    const float* cb[3];
    const float* sw8raw;
    const float* cw2raw;
};

static void sdf_forward_nostore(int M, const Ctx& X, float* base, float* sdf_dest)
{
    float2* PE  = (float2*)(base + O_E);
    float2* PB0 = (float2*)(base + O_B0);
    float2* PB1 = (float2*)(base + O_B1);
    float* PP   = base + O_PTS;
    k_embed<<<(M+255)/256, 256>>>(PP, PE, M);
    launch_one<1,0,1>(PE,  X.W2[0], X.sb[0], nullptr, PB1, M, 256, 39);
    launch_one<1,0,1>(PB1, X.W2[1], X.sb[1], nullptr, PB0, M, 256, 256);
    launch_one<1,0,1>(PB0, X.W2[2], X.sb[2], nullptr, PB1, M, 256, 256);
    launch_one<1,0,1>(PB1, X.W2[3], X.sb[3], nullptr, PB0, M, 217, 256);
    k_concat<<<(M*256+255)/256, 256>>>(PB0, PE, PB1, M);
    launch_one<1,0,1>(PB1, X.W2[4], X.sb[4], nullptr, PB0, M, 256, 256);
    launch_one<1,0,1>(PB0, X.W2[5], X.sb[5], nullptr, PB1, M, 256, 256);
    launch_one<1,0,1>(PB1, X.W2[6], X.sb[6], nullptr, PB0, M, 256, 256);
    launch_one<1,0,1>(PB0, X.W2[7], X.sb[7], nullptr, PB1, M, 256, 256);
    k_sdf_head<<<(M*32+255)/256, 256>>>(PB1, X.sw8raw, X.sb[8], sdf_dest, M);
}

extern "C" void kernel_launch(void* const* d_in, const int* in_sizes, int n_in,
                              void* d_out, int out_size)
{
    const float* ro = (const float*)d_in[0];
    const float* rd = (const float*)d_in[1];
    const float* sw[9]; const float* sb[9];
    const float* cw[3]; const float* cb[3];
    const float* var;

    bool interleaved = (in_sizes[3] < 1024);
    if (interleaved) {
        for (int l = 0; l < 9; l++) { sw[l] = (const float*)d_in[2 + 2*l]; sb[l] = (const float*)d_in[3 + 2*l]; }
        for (int l = 0; l < 3; l++) { cw[l] = (const float*)d_in[20 + 2*l]; cb[l] = (const float*)d_in[21 + 2*l]; }
        var = (const float*)d_in[26];
    } else {
        for (int l = 0; l < 9; l++) { sw[l] = (const float*)d_in[2 + l]; sb[l] = (const float*)d_in[11 + l]; }
        for (int l = 0; l < 3; l++) { cw[l] = (const float*)d_in[20 + l]; cb[l] = (const float*)d_in[23 + l]; }
        var = (const float*)d_in[26];
    }
    float* out = (float*)d_out;

    float* base = nullptr;
    cudaGetSymbolAddress((void**)&base, d_SCRATCH);

    float* PZ = base+O_Z;     float* PSDF = base+O_SDF;
    float* PZT = base+O_ZT;   float* PSDFT = base+O_SDFT;
    float* PZN = base+O_ZNEW; float* PSDFN = base+O_SDFNEW;
    float* PP = base+O_PTS;   float* PD = base+O_DIST;
    float2* PE  = (float2*)(base+O_E);
    float2* PH0 = (float2*)(base+O_H0); float2* PH1 = (float2*)(base+O_H1);
    float2* PH2 = (float2*)(base+O_H2); float2* PH3 = (float2*)(base+O_H3);
    float2* PH4 = (float2*)(base+O_H4); float2* PH5 = (float2*)(base+O_H5);
    float2* PH6 = (float2*)(base+O_H6); float2* PH7 = (float2*)(base+O_H7);
    float* PO8  = base+O_OUT8;
    float2* PB0 = (float2*)(base+O_B0); float2* PB1 = (float2*)(base+O_B1);
    float* PGE = base+O_GE; float* PGR = base+O_GRAD;
    float* PA = base+O_ALPHA; float* PW = base+O_WT; float* PRGB = base+O_RGBS;

    // ---- pre-split all 12 weight matrices (interleaved hi/lo) ----
    const float* wsrc[12] = { sw[0], sw[1], sw[2], sw[3], sw[4], sw[5],
                              sw[6], sw[7], sw[8], cw[0], cw[1], cw[2] };
    Ctx X;
    {
        float2* w2base = (float2*)(base + O_W2);
        size_t off = 0;
        for (int i = 0; i < 12; i++) {
            int n = (int)WSZ[i];
            k_wsplit2<<<(n+255)/256, 256>>>(wsrc[i], w2base + off, n);
            X.W2[i] = w2base + off;
            off += WSZ[i];
        }
    }
    for (int l = 0; l < 9; l++) X.sb[l] = sb[l];
    for (int l = 0; l < 3; l++) X.cb[l] = cb[l];
    X.sw8raw = sw[8]; X.cw2raw = cw[2];

    // ---- initial 64 samples + sdf ----
    k_ray_init<<<4, 256>>>(ro, rd, PZ);
    int S = 64;
    int M = R_RAYS * S;
    k_pts<<<(M+255)/256, 256>>>(PZ, ro, rd, PP, S, M);
    sdf_forward_nostore(M, X, base, PSDF);

    // ---- 4 importance-sampling rounds ----
    for (int i = 0; i < 4; i++) {
        float inv_s = 64.0f * (float)(1 << i);
        k_upsample<<<4, 256>>>(ro, rd, PZ, PSDF, PZN, S, inv_s);
        int Mn = R_RAYS * 16;
        k_pts<<<(Mn+255)/256, 256>>>(PZN, ro, rd, PP, 16, Mn);
        sdf_forward_nostore(Mn, X, base, PSDFN);
        k_merge<<<4, 256>>>(PZ, PSDF, PZN, PSDFN, PZT, PSDFT, S);
        S += 16;
        int n = R_RAYS * S;
        k_copy<<<(n+255)/256, 256>>>(PZ, PZT, n);
        k_copy<<<(n+255)/256, 256>>>(PSDF, PSDFT, n);
    }

    // ---- final forward (stored activations) ----
    M = (int)NPTS;
    k_dist_mid_pts<<<(M+255)/256, 256>>>(PZ, ro, rd, PP, PD);
    k_embed<<<(M+255)/256, 256>>>(PP, PE, M);
    launch_one<1,0,1>(PE,  X.W2[0], sb[0], nullptr, PH0, M, 256, 39);
    launch_one<1,0,1>(PH0, X.W2[1], sb[1], nullptr, PH1, M, 256, 256);
    launch_one<1,0,1>(PH1, X.W2[2], sb[2], nullptr, PH2, M, 256, 256);
    launch_one<1,0,1>(PH2, X.W2[3], sb[3], nullptr, PH3, M, 217, 256);
    k_concat<<<(M*256+255)/256, 256>>>(PH3, PE, PH4, M);
    launch_one<1,0,1>(PH4, X.W2[4], sb[4], nullptr, PH5, M, 256, 256);   // h4
    launch_one<1,0,1>(PH5, X.W2[5], sb[5], nullptr, PH6, M, 256, 256);   // h5
    launch_one<1,0,1>(PH6, X.W2[6], sb[6], nullptr, PH7, M, 256, 256);   // h6
    launch_one<1,0,1>(PH7, X.W2[7], sb[7], nullptr, PB0, M, 256, 256);   // h7
    launch_one<0,0,0>(PB0, X.W2[8], sb[8], nullptr, PO8, M, 257, 256);   // out f32

    // ---- backward (VJP of sdf channel) ----
    // activations: h4=PH5, h5=PH6, h6=PH7, h7=PB0 (all float2)
    k_bwinit<<<(M*256+255)/256, 256>>>(PB0, sw[8], PB1, M);
    launch_one<3,1,1>(PB1, X.W2[7], nullptr, PH7, PB0, M, 256, 256);
    launch_one<3,1,1>(PB0, X.W2[6], nullptr, PH6, PB1, M, 256, 256);
    launch_one<3,1,1>(PB1, X.W2[5], nullptr, PH5, PB0, M, 256, 256);
    launch_one<0,1,1>(PB0, X.W2[4], nullptr, nullptr, PB1, M, 256, 256);
    k_split<<<(M*256+255)/256, 256>>>(PB1, PH3, PB0, PGE, M);
    launch_one<3,1,1>(PB0, X.W2[3], nullptr, PH2, PB1, M, 256, 217);
    launch_one<3,1,1>(PB1, X.W2[2], nullptr, PH1, PB0, M, 256, 256);
    launch_one<3,1,1>(PB0, X.W2[1], nullptr, PH0, PB1, M, 256, 256);
    launch_one<0,1,1>(PB1, X.W2[0], nullptr, nullptr, PB0, M, 39, 256);
    k_gradpts<<<(M+255)/256, 256>>>(PB0, PGE, PP, PGR, M);

    // ---- color net + compositing ----
    k_alpha<<<(M+255)/256, 256>>>(PO8, PGR, PD, rd, var, PA, M);
    k_ray_weights<<<4, 256>>>(PA, PW);
    k_cin<<<(M*265+255)/256, 256>>>(PP, rd, PGR, PO8, PB0, M);
    launch_one<2,0,1>(PB0, X.W2[9],  cb[0], nullptr, PB1, M, 256, 265);
    launch_one<2,0,1>(PB1, X.W2[10], cb[1], nullptr, PB0, M, 256, 256);
    k_color_head<<<(M*32+255)/256, 256>>>(PB0, cw[2], cb[2], PRGB, M);
    k_reduce<<<4, 256>>>(PW, PRGB, out);
}

// round 11
// speedup vs baseline: 1.6403x; 1.6403x over previous
#include <cuda_runtime.h>
#include <cuda_bf16.h>
#include <math.h>
#include <stdint.h>
#include <stddef.h>

typedef __nv_bfloat16 bf16;

#define R_RAYS 1024
static constexpr size_t NPTS = 131072;

// ================= f32 scratch =================
constexpr size_t O_Z      = 0;
constexpr size_t O_SDF    = O_Z + NPTS;
constexpr size_t O_ZT     = O_SDF + NPTS;
constexpr size_t O_SDFT   = O_ZT + NPTS;
constexpr size_t O_ZNEW   = O_SDFT + NPTS;
constexpr size_t O_SDFNEW = O_ZNEW + 16384;
constexpr size_t O_PTS    = O_SDFNEW + 16384;
constexpr size_t O_DIST   = O_PTS + NPTS * 3;
constexpr size_t O_OUT8   = O_DIST + NPTS;          // f32 [M][257]
constexpr size_t O_GE     = O_OUT8 + NPTS * 257;    // f32 [M][39] (skip grad)
constexpr size_t O_GEM    = O_GE + NPTS * 39;       // f32 [M][39] (main grad)
constexpr size_t O_GRAD   = O_GEM + NPTS * 39;
constexpr size_t O_ALPHA  = O_GRAD + NPTS * 3;
constexpr size_t O_WT     = O_ALPHA + NPTS;
constexpr size_t O_RGBS   = O_WT + NPTS;
constexpr size_t F32_TOTAL = O_RGBS + NPTS * 3;
__device__ __align__(256) float d_F32[F32_TOTAL];

// ================= bf16 plane scratch =================
// widths (all multiples of 8): E 40, H0..H2 256, H3 224, I4 256, A4..A7 256,
// GP 256, GQ 256, CIN 272.  Each buffer = HI plane then LO plane.
constexpr size_t AW[13] = {40,256,256,256,224,256,256,256,256,256,256,256,272};
constexpr size_t aoff(int i) { size_t o = 0; for (int j = 0; j < i; j++) o += AW[j] * 2; return o * NPTS; }
constexpr size_t BF_ACT_TOTAL = aoff(13);
// weight plane buffers: {N, Kp} pairs; HI then LO.
// 0..8: fwd transposed sw0..sw8; 9,10: cw0,cw1 transposed;
// 11..17: bwd natural sw7,sw6,sw5,sw4,sw3,sw2,sw1; 18: bwd natural sw0.
constexpr size_t WN[19] = {256,256,256,217,256,256,256,256,257, 256,256, 256,256,256,256,256,256,256, 39};
constexpr size_t WK[19] = {40, 256,256,256,256,256,256,256,256, 272,256, 256,256,256,256,224,256,256, 256};
constexpr size_t woff(int i) { size_t o = 0; for (int j = 0; j < i; j++) o += WN[j] * WK[j] * 2; return o; }
constexpr size_t BF_W_TOTAL = woff(19);
__device__ __align__(256) bf16 d_BF[BF_ACT_TOTAL + BF_W_TOTAL];

__device__ __forceinline__ float sigmoidf_(float x) { return 1.0f / (1.0f + expf(-x)); }
__device__ __forceinline__ void store2(bf16* hi, bf16* lo, size_t i, float v) {
    bf16 h = __float2bfloat16(v);
    hi[i] = h;
    lo[i] = __float2bfloat16(v - __bfloat162float(h));
}
__device__ __forceinline__ float join2(const bf16* hi, const bf16* lo, size_t i) {
    return __bfloat162float(hi[i]) + __bfloat162float(lo[i]);
}

__device__ __forceinline__ uint32_t s2u(const void* p) {
    return (uint32_t)__cvta_generic_to_shared(p);
}
__device__ __forceinline__ void cpa16(uint32_t d, const void* s, int sz) {
    asm volatile("cp.async.ca.shared.global [%0], [%1], 16, %2;" :: "r"(d), "l"(s), "r"(sz));
}
#define CP_COMMIT() asm volatile("cp.async.commit_group;")
#define CP_WAIT1()  asm volatile("cp.async.wait_group 1;")

// weight prep: plane-split with optional transpose + zero padding
__global__ void k_wprep(const float* __restrict__ W, bf16* __restrict__ BH,
                        bf16* __restrict__ BL, int Nn, int Kp, int Wr, int Wc, int trans)
{
    int idx = blockIdx.x * blockDim.x + threadIdx.x;
    if (idx >= Nn * Kp) return;
    int n = idx / Kp, k = idx % Kp;
    float v = 0.0f;
    if (trans) { if (k < Wr && n < Wc) v = W[(size_t)k * Wc + n]; }
    else       { if (n < Wr && k < Wc) v = W[(size_t)n * Wc + k]; }
    bf16 h = __float2bfloat16(v);
    BH[idx] = h;
    BL[idx] = __float2bfloat16(v - __bfloat162float(h));
}

// ============================================================================
// bf16x3 GEMM: C = epi(A @ B^T + bias), A [M][lda] planes, B [N][ldb] planes
// (B k-major). acc += aH*bL + aL*bH + aH*bH via mma.m16n8k16.bf16 f32-acc.
// EPI: 0 lin, 1 softplus(100x)/100, 2 relu, 3 *(-expm1(-100*join(mask))).
// OSPLIT: 1 -> write bf16 hi/lo planes (C0=hi,C1=lo); 0 -> f32 (C0).
// kTile=32, 2-stage cp.async; CTA 128x128; 8 warps 4Mx2N; 2 CTAs/SM.
// K must be a multiple of 8; pad columns must be zero in global memory.
// ============================================================================
template <int EPI, int OSPLIT>
__global__ void __launch_bounds__(256, 2) gemm_bf3(
    const bf16* __restrict__ Ahi, const bf16* __restrict__ Alo, int lda,
    const bf16* __restrict__ Bhi, const bf16* __restrict__ Blo, int ldb,
    const float* __restrict__ bias,
    const bf16* __restrict__ Mhi, const bf16* __restrict__ Mlo, int ldh,
    void* __restrict__ C0, void* __restrict__ C1, int ldc,
    int M, int N, int K)
{
    extern __shared__ bf16 smb[];
    constexpr int P = 40;            // SMEM row pitch (32 data + 8 pad) = 80B
    constexpr int TILE = 128 * P;    // one plane, one stage
    // layout: stage*(4*TILE) + plane*TILE; planes: 0 AH, 1 AL, 2 BH, 3 BL

    const int tid  = threadIdx.x;
    const int wid  = tid >> 5;
    const int lane = tid & 31;
    const int wm = wid & 3;
    const int wn = wid >> 2;
    const int m0 = blockIdx.y * 128;
    const int n0 = blockIdx.x * 128;
    const int r  = lane >> 2;
    const int cq = lane & 3;

    float acc[2][8][4] = {};
    const int nsteps = (K + 31) >> 5;

    auto load_stage = [&](int stage, int k0) {
        bf16* base = smb + stage * 4 * TILE;
        int row  = tid >> 1;
        int half = (tid & 1) * 16;
        // A planes
        {
            int gm = m0 + row;
            size_t so = (size_t)(gm < M ? gm : 0) * lda + k0 + half;
            bf16* dH = base + 0 * TILE + row * P + half;
            bf16* dL = base + 1 * TILE + row * P + half;
#pragma unroll
            for (int c = 0; c < 16; c += 8) {
                int sz = (gm < M && (k0 + half + c) < K) ? 16 : 0;
                cpa16(s2u(dH + c), Ahi + so + c, sz);
                cpa16(s2u(dL + c), Alo + so + c, sz);
            }
        }
        // B planes
        {
            int gn = n0 + row;
            size_t so = (size_t)(gn < N ? gn : 0) * ldb + k0 + half;
            bf16* dH = base + 2 * TILE + row * P + half;
            bf16* dL = base + 3 * TILE + row * P + half;
#pragma unroll
            for (int c = 0; c < 16; c += 8) {
                int sz = (gn < N && (k0 + half + c) < K) ? 16 : 0;
                cpa16(s2u(dH + c), Bhi + so + c, sz);
                cpa16(s2u(dL + c), Blo + so + c, sz);
            }
        }
    };

    load_stage(0, 0);
    CP_COMMIT();

    for (int s = 0; s < nsteps; s++) {
        if (s + 1 < nsteps) load_stage((s + 1) & 1, (s + 1) * 32);
        CP_COMMIT();
        CP_WAIT1();
        __syncthreads();

        const bf16* base = smb + (s & 1) * 4 * TILE;
        const bf16* AH = base;
        const bf16* AL = base + TILE;
        const bf16* BH = base + 2 * TILE;
        const bf16* BL = base + 3 * TILE;

#pragma unroll
        for (int ks = 0; ks < 32; ks += 16) {
            uint32_t aH[2][4], aL[2][4];
#pragma unroll
            for (int i = 0; i < 2; i++) {
                int rb = wm * 32 + i * 16 + r;
                int c0 = ks + 2 * cq;
                aH[i][0] = *(const uint32_t*)(AH + rb * P + c0);
                aH[i][1] = *(const uint32_t*)(AH + (rb + 8) * P + c0);
                aH[i][2] = *(const uint32_t*)(AH + rb * P + c0 + 8);
                aH[i][3] = *(const uint32_t*)(AH + (rb + 8) * P + c0 + 8);
                aL[i][0] = *(const uint32_t*)(AL + rb * P + c0);
                aL[i][1] = *(const uint32_t*)(AL + (rb + 8) * P + c0);
                aL[i][2] = *(const uint32_t*)(AL + rb * P + c0 + 8);
                aL[i][3] = *(const uint32_t*)(AL + (rb + 8) * P + c0 + 8);
            }
#pragma unroll
            for (int j = 0; j < 8; j++) {
                int cb = wn * 64 + j * 8 + r;
                int c0 = ks + 2 * cq;
                uint32_t bH0 = *(const uint32_t*)(BH + cb * P + c0);
                uint32_t bH1 = *(const uint32_t*)(BH + cb * P + c0 + 8);
                uint32_t bL0 = *(const uint32_t*)(BL + cb * P + c0);
                uint32_t bL1 = *(const uint32_t*)(BL + cb * P + c0 + 8);
#pragma unroll
                for (int i = 0; i < 2; i++) {
                    asm volatile(
                        "mma.sync.aligned.m16n8k16.row.col.f32.bf16.bf16.f32 "
                        "{%0,%1,%2,%3}, {%4,%5,%6,%7}, {%8,%9}, {%0,%1,%2,%3};"
                        : "+f"(acc[i][j][0]), "+f"(acc[i][j][1]),
                          "+f"(acc[i][j][2]), "+f"(acc[i][j][3])
                        : "r"(aH[i][0]), "r"(aH[i][1]), "r"(aH[i][2]), "r"(aH[i][3]),
                          "r"(bL0), "r"(bL1));
                    asm volatile(
                        "mma.sync.aligned.m16n8k16.row.col.f32.bf16.bf16.f32 "
                        "{%0,%1,%2,%3}, {%4,%5,%6,%7}, {%8,%9}, {%0,%1,%2,%3};"
                        : "+f"(acc[i][j][0]), "+f"(acc[i][j][1]),
                          "+f"(acc[i][j][2]), "+f"(acc[i][j][3])
                        : "r"(aL[i][0]), "r"(aL[i][1]), "r"(aL[i][2]), "r"(aL[i][3]),
                          "r"(bH0), "r"(bH1));
                    asm volatile(
                        "mma.sync.aligned.m16n8k16.row.col.f32.bf16.bf16.f32 "
                        "{%0,%1,%2,%3}, {%4,%5,%6,%7}, {%8,%9}, {%0,%1,%2,%3};"
                        : "+f"(acc[i][j][0]), "+f"(acc[i][j][1]),
                          "+f"(acc[i][j][2]), "+f"(acc[i][j][3])
                        : "r"(aH[i][0]), "r"(aH[i][1]), "r"(aH[i][2]), "r"(aH[i][3]),
                          "r"(bH0), "r"(bH1));
                }
            }
        }
        __syncthreads();
    }

    // ---- epilogue ----
#pragma unroll
    for (int i = 0; i < 2; i++) {
        int row0 = m0 + wm * 32 + i * 16 + r;
#pragma unroll
        for (int j = 0; j < 8; j++) {
            int col0 = n0 + wn * 64 + j * 8 + cq * 2;
#pragma unroll
            for (int t = 0; t < 4; t++) {
                int row = row0 + (t >> 1) * 8;
                int col = col0 + (t & 1);
                if (row < M && col < N) {
                    float v = acc[i][j][t];
                    if (bias) v += bias[col];
                    if (EPI == 1) {
                        float s = 100.0f * v;
                        v = (fmaxf(s, 0.0f) + log1pf(expf(-fabsf(s)))) * 0.01f;
                    } else if (EPI == 2) {
                        v = fmaxf(v, 0.0f);
                    } else if (EPI == 3) {
                        v = v * (-expm1f(-100.0f * join2(Mhi, Mlo, (size_t)row * ldh + col)));
                    }
                    size_t ci = (size_t)row * ldc + col;
                    if (OSPLIT) store2((bf16*)C0, (bf16*)C1, ci, v);
                    else        ((float*)C0)[ci] = v;
                }
            }
        }
    }
}

// ===================== small kernels =====================

__global__ void k_ray_init(const float* __restrict__ ro, const float* __restrict__ rd,
                           float* __restrict__ Z)
{
    int r = blockIdx.x * blockDim.x + threadIdx.x;
    if (r >= R_RAYS) return;
    float ox = ro[r*3], oy = ro[r*3+1], oz = ro[r*3+2];
    float dx = rd[r*3], dy = rd[r*3+1], dz = rd[r*3+2];
    float a = dx*dx + dy*dy + dz*dz;
    float b = 2.0f * (ox*dx + oy*dy + oz*dz);
    float mid = -b / (2.0f * a);
    float nv = fmaxf(mid - 1.0f, 0.05f);
    float fv = mid + 1.0f;
    for (int s = 0; s < 64; s++)
        Z[r*64 + s] = nv + (fv - nv) * ((float)s * (1.0f/63.0f));
}

__global__ void k_pts(const float* __restrict__ Z, const float* __restrict__ ro,
                      const float* __restrict__ rd, float* __restrict__ P, int S, int M)
{
    int m = blockIdx.x * blockDim.x + threadIdx.x;
    if (m >= M) return;
    int r = m / S;
    float z = Z[m];
#pragma unroll
    for (int j = 0; j < 3; j++)
        P[(size_t)m*3 + j] = fmaf(rd[r*3+j], z, ro[r*3+j]);
}

__global__ void k_dist_mid_pts(const float* __restrict__ Z, const float* __restrict__ ro,
                               const float* __restrict__ rd, float* __restrict__ P,
                               float* __restrict__ D)
{
    int m = blockIdx.x * blockDim.x + threadIdx.x;
    if (m >= (int)NPTS) return;
    int s = m & 127, r = m >> 7;
    float z = Z[m];
    float d = (s < 127) ? (Z[m+1] - z) : 0.03125f;
    D[m] = d;
    float mz = fmaf(0.5f, d, z);
#pragma unroll
    for (int j = 0; j < 3; j++)
        P[(size_t)m*3 + j] = fmaf(rd[r*3+j], mz, ro[r*3+j]);
}

__global__ void k_embed(const float* __restrict__ P, bf16* __restrict__ Eh,
                        bf16* __restrict__ El, int M)
{
    int m = blockIdx.x * blockDim.x + threadIdx.x;
    if (m >= M) return;
    float p0 = P[(size_t)m*3], p1 = P[(size_t)m*3+1], p2 = P[(size_t)m*3+2];
    size_t b = (size_t)m * 40;
    store2(Eh, El, b+0, p0); store2(Eh, El, b+1, p1); store2(Eh, El, b+2, p2);
    float f = 1.0f;
#pragma unroll
    for (int k = 0; k < 6; k++) {
        float s0,c0,s1,c1,s2,c2;
        sincosf(f*p0,&s0,&c0); sincosf(f*p1,&s1,&c1); sincosf(f*p2,&s2,&c2);
        store2(Eh, El, b+3+6*k+0, s0); store2(Eh, El, b+3+6*k+1, s1); store2(Eh, El, b+3+6*k+2, s2);
        store2(Eh, El, b+3+6*k+3, c0); store2(Eh, El, b+3+6*k+4, c1); store2(Eh, El, b+3+6*k+5, c2);
        f *= 2.0f;
    }
    store2(Eh, El, b+39, 0.0f);   // pad
}

__global__ void k_concat(const bf16* __restrict__ H3h, const bf16* __restrict__ H3l,
                         const bf16* __restrict__ Eh, const bf16* __restrict__ El,
                         bf16* __restrict__ Oh, bf16* __restrict__ Ol, int M)
{
    int idx = blockIdx.x * blockDim.x + threadIdx.x;
    if (idx >= M * 256) return;
    int m = idx >> 8, c = idx & 255;
    float v = (c < 217) ? join2(H3h, H3l, (size_t)m*224 + c)
                        : join2(Eh, El, (size_t)m*40 + (c-217));
    store2(Oh, Ol, idx, v * 0.7071067811865476f);
}

__global__ void k_sdf_head(const bf16* __restrict__ Hh, const bf16* __restrict__ Hl,
                           const float* __restrict__ W8, const float* __restrict__ b8,
                           float* __restrict__ out, int M)
{
    int gw = (blockIdx.x * blockDim.x + threadIdx.x) >> 5;
    int lane = threadIdx.x & 31;
    if (gw >= M) return;
    size_t b = (size_t)gw * 256;
    float s = 0.0f;
#pragma unroll
    for (int k = lane; k < 256; k += 32) s = fmaf(join2(Hh, Hl, b + k), W8[(size_t)k*257], s);
#pragma unroll
    for (int o = 16; o; o >>= 1) s += __shfl_xor_sync(0xffffffffu, s, o);
    if (!lane) out[gw] = s + b8[0];
}

__global__ void k_upsample(const float* __restrict__ ro, const float* __restrict__ rd,
                           const float* __restrict__ Z, const float* __restrict__ SD,
                           float* __restrict__ ZN, int S, float inv_s)
{
    int r = blockIdx.x * blockDim.x + threadIdx.x;
    if (r >= R_RAYS) return;
    float ox = ro[r*3], oy = ro[r*3+1], oz = ro[r*3+2];
    float dx = rd[r*3], dy = rd[r*3+1], dz = rd[r*3+2];
    const float* zr = Z + (size_t)r * S;
    const float* sr = SD + (size_t)r * S;

    float w[128], cdf[129];
    float prev_raw = 0.0f, T = 1.0f, wsum = 0.0f;
    float z_i = zr[0];
    float px = fmaf(dx,z_i,ox), py = fmaf(dy,z_i,oy), pz = fmaf(dz,z_i,oz);
    float rad_i = sqrtf(px*px + py*py + pz*pz);
    float sdf_i = sr[0];

    for (int i = 0; i < S - 1; i++) {
        float z_n = zr[i+1], sdf_n = sr[i+1];
        float qx = fmaf(dx,z_n,ox), qy = fmaf(dy,z_n,oy), qz = fmaf(dz,z_n,oz);
        float rad_n = sqrtf(qx*qx + qy*qy + qz*qz);
        bool inside = (rad_i < 1.0f) || (rad_n < 1.0f);
        float mid_sdf = 0.5f * (sdf_i + sdf_n);
        float raw = (sdf_n - sdf_i) / (z_n - z_i + 1e-5f);
        float cosv = fminf(raw, prev_raw);
        prev_raw = raw;
        cosv = fminf(fmaxf(cosv, -1000.0f), 0.0f);
        if (!inside) cosv = 0.0f;
        float dist = z_n - z_i;
        float pc = sigmoidf_((mid_sdf - cosv*dist*0.5f) * inv_s);
        float nc = sigmoidf_((mid_sdf + cosv*dist*0.5f) * inv_s);
        float alpha = (pc - nc + 1e-5f) / (pc + 1e-5f);
        float wi = alpha * T;
        T *= (1.0f - alpha + 1e-7f);
        wi += 1e-5f;
        w[i] = wi; wsum += wi;
        z_i = z_n; rad_i = rad_n; sdf_i = sdf_n;
    }

    cdf[0] = 0.0f;
    float invsum = 1.0f / wsum;
    for (int i = 0; i < S - 1; i++) cdf[i+1] = cdf[i] + w[i] * invsum;

    for (int j = 0; j < 16; j++) {
        float u = 0.03125f + (float)j * 0.0625f;
        int lo = 0, hi = S;
        while (lo < hi) { int md = (lo + hi) >> 1; if (cdf[md] <= u) lo = md + 1; else hi = md; }
        int below = lo - 1; if (below < 0) below = 0; if (below > S-1) below = S-1;
        int above = lo;     if (above > S-1) above = S-1;
        float c0 = cdf[below], c1 = cdf[above];
        float b0 = zr[below],  b1 = zr[above];
        float den = (c1 - c0) < 1e-5f ? 1.0f : (c1 - c0);
        ZN[r*16 + j] = b0 + (u - c0) / den * (b1 - b0);
    }
}

__global__ void k_merge(const float* __restrict__ Z, const float* __restrict__ SD,
                        const float* __restrict__ ZN, const float* __restrict__ SN,
                        float* __restrict__ ZT, float* __restrict__ ST, int S)
{
    int r = blockIdx.x * blockDim.x + threadIdx.x;
    if (r >= R_RAYS) return;
    const float* zo = Z + (size_t)r*S;  const float* so = SD + (size_t)r*S;
    const float* zn = ZN + r*16;        const float* sn = SN + r*16;
    float* zt = ZT + (size_t)r*(S+16);  float* st = ST + (size_t)r*(S+16);
    int i = 0, j = 0;
    for (int k = 0; k < S + 16; k++) {
        bool useOld = (i < S) && ((j >= 16) || (zo[i] <= zn[j]));
        if (useOld) { zt[k] = zo[i]; st[k] = so[i]; i++; }
        else        { zt[k] = zn[j]; st[k] = sn[j]; j++; }
    }
}

__global__ void k_copy(float* __restrict__ dst, const float* __restrict__ src, int n)
{
    int i = blockIdx.x * blockDim.x + threadIdx.x;
    if (i < n) dst[i] = src[i];
}

__global__ void k_bwinit(const bf16* __restrict__ H7h, const bf16* __restrict__ H7l,
                         const float* __restrict__ W8, bf16* __restrict__ Gh,
                         bf16* __restrict__ Gl, int M)
{
    int idx = blockIdx.x * blockDim.x + threadIdx.x;
    if (idx >= M * 256) return;
    int c = idx & 255;
    store2(Gh, Gl, idx, W8[(size_t)c * 257] * (-expm1f(-100.0f * join2(H7h, H7l, idx))));
}

__global__ void k_split(const bf16* __restrict__ Gh, const bf16* __restrict__ Gl,
                        const bf16* __restrict__ H3h, const bf16* __restrict__ H3l,
                        bf16* __restrict__ Zh, bf16* __restrict__ Zl,
                        float* __restrict__ GE, int M)
{
    int idx = blockIdx.x * blockDim.x + threadIdx.x;
    if (idx >= M * 256) return;
    int m = idx >> 8, c = idx & 255;
    float v = join2(Gh, Gl, idx) * 0.7071067811865476f;
    if (c < 217)
        store2(Zh, Zl, (size_t)m*224 + c, v * (-expm1f(-100.0f * join2(H3h, H3l, (size_t)m*224 + c))));
    else
        GE[(size_t)m*39 + (c - 217)] = v;
}

__global__ void k_padzero(bf16* __restrict__ Zh, bf16* __restrict__ Zl,
                          int M, int pitch, int from)
{
    int n = M * (pitch - from);
    int idx = blockIdx.x * blockDim.x + threadIdx.x;
    if (idx >= n) return;
    int w = pitch - from;
    int m = idx / w, c = from + idx % w;
    Zh[(size_t)m*pitch + c] = __float2bfloat16(0.0f);
    Zl[(size_t)m*pitch + c] = __float2bfloat16(0.0f);
}

__global__ void k_gradpts(const float* __restrict__ GEm, const float* __restrict__ GEs,
                          const float* __restrict__ P, float* __restrict__ GR, int M)
{
    int m = blockIdx.x * blockDim.x + threadIdx.x;
    if (m >= M) return;
    const float* ga = GEm + (size_t)m*39;
    const float* gb = GEs + (size_t)m*39;
    float p[3] = {P[(size_t)m*3], P[(size_t)m*3+1], P[(size_t)m*3+2]};
    float g[3];
#pragma unroll
    for (int j = 0; j < 3; j++) g[j] = ga[j] + gb[j];
    float f = 1.0f;
#pragma unroll
    for (int k = 0; k < 6; k++) {
#pragma unroll
        for (int j = 0; j < 3; j++) {
            float s, c;
            sincosf(f * p[j], &s, &c);
            float gs = ga[3+6*k+j]   + gb[3+6*k+j];
            float gc = ga[3+6*k+3+j] + gb[3+6*k+3+j];
            g[j] = fmaf( f * c, gs, g[j]);
            g[j] = fmaf(-f * s, gc, g[j]);
        }
        f *= 2.0f;
    }
#pragma unroll
    for (int j = 0; j < 3; j++) GR[(size_t)m*3 + j] = g[j];
}

__global__ void k_alpha(const float* __restrict__ OUT8, const float* __restrict__ GR,
                        const float* __restrict__ D, const float* __restrict__ rd,
                        const float* __restrict__ var, float* __restrict__ A, int M)
{
    int m = blockIdx.x * blockDim.x + threadIdx.x;
    if (m >= M) return;
    int r = m >> 7;
    float tc = rd[r*3]*GR[(size_t)m*3] + rd[r*3+1]*GR[(size_t)m*3+1] + rd[r*3+2]*GR[(size_t)m*3+2];
    float ic = fminf(tc, 0.0f);
    float sdf = OUT8[(size_t)m * 257];
    float dist = D[m];
    float inv_s = fminf(fmaxf(expf(10.0f * var[0]), 1e-6f), 1e6f);
    float pc = sigmoidf_((sdf - ic*dist*0.5f) * inv_s);
    float nc = sigmoidf_((sdf + ic*dist*0.5f) * inv_s);
    float a = (pc - nc + 1e-5f) / (pc + 1e-5f);
    A[m] = fminf(fmaxf(a, 0.0f), 1.0f);
}

__global__ void k_ray_weights(const float* __restrict__ A, float* __restrict__ W)
{
    int r = blockIdx.x * blockDim.x + threadIdx.x;
    if (r >= R_RAYS) return;
    float T = 1.0f;
    for (int s = 0; s < 128; s++) {
        int m = r*128 + s;
        float a = A[m];
        W[m] = a * T;
        T *= (1.0f - a + 1e-7f);
    }
}

__global__ void k_cin(const float* __restrict__ P, const float* __restrict__ rd,
                      const float* __restrict__ GR, const float* __restrict__ OUT8,
                      bf16* __restrict__ Ch, bf16* __restrict__ Cl, int M)
{
    int idx = blockIdx.x * blockDim.x + threadIdx.x;
    if (idx >= M * 272) return;
    int m = idx / 272, c = idx % 272;
    float v;
    if (c >= 265) v = 0.0f;
    else if (c < 3) v = P[(size_t)m*3 + c];
    else if (c < 6) { int r = m >> 7; v = rd[r*3 + (c-3)]; }
    else if (c < 9) {
        float g0 = GR[(size_t)m*3], g1 = GR[(size_t)m*3+1], g2 = GR[(size_t)m*3+2];
        float n = fmaxf(sqrtf(g0*g0 + g1*g1 + g2*g2), 1e-6f);
        v = GR[(size_t)m*3 + (c-6)] / n;
    } else v = OUT8[(size_t)m*257 + 1 + (c-9)];
    store2(Ch, Cl, idx, v);
}

__global__ void k_color_head(const bf16* __restrict__ Hh, const bf16* __restrict__ Hl,
                             const float* __restrict__ W, const float* __restrict__ b,
                             float* __restrict__ rgbs, int M)
{
    int gw = (blockIdx.x * blockDim.x + threadIdx.x) >> 5;
    int lane = threadIdx.x & 31;
    if (gw >= M) return;
    size_t hb = (size_t)gw * 256;
    float a0 = 0.f, a1 = 0.f, a2 = 0.f;
#pragma unroll
    for (int k = lane; k < 256; k += 32) {
        float hv = join2(Hh, Hl, hb + k);
        a0 = fmaf(hv, W[k*3+0], a0);
        a1 = fmaf(hv, W[k*3+1], a1);
        a2 = fmaf(hv, W[k*3+2], a2);
    }
#pragma unroll
    for (int o = 16; o; o >>= 1) {
        a0 += __shfl_xor_sync(0xffffffffu, a0, o);
        a1 += __shfl_xor_sync(0xffffffffu, a1, o);
        a2 += __shfl_xor_sync(0xffffffffu, a2, o);
    }
    if (!lane) {
        rgbs[(size_t)gw*3+0] = sigmoidf_(a0 + b[0]);
        rgbs[(size_t)gw*3+1] = sigmoidf_(a1 + b[1]);
        rgbs[(size_t)gw*3+2] = sigmoidf_(a2 + b[2]);
    }
}

__global__ void k_reduce(const float* __restrict__ W, const float* __restrict__ rgbs,
                         float* __restrict__ out)
{
    int r = blockIdx.x * blockDim.x + threadIdx.x;
    if (r >= R_RAYS) return;
    float s0 = 0.f, s1 = 0.f, s2 = 0.f;
    for (int s = 0; s < 128; s++) {
        int m = r*128 + s;
        float w = W[m];
        s0 = fmaf(w, rgbs[(size_t)m*3+0], s0);
        s1 = fmaf(w, rgbs[(size_t)m*3+1], s1);
        s2 = fmaf(w, rgbs[(size_t)m*3+2], s2);
    }
    out[r*3+0] = s0; out[r*3+1] = s1; out[r*3+2] = s2;
}

// ===================== host orchestration =====================

static const int GEMM_SHM = 81920;

struct Plane { bf16* hi; bf16* lo; };

template <int EPI, int OSPLIT>
static void launch_bf3(Plane A, int lda, Plane B, int ldb, const float* bias,
                       Plane Hm, int ldh, void* C0, void* C1, int ldc,
                       int M, int N, int K)
{
    dim3 g((N + 127) / 128, (M + 127) / 128);
    cudaFuncSetAttribute(gemm_bf3<EPI,OSPLIT>,
                         cudaFuncAttributeMaxDynamicSharedMemorySize, GEMM_SHM);
    gemm_bf3<EPI,OSPLIT><<<g, 256, GEMM_SHM>>>(A.hi, A.lo, lda, B.hi, B.lo, ldb,
                                               bias, Hm.hi, Hm.lo, ldh, C0, C1, ldc, M, N, K);
}

struct Ctx {
    Plane act[13];   // E,H0,H1,H2,H3,I4,A4,A5,A6,A7,GP,GQ,CIN
    Plane wb[19];
    const float* sb[9]; const float* cb[3];
    const float* sw8raw; const float* cw2raw;
};
enum { E_=0, H0_, H1_, H2_, H3_, I4_, A4_, A5_, A6_, A7_, GP_, GQ_, CIN_ };

static void sdf_forward_nostore(int M, const Ctx& X, float* fbase, float* sdf_dest)
{
    Plane none = {nullptr, nullptr};
    Plane E = X.act[E_], GP = X.act[GP_], GQ = X.act[GQ_];
    float* PP = fbase + O_PTS;
    k_embed<<<(M+255)/256, 256>>>(PP, E.hi, E.lo, M);
    launch_bf3<1,1>(E, 40,  X.wb[0], 40,  X.sb[0], none, 0, GP.hi, GP.lo, 256, M, 256, 40);
    launch_bf3<1,1>(GP, 256, X.wb[1], 256, X.sb[1], none, 0, GQ.hi, GQ.lo, 256, M, 256, 256);
    launch_bf3<1,1>(GQ, 256, X.wb[2], 256, X.sb[2], none, 0, GP.hi, GP.lo, 256, M, 256, 256);
    launch_bf3<1,1>(GP, 256, X.wb[3], 256, X.sb[3], none, 0, GQ.hi, GQ.lo, 224, M, 217, 256);
    k_concat<<<(M*256+255)/256, 256>>>(GQ.hi, GQ.lo, E.hi, E.lo, GP.hi, GP.lo, M);
    launch_bf3<1,1>(GP, 256, X.wb[4], 256, X.sb[4], none, 0, GQ.hi, GQ.lo, 256, M, 256, 256);
    launch_bf3<1,1>(GQ, 256, X.wb[5], 256, X.sb[5], none, 0, GP.hi, GP.lo, 256, M, 256, 256);
    launch_bf3<1,1>(GP, 256, X.wb[6], 256, X.sb[6], none, 0, GQ.hi, GQ.lo, 256, M, 256, 256);
    launch_bf3<1,1>(GQ, 256, X.wb[7], 256, X.sb[7], none, 0, GP.hi, GP.lo, 256, M, 256, 256);
    k_sdf_head<<<(M*32+255)/256, 256>>>(GP.hi, GP.lo, X.sw8raw, X.sb[8], sdf_dest, M);
}

extern "C" void kernel_launch(void* const* d_in, const int* in_sizes, int n_in,
                              void* d_out, int out_size)
{
    const float* ro = (const float*)d_in[0];
    const float* rd = (const float*)d_in[1];
    const float* sw[9]; const float* sb[9];
    const float* cw[3]; const float* cb[3];
    const float* var;

    bool interleaved = (in_sizes[3] < 1024);
    if (interleaved) {
        for (int l = 0; l < 9; l++) { sw[l] = (const float*)d_in[2 + 2*l]; sb[l] = (const float*)d_in[3 + 2*l]; }
        for (int l = 0; l < 3; l++) { cw[l] = (const float*)d_in[20 + 2*l]; cb[l] = (const float*)d_in[21 + 2*l]; }
        var = (const float*)d_in[26];
    } else {
        for (int l = 0; l < 9; l++) { sw[l] = (const float*)d_in[2 + l]; sb[l] = (const float*)d_in[11 + l]; }
        for (int l = 0; l < 3; l++) { cw[l] = (const float*)d_in[20 + l]; cb[l] = (const float*)d_in[23 + l]; }
        var = (const float*)d_in[26];
    }
    float* out = (float*)d_out;

    float* fbase = nullptr;
    bf16* bbase = nullptr;
    cudaGetSymbolAddress((void**)&fbase, d_F32);
    cudaGetSymbolAddress((void**)&bbase, d_BF);

    float* PZ = fbase+O_Z;     float* PSDF = fbase+O_SDF;
    float* PZT = fbase+O_ZT;   float* PSDFT = fbase+O_SDFT;
    float* PZN = fbase+O_ZNEW; float* PSDFN = fbase+O_SDFNEW;
    float* PP = fbase+O_PTS;   float* PD = fbase+O_DIST;
    float* PO8 = fbase+O_OUT8; float* PGE = fbase+O_GE; float* PGEM = fbase+O_GEM;
    float* PGR = fbase+O_GRAD; float* PA = fbase+O_ALPHA;
    float* PW = fbase+O_WT;    float* PRGB = fbase+O_RGBS;

    Ctx X;
    for (int i = 0; i < 13; i++) {
        X.act[i].hi = bbase + aoff(i);
        X.act[i].lo = bbase + aoff(i) + NPTS * AW[i];
    }
    bf16* wb0 = bbase + BF_ACT_TOTAL;
    for (int i = 0; i < 19; i++) {
        X.wb[i].hi = wb0 + woff(i);
        X.wb[i].lo = wb0 + woff(i) + WN[i] * WK[i];
    }
    for (int l = 0; l < 9; l++) X.sb[l] = sb[l];
    for (int l = 0; l < 3; l++) X.cb[l] = cb[l];
    X.sw8raw = sw[8]; X.cw2raw = cw[2];

    // ---- weight plane prep (19 buffers) ----
    struct WD { const float* W; int Wr, Wc, trans; };
    WD wd[19] = {
        {sw[0],39,256,1},{sw[1],256,256,1},{sw[2],256,256,1},{sw[3],256,217,1},
        {sw[4],256,256,1},{sw[5],256,256,1},{sw[6],256,256,1},{sw[7],256,256,1},
        {sw[8],256,257,1},
        {cw[0],265,256,1},{cw[1],256,256,1},
        {sw[7],256,256,0},{sw[6],256,256,0},{sw[5],256,256,0},{sw[4],256,256,0},
        {sw[3],256,217,0},{sw[2],256,256,0},{sw[1],256,256,0},
        {sw[0],39,256,0}
    };
    for (int i = 0; i < 19; i++) {
        int n = (int)(WN[i] * WK[i]);
        k_wprep<<<(n+255)/256, 256>>>(wd[i].W, X.wb[i].hi, X.wb[i].lo,
                                      (int)WN[i], (int)WK[i], wd[i].Wr, wd[i].Wc, wd[i].trans);
    }

    Plane none = {nullptr, nullptr};
    Plane E = X.act[E_], H0 = X.act[H0_], H1 = X.act[H1_], H2 = X.act[H2_];
    Plane H3 = X.act[H3_], I4 = X.act[I4_], A4 = X.act[A4_], A5 = X.act[A5_];
    Plane A6 = X.act[A6_], A7 = X.act[A7_], GP = X.act[GP_], GQ = X.act[GQ_];
    Plane CIN = X.act[CIN_];

    // ---- initial 64 samples + sdf ----
    k_ray_init<<<4, 256>>>(ro, rd, PZ);
    int S = 64;
    int M = R_RAYS * S;
    k_pts<<<(M+255)/256, 256>>>(PZ, ro, rd, PP, S, M);
    sdf_forward_nostore(M, X, fbase, PSDF);

    // ---- 4 importance-sampling rounds ----
    for (int i = 0; i < 4; i++) {
        float inv_s = 64.0f * (float)(1 << i);
        k_upsample<<<4, 256>>>(ro, rd, PZ, PSDF, PZN, S, inv_s);
        int Mn = R_RAYS * 16;
        k_pts<<<(Mn+255)/256, 256>>>(PZN, ro, rd, PP, 16, Mn);
        sdf_forward_nostore(Mn, X, fbase, PSDFN);
        k_merge<<<4, 256>>>(PZ, PSDF, PZN, PSDFN, PZT, PSDFT, S);
        S += 16;
        int n = R_RAYS * S;
        k_copy<<<(n+255)/256, 256>>>(PZ, PZT, n);
        k_copy<<<(n+255)/256, 256>>>(PSDF, PSDFT, n);
    }

    // ---- final forward (stored activations) ----
    M = (int)NPTS;
    k_dist_mid_pts<<<(M+255)/256, 256>>>(PZ, ro, rd, PP, PD);
    k_embed<<<(M+255)/256, 256>>>(PP, E.hi, E.lo, M);
    launch_bf3<1,1>(E, 40,   X.wb[0], 40,  sb[0], none, 0, H0.hi, H0.lo, 256, M, 256, 40);
    launch_bf3<1,1>(H0, 256, X.wb[1], 256, sb[1], none, 0, H1.hi, H1.lo, 256, M, 256, 256);
    launch_bf3<1,1>(H1, 256, X.wb[2], 256, sb[2], none, 0, H2.hi, H2.lo, 256, M, 256, 256);
    launch_bf3<1,1>(H2, 256, X.wb[3], 256, sb[3], none, 0, H3.hi, H3.lo, 224, M, 217, 256);
    k_concat<<<(M*256+255)/256, 256>>>(H3.hi, H3.lo, E.hi, E.lo, I4.hi, I4.lo, M);
    launch_bf3<1,1>(I4, 256, X.wb[4], 256, sb[4], none, 0, A4.hi, A4.lo, 256, M, 256, 256);
    launch_bf3<1,1>(A4, 256, X.wb[5], 256, sb[5], none, 0, A5.hi, A5.lo, 256, M, 256, 256);
    launch_bf3<1,1>(A5, 256, X.wb[6], 256, sb[6], none, 0, A6.hi, A6.lo, 256, M, 256, 256);
    launch_bf3<1,1>(A6, 256, X.wb[7], 256, sb[7], none, 0, A7.hi, A7.lo, 256, M, 256, 256);
    launch_bf3<0,0>(A7, 256, X.wb[8], 256, sb[8], none, 0, PO8, nullptr, 257, M, 257, 256);

    // ---- backward VJP ----
    k_bwinit<<<(M*256+255)/256, 256>>>(A7.hi, A7.lo, sw[8], GP.hi, GP.lo, M);
    launch_bf3<3,1>(GP, 256, X.wb[11], 256, nullptr, A6, 256, GQ.hi, GQ.lo, 256, M, 256, 256);
    launch_bf3<3,1>(GQ, 256, X.wb[12], 256, nullptr, A5, 256, GP.hi, GP.lo, 256, M, 256, 256);
    launch_bf3<3,1>(GP, 256, X.wb[13], 256, nullptr, A4, 256, GQ.hi, GQ.lo, 256, M, 256, 256);
    launch_bf3<0,1>(GQ, 256, X.wb[14], 256, nullptr, none, 0, GP.hi, GP.lo, 256, M, 256, 256);
    k_split<<<(M*256+255)/256, 256>>>(GP.hi, GP.lo, H3.hi, H3.lo, GQ.hi, GQ.lo, PGE, M);
    k_padzero<<<(M*7+255)/256, 256>>>(GQ.hi, GQ.lo, M, 224, 217);
    launch_bf3<3,1>(GQ, 224, X.wb[15], 224, nullptr, H2, 256, GP.hi, GP.lo, 256, M, 256, 224);
    launch_bf3<3,1>(GP, 256, X.wb[16], 256, nullptr, H1, 256, GQ.hi, GQ.lo, 256, M, 256, 256);
    launch_bf3<3,1>(GQ, 256, X.wb[17], 256, nullptr, H0, 256, GP.hi, GP.lo, 256, M, 256, 256);
    launch_bf3<0,0>(GP, 256, X.wb[18], 256, nullptr, none, 0, PGEM, nullptr, 39, M, 39, 256);
    k_gradpts<<<(M+255)/256, 256>>>(PGEM, PGE, PP, PGR, M);

    // ---- color net + compositing ----
    k_alpha<<<(M+255)/256, 256>>>(PO8, PGR, PD, rd, var, PA, M);
    k_ray_weights<<<4, 256>>>(PA, PW);
    k_cin<<<(M*272+255)/256, 256>>>(PP, rd, PGR, PO8, CIN.hi, CIN.lo, M);
    launch_bf3<2,1>(CIN, 272, X.wb[9], 272, cb[0], none, 0, GP.hi, GP.lo, 256, M, 256, 272);
    launch_bf3<2,1>(GP, 256, X.wb[10], 256, cb[1], none, 0, GQ.hi, GQ.lo, 256, M, 256, 256);
    k_color_head<<<(M*32+255)/256, 256>>>(GQ.hi, GQ.lo, cw[2], cb[2], PRGB, M);
    k_reduce<<<4, 256>>>(PW, PRGB, out);
}

// round 13
// speedup vs baseline: 1.7057x; 1.0399x over previous
#include <cuda_runtime.h>
#include <cuda_bf16.h>
#include <math.h>
#include <stdint.h>
#include <stddef.h>

typedef __nv_bfloat16 bf16;

#define R_RAYS 1024
static constexpr size_t NPTS = 131072;

// ================= f32 scratch =================
constexpr size_t O_Z      = 0;
constexpr size_t O_SDF    = O_Z + NPTS;
constexpr size_t O_ZT     = O_SDF + NPTS;
constexpr size_t O_SDFT   = O_ZT + NPTS;
constexpr size_t O_ZNEW   = O_SDFT + NPTS;
constexpr size_t O_SDFNEW = O_ZNEW + 16384;
constexpr size_t O_PTS    = O_SDFNEW + 16384;
constexpr size_t O_DIST   = O_PTS + NPTS * 3;
constexpr size_t O_SDFO   = O_DIST + NPTS;          // f32 [M] final sdf
constexpr size_t O_GE     = O_SDFO + NPTS;          // f32 [M][39] skip grad
constexpr size_t O_GEM    = O_GE + NPTS * 39;       // f32 [M][39] main grad
constexpr size_t O_GRAD   = O_GEM + NPTS * 39;
constexpr size_t O_ALPHA  = O_GRAD + NPTS * 3;
constexpr size_t O_WT     = O_ALPHA + NPTS;
constexpr size_t O_RGBS   = O_WT + NPTS;
constexpr size_t F32_TOTAL = O_RGBS + NPTS * 3;
__device__ __align__(256) float d_F32[F32_TOTAL];

// ================= bf16 plane scratch =================
constexpr size_t AW[13] = {40,256,256,256,224,256,256,256,256,256,256,256,272};
constexpr size_t aoff(int i) { size_t o = 0; for (int j = 0; j < i; j++) o += AW[j] * 2; return o * NPTS; }
constexpr size_t BF_ACT_TOTAL = aoff(13);
// weight plane buffers (host-side tables)
constexpr size_t WN[19] = {256,256,256,217,256,256,256,256,257, 256,256, 256,256,256,256,256,256,256, 39};
constexpr size_t WK[19] = {40, 256,256,256,256,256,256,256,256, 272,256, 256,256,256,256,224,256,256, 256};
constexpr size_t woff(int i) { size_t o = 0; for (int j = 0; j < i; j++) o += WN[j] * WK[j] * 2; return o; }
constexpr size_t BF_W_TOTAL = woff(19);
__device__ __align__(256) bf16 d_BF[BF_ACT_TOTAL + BF_W_TOTAL];

__device__ __forceinline__ float sigmoidf_(float x) { return 1.0f / (1.0f + expf(-x)); }
__device__ __forceinline__ void store2(void* hi, void* lo, size_t i, float v) {
    bf16 h = __float2bfloat16(v);
    ((bf16*)hi)[i] = h;
    ((bf16*)lo)[i] = __float2bfloat16(v - __bfloat162float(h));
}
__device__ __forceinline__ float join2(const bf16* hi, const bf16* lo, size_t i) {
    return __bfloat162float(hi[i]) + __bfloat162float(lo[i]);
}
__device__ __forceinline__ float softp_(float v) {
    float s = 100.0f * v;
    return (fmaxf(s, 0.0f) + log1pf(expf(-fabsf(s)))) * 0.01f;
}

__device__ __forceinline__ uint32_t s2u(const void* p) {
    return (uint32_t)__cvta_generic_to_shared(p);
}
__device__ __forceinline__ void cpa16(uint32_t d, const void* s, int sz) {
    asm volatile("cp.async.ca.shared.global [%0], [%1], 16, %2;" :: "r"(d), "l"(s), "r"(sz));
}
#define CP_COMMIT() asm volatile("cp.async.commit_group;")
#define CP_WAIT1()  asm volatile("cp.async.wait_group 1;")

__device__ __forceinline__ void ldsm4(uint32_t& r0, uint32_t& r1, uint32_t& r2, uint32_t& r3,
                                      uint32_t addr) {
    asm volatile("ldmatrix.sync.aligned.m8n8.x4.shared.b16 {%0,%1,%2,%3}, [%4];"
                 : "=r"(r0), "=r"(r1), "=r"(r2), "=r"(r3) : "r"(addr));
}

// ---- fused weight prep: all 19 plane buffers in one launch ----
struct WSrc { const float* p[19]; };
__global__ void k_wprep_all(WSrc ws, bf16* __restrict__ wb, int total)
{
    // device-local copies of the descriptor tables
    const int wn[19] = {256,256,256,217,256,256,256,256,257, 256,256, 256,256,256,256,256,256,256, 39};
    const int wk[19] = {40, 256,256,256,256,256,256,256,256, 272,256, 256,256,256,256,224,256,256, 256};
    const int wr[19] = {39,256,256,256,256,256,256,256,256, 265,256, 256,256,256,256,256,256,256, 39};
    const int wc[19] = {256,256,256,217,256,256,256,256,257, 256,256, 256,256,256,256,217,256,256, 256};

    int idx = blockIdx.x * blockDim.x + threadIdx.x;
    if (idx >= total) return;
    size_t off = (size_t)idx;
    int bi = 0;
    size_t base = 0;
#pragma unroll
    for (int i = 0; i < 19; i++) {
        size_t sz = (size_t)wn[i] * wk[i];
        if (off < sz) { bi = i; break; }
        off -= sz;
        base += 2 * sz;
    }
    int Kp = wk[bi];
    int n = (int)(off / Kp), k = (int)(off % Kp);
    const float* W = ws.p[bi];
    float v = 0.0f;
    if (bi <= 10) { if (k < wr[bi] && n < wc[bi]) v = W[(size_t)k * wc[bi] + n]; }
    else          { if (n < wr[bi] && k < wc[bi]) v = W[(size_t)n * wc[bi] + k]; }
    bf16 h = __float2bfloat16(v);
    wb[base + off] = h;
    wb[base + (size_t)wn[bi] * wk[bi] + off] = __float2bfloat16(v - __bfloat162float(h));
}

// ============================================================================
// bf16x3 GEMM: C = epi(A @ B^T + bias). A [M][lda], B [N][ldb] hi/lo planes.
// ldmatrix fragment loads. kTile=32, 2-stage cp.async, CTA 128x128, 2 CTAs/SM.
// EPI: 0 f32 lin | 1 sp->planes | 2 relu->planes | 3 mask-mul->planes
//      4 sp->planes + bwinit->D | 5 out8: col0->f32 sdf, col>=1 ->CIN planes
//      6 sp->planes + concat->D | 7 sp->concat->D only | 8 split: Gz+GE
// ============================================================================
template <int EPI>
__global__ void __launch_bounds__(256, 2) gemm_bf3(
    const bf16* __restrict__ Ahi, const bf16* __restrict__ Alo, int lda,
    const bf16* __restrict__ Bhi, const bf16* __restrict__ Blo, int ldb,
    const float* __restrict__ bias,
    const bf16* __restrict__ Mhi, const bf16* __restrict__ Mlo, int ldh,
    void* __restrict__ C0, void* __restrict__ C1, int ldc,
    bf16* __restrict__ D0, bf16* __restrict__ D1, int ldd,
    const float* __restrict__ W8, float* __restrict__ GE,
    int M, int N, int K)
{
    extern __shared__ bf16 smb[];
    constexpr int P = 40;
    constexpr int TILE = 128 * P;

    const int tid  = threadIdx.x;
    const int wid  = tid >> 5;
    const int lane = tid & 31;
    const int wm = wid & 3;
    const int wn = wid >> 2;
    const int m0 = blockIdx.y * 128;
    const int n0 = blockIdx.x * 128;
    const int r  = lane >> 2;
    const int cq = lane & 3;

    // ldmatrix lane offsets (elements)
    const int aOff = (wm * 32 + (lane & 15)) * P + ((lane >> 4) << 3);
    const int bOff = (wn * 64 + (lane & 7) + ((lane & 16) >> 1)) * P + (((lane >> 3) & 1) << 3);

    float acc[2][8][4] = {};
    const int nsteps = (K + 31) >> 5;

    auto load_stage = [&](int stage, int k0) {
        bf16* base = smb + stage * 4 * TILE;
        int row  = tid >> 1;
        int half = (tid & 1) * 16;
        {
            int gm = m0 + row;
            size_t so = (size_t)(gm < M ? gm : 0) * lda + k0 + half;
            bf16* dH = base + 0 * TILE + row * P + half;
            bf16* dL = base + 1 * TILE + row * P + half;
#pragma unroll
            for (int c = 0; c < 16; c += 8) {
                int sz = (gm < M && (k0 + half + c) < K) ? 16 : 0;
                cpa16(s2u(dH + c), Ahi + so + c, sz);
                cpa16(s2u(dL + c), Alo + so + c, sz);
            }
        }
        {
            int gn = n0 + row;
            size_t so = (size_t)(gn < N ? gn : 0) * ldb + k0 + half;
            bf16* dH = base + 2 * TILE + row * P + half;
            bf16* dL = base + 3 * TILE + row * P + half;
#pragma unroll
            for (int c = 0; c < 16; c += 8) {
                int sz = (gn < N && (k0 + half + c) < K) ? 16 : 0;
                cpa16(s2u(dH + c), Bhi + so + c, sz);
                cpa16(s2u(dL + c), Blo + so + c, sz);
            }
        }
    };

    load_stage(0, 0);
    CP_COMMIT();

    for (int s = 0; s < nsteps; s++) {
        if (s + 1 < nsteps) load_stage((s + 1) & 1, (s + 1) * 32);
        CP_COMMIT();
        CP_WAIT1();
        __syncthreads();

        const bf16* base = smb + (s & 1) * 4 * TILE;
        uint32_t aAH = s2u(base + 0 * TILE + aOff);
        uint32_t aAL = s2u(base + 1 * TILE + aOff);
        uint32_t aBH = s2u(base + 2 * TILE + bOff);
        uint32_t aBL = s2u(base + 3 * TILE + bOff);

#pragma unroll
        for (int ks = 0; ks < 32; ks += 16) {
            uint32_t aH[2][4], aL[2][4];
#pragma unroll
            for (int i = 0; i < 2; i++) {
                uint32_t ao = (uint32_t)((i * 16 * P + ks) * 2);
                ldsm4(aH[i][0], aH[i][1], aH[i][2], aH[i][3], aAH + ao);
                ldsm4(aL[i][0], aL[i][1], aL[i][2], aL[i][3], aAL + ao);
            }
#pragma unroll
            for (int j2 = 0; j2 < 4; j2++) {
                uint32_t bo = (uint32_t)((j2 * 16 * P + ks) * 2);
                uint32_t bh[4], bl[4];
                ldsm4(bh[0], bh[1], bh[2], bh[3], aBH + bo);
                ldsm4(bl[0], bl[1], bl[2], bl[3], aBL + bo);
#pragma unroll
                for (int jj = 0; jj < 2; jj++) {
                    int j = j2 * 2 + jj;
                    uint32_t bH0 = bh[jj*2], bH1 = bh[jj*2+1];
                    uint32_t bL0 = bl[jj*2], bL1 = bl[jj*2+1];
#pragma unroll
                    for (int i = 0; i < 2; i++) {
                        asm volatile(
                            "mma.sync.aligned.m16n8k16.row.col.f32.bf16.bf16.f32 "
                            "{%0,%1,%2,%3}, {%4,%5,%6,%7}, {%8,%9}, {%0,%1,%2,%3};"
                            : "+f"(acc[i][j][0]), "+f"(acc[i][j][1]),
                              "+f"(acc[i][j][2]), "+f"(acc[i][j][3])
                            : "r"(aH[i][0]), "r"(aH[i][1]), "r"(aH[i][2]), "r"(aH[i][3]),
                              "r"(bL0), "r"(bL1));
                        asm volatile(
                            "mma.sync.aligned.m16n8k16.row.col.f32.bf16.bf16.f32 "
                            "{%0,%1,%2,%3}, {%4,%5,%6,%7}, {%8,%9}, {%0,%1,%2,%3};"
                            : "+f"(acc[i][j][0]), "+f"(acc[i][j][1]),
                              "+f"(acc[i][j][2]), "+f"(acc[i][j][3])
                            : "r"(aL[i][0]), "r"(aL[i][1]), "r"(aL[i][2]), "r"(aL[i][3]),
                              "r"(bH0), "r"(bH1));
                        asm volatile(
                            "mma.sync.aligned.m16n8k16.row.col.f32.bf16.bf16.f32 "
                            "{%0,%1,%2,%3}, {%4,%5,%6,%7}, {%8,%9}, {%0,%1,%2,%3};"
                            : "+f"(acc[i][j][0]), "+f"(acc[i][j][1]),
                              "+f"(acc[i][j][2]), "+f"(acc[i][j][3])
                            : "r"(aH[i][0]), "r"(aH[i][1]), "r"(aH[i][2]), "r"(aH[i][3]),
                              "r"(bH0), "r"(bH1));
                    }
                }
            }
        }
        __syncthreads();
    }

    // ---- epilogue ----
#pragma unroll
    for (int i = 0; i < 2; i++) {
        int row0 = m0 + wm * 32 + i * 16 + r;
#pragma unroll
        for (int j = 0; j < 8; j++) {
            int col0 = n0 + wn * 64 + j * 8 + cq * 2;
#pragma unroll
            for (int t = 0; t < 4; t++) {
                int row = row0 + (t >> 1) * 8;
                int col = col0 + (t & 1);
                if (row < M && col < N) {
                    float v = acc[i][j][t];
                    if (bias) v += bias[col];
                    if (EPI == 1 || EPI == 4 || EPI == 6 || EPI == 7) v = softp_(v);
                    else if (EPI == 2) v = fmaxf(v, 0.0f);
                    else if (EPI == 3) v = v * (-expm1f(-100.0f * join2(Mhi, Mlo, (size_t)row * ldh + col)));

                    if (EPI == 0) {
                        ((float*)C0)[(size_t)row * ldc + col] = v;
                    } else if (EPI == 1 || EPI == 2 || EPI == 3) {
                        store2(C0, C1, (size_t)row * ldc + col, v);
                    } else if (EPI == 4) {
                        store2(C0, C1, (size_t)row * ldc + col, v);
                        store2(D0, D1, (size_t)row * ldd + col,
                               W8[(size_t)col * 257] * (-expm1f(-100.0f * v)));
                    } else if (EPI == 5) {
                        if (col == 0) ((float*)C0)[row] = v;
                        else store2(D0, D1, (size_t)row * ldd + 8 + col, v);
                    } else if (EPI == 6) {
                        store2(C0, C1, (size_t)row * ldc + col, v);
                        store2(D0, D1, (size_t)row * ldd + col, v * 0.7071067811865476f);
                    } else if (EPI == 7) {
                        store2(D0, D1, (size_t)row * ldd + col, v * 0.7071067811865476f);
                    } else if (EPI == 8) {
                        float vs = v * 0.7071067811865476f;
                        if (col < 217) {
                            store2(C0, C1, (size_t)row * 224 + col,
                                   vs * (-expm1f(-100.0f * join2(Mhi, Mlo, (size_t)row * ldh + col))));
                        } else {
                            if (col < 224) store2(C0, C1, (size_t)row * 224 + col, 0.0f);
                            GE[(size_t)row * 39 + col - 217] = vs;
                        }
                    }
                }
            }
        }
    }
}

// ===================== small kernels =====================

__global__ void k_ray_init(const float* __restrict__ ro, const float* __restrict__ rd,
                           float* __restrict__ Z)
{
    int r = blockIdx.x * blockDim.x + threadIdx.x;
    if (r >= R_RAYS) return;
    float ox = ro[r*3], oy = ro[r*3+1], oz = ro[r*3+2];
    float dx = rd[r*3], dy = rd[r*3+1], dz = rd[r*3+2];
    float a = dx*dx + dy*dy + dz*dz;
    float b = 2.0f * (ox*dx + oy*dy + oz*dz);
    float mid = -b / (2.0f * a);
    float nv = fmaxf(mid - 1.0f, 0.05f);
    float fv = mid + 1.0f;
    for (int s = 0; s < 64; s++)
        Z[r*64 + s] = nv + (fv - nv) * ((float)s * (1.0f/63.0f));
}

__global__ void k_pts(const float* __restrict__ Z, const float* __restrict__ ro,
                      const float* __restrict__ rd, float* __restrict__ P, int S, int M)
{
    int m = blockIdx.x * blockDim.x + threadIdx.x;
    if (m >= M) return;
    int r = m / S;
    float z = Z[m];
#pragma unroll
    for (int j = 0; j < 3; j++)
        P[(size_t)m*3 + j] = fmaf(rd[r*3+j], z, ro[r*3+j]);
}

__global__ void k_dist_mid_pts(const float* __restrict__ Z, const float* __restrict__ ro,
                               const float* __restrict__ rd, float* __restrict__ P,
                               float* __restrict__ D)
{
    int m = blockIdx.x * blockDim.x + threadIdx.x;
    if (m >= (int)NPTS) return;
    int s = m & 127, r = m >> 7;
    float z = Z[m];
    float d = (s < 127) ? (Z[m+1] - z) : 0.03125f;
    D[m] = d;
    float mz = fmaf(0.5f, d, z);
#pragma unroll
    for (int j = 0; j < 3; j++)
        P[(size_t)m*3 + j] = fmaf(rd[r*3+j], mz, ro[r*3+j]);
}

// embed: writes E planes AND the concat tail (scaled) into tail buffer
__global__ void k_embed(const float* __restrict__ P, bf16* __restrict__ Eh,
                        bf16* __restrict__ El, bf16* __restrict__ Th,
                        bf16* __restrict__ Tl, int tp, int M)
{
    int m = blockIdx.x * blockDim.x + threadIdx.x;
    if (m >= M) return;
    float p0 = P[(size_t)m*3], p1 = P[(size_t)m*3+1], p2 = P[(size_t)m*3+2];
    size_t b = (size_t)m * 40;
    size_t tb = (size_t)m * tp + 217;
    float e[39];
    e[0] = p0; e[1] = p1; e[2] = p2;
    float f = 1.0f;
#pragma unroll
    for (int k = 0; k < 6; k++) {
        float s0,c0,s1,c1,s2,c2;
        sincosf(f*p0,&s0,&c0); sincosf(f*p1,&s1,&c1); sincosf(f*p2,&s2,&c2);
        e[3+6*k+0]=s0; e[3+6*k+1]=s1; e[3+6*k+2]=s2;
        e[3+6*k+3]=c0; e[3+6*k+4]=c1; e[3+6*k+5]=c2;
        f *= 2.0f;
    }
#pragma unroll
    for (int c = 0; c < 39; c++) {
        store2(Eh, El, b + c, e[c]);
        store2(Th, Tl, tb + c, e[c] * 0.7071067811865476f);
    }
    store2(Eh, El, b + 39, 0.0f);
}

__global__ void k_sdf_head(const bf16* __restrict__ Hh, const bf16* __restrict__ Hl,
                           const float* __restrict__ W8, const float* __restrict__ b8,
                           float* __restrict__ out, int M)
{
    int gw = (blockIdx.x * blockDim.x + threadIdx.x) >> 5;
    int lane = threadIdx.x & 31;
    if (gw >= M) return;
    size_t b = (size_t)gw * 256;
    float s = 0.0f;
#pragma unroll
    for (int k = lane; k < 256; k += 32) s = fmaf(join2(Hh, Hl, b + k), W8[(size_t)k*257], s);
#pragma unroll
    for (int o = 16; o; o >>= 1) s += __shfl_xor_sync(0xffffffffu, s, o);
    if (!lane) out[gw] = s + b8[0];
}

__global__ void k_upsample(const float* __restrict__ ro, const float* __restrict__ rd,
                           const float* __restrict__ Z, const float* __restrict__ SD,
                           float* __restrict__ ZN, int S, float inv_s)
{
    int r = blockIdx.x * blockDim.x + threadIdx.x;
    if (r >= R_RAYS) return;
    float ox = ro[r*3], oy = ro[r*3+1], oz = ro[r*3+2];
    float dx = rd[r*3], dy = rd[r*3+1], dz = rd[r*3+2];
    const float* zr = Z + (size_t)r * S;
    const float* sr = SD + (size_t)r * S;

    float w[128], cdf[129];
    float prev_raw = 0.0f, T = 1.0f, wsum = 0.0f;
    float z_i = zr[0];
    float px = fmaf(dx,z_i,ox), py = fmaf(dy,z_i,oy), pz = fmaf(dz,z_i,oz);
    float rad_i = sqrtf(px*px + py*py + pz*pz);
    float sdf_i = sr[0];

    for (int i = 0; i < S - 1; i++) {
        float z_n = zr[i+1], sdf_n = sr[i+1];
        float qx = fmaf(dx,z_n,ox), qy = fmaf(dy,z_n,oy), qz = fmaf(dz,z_n,oz);
        float rad_n = sqrtf(qx*qx + qy*qy + qz*qz);
        bool inside = (rad_i < 1.0f) || (rad_n < 1.0f);
        float mid_sdf = 0.5f * (sdf_i + sdf_n);
        float raw = (sdf_n - sdf_i) / (z_n - z_i + 1e-5f);
        float cosv = fminf(raw, prev_raw);
        prev_raw = raw;
        cosv = fminf(fmaxf(cosv, -1000.0f), 0.0f);
        if (!inside) cosv = 0.0f;
        float dist = z_n - z_i;
        float pc = sigmoidf_((mid_sdf - cosv*dist*0.5f) * inv_s);
        float nc = sigmoidf_((mid_sdf + cosv*dist*0.5f) * inv_s);
        float alpha = (pc - nc + 1e-5f) / (pc + 1e-5f);
        float wi = alpha * T;
        T *= (1.0f - alpha + 1e-7f);
        wi += 1e-5f;
        w[i] = wi; wsum += wi;
        z_i = z_n; rad_i = rad_n; sdf_i = sdf_n;
    }

    cdf[0] = 0.0f;
    float invsum = 1.0f / wsum;
    for (int i = 0; i < S - 1; i++) cdf[i+1] = cdf[i] + w[i] * invsum;

    for (int j = 0; j < 16; j++) {
        float u = 0.03125f + (float)j * 0.0625f;
        int lo = 0, hi = S;
        while (lo < hi) { int md = (lo + hi) >> 1; if (cdf[md] <= u) lo = md + 1; else hi = md; }
        int below = lo - 1; if (below < 0) below = 0; if (below > S-1) below = S-1;
        int above = lo;     if (above > S-1) above = S-1;
        float c0 = cdf[below], c1 = cdf[above];
        float b0 = zr[below],  b1 = zr[above];
        float den = (c1 - c0) < 1e-5f ? 1.0f : (c1 - c0);
        ZN[r*16 + j] = b0 + (u - c0) / den * (b1 - b0);
    }
}

__global__ void k_merge(const float* __restrict__ Z, const float* __restrict__ SD,
                        const float* __restrict__ ZN, const float* __restrict__ SN,
                        float* __restrict__ ZT, float* __restrict__ ST, int S)
{
    int r = blockIdx.x * blockDim.x + threadIdx.x;
    if (r >= R_RAYS) return;
    const float* zo = Z + (size_t)r*S;  const float* so = SD + (size_t)r*S;
    const float* zn = ZN + r*16;        const float* sn = SN + r*16;
    float* zt = ZT + (size_t)r*(S+16);  float* st = ST + (size_t)r*(S+16);
    int i = 0, j = 0;
    for (int k = 0; k < S + 16; k++) {
        bool useOld = (i < S) && ((j >= 16) || (zo[i] <= zn[j]));
        if (useOld) { zt[k] = zo[i]; st[k] = so[i]; i++; }
        else        { zt[k] = zn[j]; st[k] = sn[j]; j++; }
    }
}

__global__ void k_copy(float* __restrict__ dst, const float* __restrict__ src, int n)
{
    int i = blockIdx.x * blockDim.x + threadIdx.x;
    if (i < n) dst[i] = src[i];
}

__global__ void k_gradpts(const float* __restrict__ GEm, const float* __restrict__ GEs,
                          const float* __restrict__ P, float* __restrict__ GR, int M)
{
    int m = blockIdx.x * blockDim.x + threadIdx.x;
    if (m >= M) return;
    const float* ga = GEm + (size_t)m*39;
    const float* gb = GEs + (size_t)m*39;
    float p[3] = {P[(size_t)m*3], P[(size_t)m*3+1], P[(size_t)m*3+2]};
    float g[3];
#pragma unroll
    for (int j = 0; j < 3; j++) g[j] = ga[j] + gb[j];
    float f = 1.0f;
#pragma unroll
    for (int k = 0; k < 6; k++) {
#pragma unroll
        for (int j = 0; j < 3; j++) {
            float s, c;
            sincosf(f * p[j], &s, &c);
            float gs = ga[3+6*k+j]   + gb[3+6*k+j];
            float gc = ga[3+6*k+3+j] + gb[3+6*k+3+j];
            g[j] = fmaf( f * c, gs, g[j]);
            g[j] = fmaf(-f * s, gc, g[j]);
        }
        f *= 2.0f;
    }
#pragma unroll
    for (int j = 0; j < 3; j++) GR[(size_t)m*3 + j] = g[j];
}

__global__ void k_alpha(const float* __restrict__ SDFO, const float* __restrict__ GR,
                        const float* __restrict__ D, const float* __restrict__ rd,
                        const float* __restrict__ var, float* __restrict__ A, int M)
{
    int m = blockIdx.x * blockDim.x + threadIdx.x;
    if (m >= M) return;
    int r = m >> 7;
    float tc = rd[r*3]*GR[(size_t)m*3] + rd[r*3+1]*GR[(size_t)m*3+1] + rd[r*3+2]*GR[(size_t)m*3+2];
    float ic = fminf(tc, 0.0f);
    float sdf = SDFO[m];
    float dist = D[m];
    float inv_s = fminf(fmaxf(expf(10.0f * var[0]), 1e-6f), 1e6f);
    float pc = sigmoidf_((sdf - ic*dist*0.5f) * inv_s);
    float nc = sigmoidf_((sdf + ic*dist*0.5f) * inv_s);
    float a = (pc - nc + 1e-5f) / (pc + 1e-5f);
    A[m] = fminf(fmaxf(a, 0.0f), 1.0f);
}

__global__ void k_ray_weights(const float* __restrict__ A, float* __restrict__ W)
{
    int r = blockIdx.x * blockDim.x + threadIdx.x;
    if (r >= R_RAYS) return;
    float T = 1.0f;
    for (int s = 0; s < 128; s++) {
        int m = r*128 + s;
        float a = A[m];
        W[m] = a * T;
        T *= (1.0f - a + 1e-7f);
    }
}

// fill CIN cols 0..8 (pts/dirs/normals) and 265..271 (pad)
__global__ void k_cin9(const float* __restrict__ P, const float* __restrict__ rd,
                       const float* __restrict__ GR, bf16* __restrict__ Ch,
                       bf16* __restrict__ Cl, int M)
{
    int idx = blockIdx.x * blockDim.x + threadIdx.x;
    if (idx >= M * 16) return;
    int m = idx >> 4, c = idx & 15;
    if (c < 9) {
        float v;
        if (c < 3) v = P[(size_t)m*3 + c];
        else if (c < 6) { int r = m >> 7; v = rd[r*3 + (c-3)]; }
        else {
            float g0 = GR[(size_t)m*3], g1 = GR[(size_t)m*3+1], g2 = GR[(size_t)m*3+2];
            float n = fmaxf(sqrtf(g0*g0 + g1*g1 + g2*g2), 1e-6f);
            v = GR[(size_t)m*3 + (c-6)] / n;
        }
        store2(Ch, Cl, (size_t)m*272 + c, v);
    } else {
        store2(Ch, Cl, (size_t)m*272 + 265 + (c - 9), 0.0f);
    }
}

__global__ void k_color_head(const bf16* __restrict__ Hh, const bf16* __restrict__ Hl,
                             const float* __restrict__ W, const float* __restrict__ b,
                             float* __restrict__ rgbs, int M)
{
    int gw = (blockIdx.x * blockDim.x + threadIdx.x) >> 5;
    int lane = threadIdx.x & 31;
    if (gw >= M) return;
    size_t hb = (size_t)gw * 256;
    float a0 = 0.f, a1 = 0.f, a2 = 0.f;
#pragma unroll
    for (int k = lane; k < 256; k += 32) {
        float hv = join2(Hh, Hl, hb + k);
        a0 = fmaf(hv, W[k*3+0], a0);
        a1 = fmaf(hv, W[k*3+1], a1);
        a2 = fmaf(hv, W[k*3+2], a2);
    }
#pragma unroll
    for (int o = 16; o; o >>= 1) {
        a0 += __shfl_xor_sync(0xffffffffu, a0, o);
        a1 += __shfl_xor_sync(0xffffffffu, a1, o);
        a2 += __shfl_xor_sync(0xffffffffu, a2, o);
    }
    if (!lane) {
        rgbs[(size_t)gw*3+0] = sigmoidf_(a0 + b[0]);
        rgbs[(size_t)gw*3+1] = sigmoidf_(a1 + b[1]);
        rgbs[(size_t)gw*3+2] = sigmoidf_(a2 + b[2]);
    }
}

__global__ void k_reduce(const float* __restrict__ W, const float* __restrict__ rgbs,
                         float* __restrict__ out)
{
    int r = blockIdx.x * blockDim.x + threadIdx.x;
    if (r >= R_RAYS) return;
    float s0 = 0.f, s1 = 0.f, s2 = 0.f;
    for (int s = 0; s < 128; s++) {
        int m = r*128 + s;
        float w = W[m];
        s0 = fmaf(w, rgbs[(size_t)m*3+0], s0);
        s1 = fmaf(w, rgbs[(size_t)m*3+1], s1);
        s2 = fmaf(w, rgbs[(size_t)m*3+2], s2);
    }
    out[r*3+0] = s0; out[r*3+1] = s1; out[r*3+2] = s2;
}

// ===================== host orchestration =====================

static const int GEMM_SHM = 81920;

struct Plane { bf16* hi; bf16* lo; };
static Plane PNONE = {nullptr, nullptr};

template <int EPI>
static void launch_bf3(Plane A, int lda, Plane B, int ldb, const float* bias,
                       Plane Hm, int ldh, void* C0, void* C1, int ldc,
                       Plane D, int ldd, const float* W8, float* GE,
                       int M, int N, int K)
{
    dim3 g((N + 127) / 128, (M + 127) / 128);
    cudaFuncSetAttribute(gemm_bf3<EPI>, cudaFuncAttributeMaxDynamicSharedMemorySize, GEMM_SHM);
    gemm_bf3<EPI><<<g, 256, GEMM_SHM>>>(A.hi, A.lo, lda, B.hi, B.lo, ldb, bias,
                                        Hm.hi, Hm.lo, ldh, C0, C1, ldc,
                                        D.hi, D.lo, ldd, W8, GE, M, N, K);
}

struct Ctx {
    Plane act[13];
    Plane wb[19];
    const float* sb[9]; const float* cb[3];
    const float* sw8raw; const float* cw2raw;
};
enum { E_=0, H0_, H1_, H2_, H3_, I4_, A4_, A5_, A6_, A7_, GP_, GQ_, CIN_ };

static void sdf_forward_nostore(int M, const Ctx& X, float* fbase, float* sdf_dest)
{
    Plane E = X.act[E_], GP = X.act[GP_], GQ = X.act[GQ_], CIN = X.act[CIN_];
    float* PP = fbase + O_PTS;
    k_embed<<<(M+255)/256, 256>>>(PP, E.hi, E.lo, CIN.hi, CIN.lo, 272, M);
    launch_bf3<1>(E, 40,   X.wb[0], 40,  X.sb[0], PNONE,0, GP.hi,GP.lo,256, PNONE,0,nullptr,nullptr, M,256,40);
    launch_bf3<1>(GP, 256, X.wb[1], 256, X.sb[1], PNONE,0, GQ.hi,GQ.lo,256, PNONE,0,nullptr,nullptr, M,256,256);
    launch_bf3<1>(GQ, 256, X.wb[2], 256, X.sb[2], PNONE,0, GP.hi,GP.lo,256, PNONE,0,nullptr,nullptr, M,256,256);
    launch_bf3<7>(GP, 256, X.wb[3], 256, X.sb[3], PNONE,0, nullptr,nullptr,0, CIN,272,nullptr,nullptr, M,217,256);
    launch_bf3<1>(CIN, 272, X.wb[4], 256, X.sb[4], PNONE,0, GQ.hi,GQ.lo,256, PNONE,0,nullptr,nullptr, M,256,256);
    launch_bf3<1>(GQ, 256, X.wb[5], 256, X.sb[5], PNONE,0, GP.hi,GP.lo,256, PNONE,0,nullptr,nullptr, M,256,256);
    launch_bf3<1>(GP, 256, X.wb[6], 256, X.sb[6], PNONE,0, GQ.hi,GQ.lo,256, PNONE,0,nullptr,nullptr, M,256,256);
    launch_bf3<1>(GQ, 256, X.wb[7], 256, X.sb[7], PNONE,0, GP.hi,GP.lo,256, PNONE,0,nullptr,nullptr, M,256,256);
    k_sdf_head<<<(M*32+255)/256, 256>>>(GP.hi, GP.lo, X.sw8raw, X.sb[8], sdf_dest, M);
}

extern "C" void kernel_launch(void* const* d_in, const int* in_sizes, int n_in,
                              void* d_out, int out_size)
{
    const float* ro = (const float*)d_in[0];
    const float* rd = (const float*)d_in[1];
    const float* sw[9]; const float* sb[9];
    const float* cw[3]; const float* cb[3];
    const float* var;

    bool interleaved = (in_sizes[3] < 1024);
    if (interleaved) {
        for (int l = 0; l < 9; l++) { sw[l] = (const float*)d_in[2 + 2*l]; sb[l] = (const float*)d_in[3 + 2*l]; }
        for (int l = 0; l < 3; l++) { cw[l] = (const float*)d_in[20 + 2*l]; cb[l] = (const float*)d_in[21 + 2*l]; }
        var = (const float*)d_in[26];
    } else {
        for (int l = 0; l < 9; l++) { sw[l] = (const float*)d_in[2 + l]; sb[l] = (const float*)d_in[11 + l]; }
        for (int l = 0; l < 3; l++) { cw[l] = (const float*)d_in[20 + l]; cb[l] = (const float*)d_in[23 + l]; }
        var = (const float*)d_in[26];
    }
    float* out = (float*)d_out;

    float* fbase = nullptr;
    bf16* bbase = nullptr;
    cudaGetSymbolAddress((void**)&fbase, d_F32);
    cudaGetSymbolAddress((void**)&bbase, d_BF);

    float* PZ = fbase+O_Z;     float* PSDF = fbase+O_SDF;
    float* PZT = fbase+O_ZT;   float* PSDFT = fbase+O_SDFT;
    float* PZN = fbase+O_ZNEW; float* PSDFN = fbase+O_SDFNEW;
    float* PP = fbase+O_PTS;   float* PD = fbase+O_DIST;
    float* PSDFO = fbase+O_SDFO; float* PGE = fbase+O_GE; float* PGEM = fbase+O_GEM;
    float* PGR = fbase+O_GRAD; float* PA = fbase+O_ALPHA;
    float* PW = fbase+O_WT;    float* PRGB = fbase+O_RGBS;

    Ctx X;
    for (int i = 0; i < 13; i++) {
        X.act[i].hi = bbase + aoff(i);
        X.act[i].lo = bbase + aoff(i) + NPTS * AW[i];
    }
    bf16* wb0 = bbase + BF_ACT_TOTAL;
    for (int i = 0; i < 19; i++) {
        X.wb[i].hi = wb0 + woff(i);
        X.wb[i].lo = wb0 + woff(i) + WN[i] * WK[i];
    }
    for (int l = 0; l < 9; l++) X.sb[l] = sb[l];
    for (int l = 0; l < 3; l++) X.cb[l] = cb[l];
    X.sw8raw = sw[8]; X.cw2raw = cw[2];

    // ---- fused weight plane prep (ONE launch) ----
    {
        WSrc ws;
        const float* wsrc[19] = { sw[0],sw[1],sw[2],sw[3],sw[4],sw[5],sw[6],sw[7],sw[8],
                                  cw[0],cw[1],
                                  sw[7],sw[6],sw[5],sw[4],sw[3],sw[2],sw[1],sw[0] };
        for (int i = 0; i < 19; i++) ws.p[i] = wsrc[i];
        int total = (int)(BF_W_TOTAL / 2);
        k_wprep_all<<<(total+255)/256, 256>>>(ws, wb0, total);
    }

    Plane E = X.act[E_], H0 = X.act[H0_], H1 = X.act[H1_], H2 = X.act[H2_];
    Plane H3 = X.act[H3_], I4 = X.act[I4_], A4 = X.act[A4_], A5 = X.act[A5_];
    Plane A6 = X.act[A6_], A7 = X.act[A7_], GP = X.act[GP_], GQ = X.act[GQ_];
    Plane CIN = X.act[CIN_];

    // ---- initial 64 samples + sdf ----
    k_ray_init<<<4, 256>>>(ro, rd, PZ);
    int S = 64;
    int M = R_RAYS * S;
    k_pts<<<(M+255)/256, 256>>>(PZ, ro, rd, PP, S, M);
    sdf_forward_nostore(M, X, fbase, PSDF);

    // ---- 4 importance-sampling rounds ----
    for (int i = 0; i < 4; i++) {
        float inv_s = 64.0f * (float)(1 << i);
        k_upsample<<<4, 256>>>(ro, rd, PZ, PSDF, PZN, S, inv_s);
        int Mn = R_RAYS * 16;
        k_pts<<<(Mn+255)/256, 256>>>(PZN, ro, rd, PP, 16, Mn);
        sdf_forward_nostore(Mn, X, fbase, PSDFN);
        k_merge<<<4, 256>>>(PZ, PSDF, PZN, PSDFN, PZT, PSDFT, S);
        S += 16;
        int n = R_RAYS * S;
        k_copy<<<(n+255)/256, 256>>>(PZ, PZT, n);
        k_copy<<<(n+255)/256, 256>>>(PSDF, PSDFT, n);
    }

    // ---- final forward (stored activations, fused concat/bwinit/out8) ----
    M = (int)NPTS;
    k_dist_mid_pts<<<(M+255)/256, 256>>>(PZ, ro, rd, PP, PD);
    k_embed<<<(M+255)/256, 256>>>(PP, E.hi, E.lo, I4.hi, I4.lo, 256, M);
    launch_bf3<1>(E, 40,   X.wb[0], 40,  sb[0], PNONE,0, H0.hi,H0.lo,256, PNONE,0,nullptr,nullptr, M,256,40);
    launch_bf3<1>(H0, 256, X.wb[1], 256, sb[1], PNONE,0, H1.hi,H1.lo,256, PNONE,0,nullptr,nullptr, M,256,256);
    launch_bf3<1>(H1, 256, X.wb[2], 256, sb[2], PNONE,0, H2.hi,H2.lo,256, PNONE,0,nullptr,nullptr, M,256,256);
    launch_bf3<6>(H2, 256, X.wb[3], 256, sb[3], PNONE,0, H3.hi,H3.lo,224, I4,256,nullptr,nullptr, M,217,256);
    launch_bf3<1>(I4, 256, X.wb[4], 256, sb[4], PNONE,0, A4.hi,A4.lo,256, PNONE,0,nullptr,nullptr, M,256,256);
    launch_bf3<1>(A4, 256, X.wb[5], 256, sb[5], PNONE,0, A5.hi,A5.lo,256, PNONE,0,nullptr,nullptr, M,256,256);
    launch_bf3<1>(A5, 256, X.wb[6], 256, sb[6], PNONE,0, A6.hi,A6.lo,256, PNONE,0,nullptr,nullptr, M,256,256);
    launch_bf3<4>(A6, 256, X.wb[7], 256, sb[7], PNONE,0, A7.hi,A7.lo,256, GP,256, sw[8],nullptr, M,256,256);
    launch_bf3<5>(A7, 256, X.wb[8], 256, sb[8], PNONE,0, PSDFO,nullptr,0, CIN,272,nullptr,nullptr, M,257,256);

    // ---- backward VJP (g_z7 already in GP from EPI4) ----
    launch_bf3<3>(GP, 256, X.wb[11], 256, nullptr, A6,256, GQ.hi,GQ.lo,256, PNONE,0,nullptr,nullptr, M,256,256);
    launch_bf3<3>(GQ, 256, X.wb[12], 256, nullptr, A5,256, GP.hi,GP.lo,256, PNONE,0,nullptr,nullptr, M,256,256);
    launch_bf3<3>(GP, 256, X.wb[13], 256, nullptr, A4,256, GQ.hi,GQ.lo,256, PNONE,0,nullptr,nullptr, M,256,256);
    launch_bf3<8>(GQ, 256, X.wb[14], 256, nullptr, H3,224, GP.hi,GP.lo,224, PNONE,0,nullptr,PGE, M,256,256);
    launch_bf3<3>(GP, 224, X.wb[15], 224, nullptr, H2,256, GQ.hi,GQ.lo,256, PNONE,0,nullptr,nullptr, M,256,224);
    launch_bf3<3>(GQ, 256, X.wb[16], 256, nullptr, H1,256, GP.hi,GP.lo,256, PNONE,0,nullptr,nullptr, M,256,256);
    launch_bf3<3>(GP, 256, X.wb[17], 256, nullptr, H0,256, GQ.hi,GQ.lo,256, PNONE,0,nullptr,nullptr, M,256,256);
    launch_bf3<0>(GQ, 256, X.wb[18], 256, nullptr, PNONE,0, PGEM,nullptr,39, PNONE,0,nullptr,nullptr, M,39,256);
    k_gradpts<<<(M+255)/256, 256>>>(PGEM, PGE, PP, PGR, M);

    // ---- color net + compositing ----
    k_alpha<<<(M+255)/256, 256>>>(PSDFO, PGR, PD, rd, var, PA, M);
    k_ray_weights<<<4, 256>>>(PA, PW);
    k_cin9<<<(M*16+255)/256, 256>>>(PP, rd, PGR, CIN.hi, CIN.lo, M);
    launch_bf3<2>(CIN, 272, X.wb[9], 272, cb[0], PNONE,0, GP.hi,GP.lo,256, PNONE,0,nullptr,nullptr, M,256,272);
    launch_bf3<2>(GP, 256, X.wb[10], 256, cb[1], PNONE,0, GQ.hi,GQ.lo,256, PNONE,0,nullptr,nullptr, M,256,256);
    k_color_head<<<(M*32+255)/256, 256>>>(GQ.hi, GQ.lo, cw[2], cb[2], PRGB, M);
    k_reduce<<<4, 256>>>(PW, PRGB, out);
}

// round 15
// speedup vs baseline: 2.1190x; 1.2423x over previous
#include <cuda_runtime.h>
#include <cuda_bf16.h>
#include <math.h>
#include <stdint.h>
#include <stddef.h>

typedef __nv_bfloat16 bf16;

#define R_RAYS 1024
static constexpr size_t NPTS = 131072;

// ================= f32 scratch =================
constexpr size_t O_Z      = 0;
constexpr size_t O_SDF    = O_Z + NPTS;
constexpr size_t O_ZT     = O_SDF + NPTS;
constexpr size_t O_SDFT   = O_ZT + NPTS;
constexpr size_t O_ZNEW   = O_SDFT + NPTS;
constexpr size_t O_SDFNEW = O_ZNEW + 16384;
constexpr size_t O_PTS    = O_SDFNEW + 16384;
constexpr size_t O_DIST   = O_PTS + NPTS * 3;
constexpr size_t O_SDFO   = O_DIST + NPTS;
constexpr size_t O_GE     = O_SDFO + NPTS;
constexpr size_t O_GEM    = O_GE + NPTS * 39;
constexpr size_t O_GRAD   = O_GEM + NPTS * 39;
constexpr size_t O_ALPHA  = O_GRAD + NPTS * 3;
constexpr size_t O_WT     = O_ALPHA + NPTS;
constexpr size_t O_RGBS   = O_WT + NPTS;
constexpr size_t F32_TOTAL = O_RGBS + NPTS * 3;
__device__ __align__(256) float d_F32[F32_TOTAL];

// ================= bf16 plane scratch =================
constexpr size_t AW[13] = {40,256,256,256,224,256,256,256,256,256,256,256,272};
constexpr size_t aoff(int i) { size_t o = 0; for (int j = 0; j < i; j++) o += AW[j] * 2; return o * NPTS; }
constexpr size_t BF_ACT_TOTAL = aoff(13);
constexpr size_t WN[19] = {256,256,256,217,256,256,256,256,257, 256,256, 256,256,256,256,256,256,256, 39};
constexpr size_t WK[19] = {40, 256,256,256,256,256,256,256,256, 272,256, 256,256,256,256,224,256,256, 256};
constexpr size_t woff(int i) { size_t o = 0; for (int j = 0; j < i; j++) o += WN[j] * WK[j] * 2; return o; }
constexpr size_t BF_W_TOTAL = woff(19);
__device__ __align__(256) bf16 d_BF[BF_ACT_TOTAL + BF_W_TOTAL];

__device__ __forceinline__ float sigmoidf_(float x) { return 1.0f / (1.0f + expf(-x)); }
__device__ __forceinline__ void store2(void* hi, void* lo, size_t i, float v) {
    bf16 h = __float2bfloat16(v);
    ((bf16*)hi)[i] = h;
    ((bf16*)lo)[i] = __float2bfloat16(v - __bfloat162float(h));
}
__device__ __forceinline__ void store2x2(void* hi, void* lo, size_t i, float v0, float v1) {
    bf16 h0 = __float2bfloat16(v0), h1 = __float2bfloat16(v1);
    __nv_bfloat162 hh; hh.x = h0; hh.y = h1;
    *(__nv_bfloat162*)((bf16*)hi + i) = hh;
    __nv_bfloat162 ll;
    ll.x = __float2bfloat16(v0 - __bfloat162float(h0));
    ll.y = __float2bfloat16(v1 - __bfloat162float(h1));
    *(__nv_bfloat162*)((bf16*)lo + i) = ll;
}
__device__ __forceinline__ float join2(const bf16* hi, const bf16* lo, size_t i) {
    return __bfloat162float(hi[i]) + __bfloat162float(lo[i]);
}
__device__ __forceinline__ float softp_(float v) {
    float s = 100.0f * v;
    return (fmaxf(s, 0.0f) + log1pf(expf(-fabsf(s)))) * 0.01f;
}

__device__ __forceinline__ uint32_t s2u(const void* p) {
    return (uint32_t)__cvta_generic_to_shared(p);
}
__device__ __forceinline__ void cpa16(uint32_t d, const void* s, int sz) {
    asm volatile("cp.async.ca.shared.global [%0], [%1], 16, %2;" :: "r"(d), "l"(s), "r"(sz));
}
#define CP_COMMIT() asm volatile("cp.async.commit_group;")
#define CP_WAIT1()  asm volatile("cp.async.wait_group 1;")

__device__ __forceinline__ void ldsm4(uint32_t& r0, uint32_t& r1, uint32_t& r2, uint32_t& r3,
                                      uint32_t addr) {
    asm volatile("ldmatrix.sync.aligned.m8n8.x4.shared.b16 {%0,%1,%2,%3}, [%4];"
                 : "=r"(r0), "=r"(r1), "=r"(r2), "=r"(r3) : "r"(addr));
}

// ---- fused weight prep ----
struct WSrc { const float* p[19]; };
__global__ void k_wprep_all(WSrc ws, bf16* __restrict__ wb, int total)
{
    const int wn[19] = {256,256,256,217,256,256,256,256,257, 256,256, 256,256,256,256,256,256,256, 39};
    const int wk[19] = {40, 256,256,256,256,256,256,256,256, 272,256, 256,256,256,256,224,256,256, 256};
    const int wr[19] = {39,256,256,256,256,256,256,256,256, 265,256, 256,256,256,256,256,256,256, 39};
    const int wc[19] = {256,256,256,217,256,256,256,256,257, 256,256, 256,256,256,256,217,256,256, 256};

    int idx = blockIdx.x * blockDim.x + threadIdx.x;
    if (idx >= total) return;
    size_t off = (size_t)idx;
    int bi = 0;
    size_t base = 0;
#pragma unroll
    for (int i = 0; i < 19; i++) {
        size_t sz = (size_t)wn[i] * wk[i];
        if (off < sz) { bi = i; break; }
        off -= sz;
        base += 2 * sz;
    }
    int Kp = wk[bi];
    int n = (int)(off / Kp), k = (int)(off % Kp);
    const float* W = ws.p[bi];
    float v = 0.0f;
    if (bi <= 10) { if (k < wr[bi] && n < wc[bi]) v = W[(size_t)k * wc[bi] + n]; }
    else          { if (n < wr[bi] && k < wc[bi]) v = W[(size_t)n * wc[bi] + k]; }
    bf16 h = __float2bfloat16(v);
    wb[base + off] = h;
    wb[base + (size_t)wn[bi] * wk[bi] + off] = __float2bfloat16(v - __bfloat162float(h));
}

// ============================================================================
// bf16x3 GEMM, ldmatrix loads, packed (alignment-guarded) epilogue stores.
// EPI: 0 f32 lin | 1 sp->planes | 2 relu->planes | 3 mask-mul->planes
//      4 sp->planes + bwinit->D | 5 out8: col0->f32 sdf, col>=1 ->CIN planes
//      6 sp->planes + concat->D | 7 sp->concat->D only | 8 split: Gz+GE
// ============================================================================
template <int EPI>
__global__ void __launch_bounds__(256, 2) gemm_bf3(
    const bf16* __restrict__ Ahi, const bf16* __restrict__ Alo, int lda,
    const bf16* __restrict__ Bhi, const bf16* __restrict__ Blo, int ldb,
    const float* __restrict__ bias,
    const bf16* __restrict__ Mhi, const bf16* __restrict__ Mlo, int ldh,
    void* __restrict__ C0, void* __restrict__ C1, int ldc,
    bf16* __restrict__ D0, bf16* __restrict__ D1, int ldd,
    const float* __restrict__ W8, float* __restrict__ GE,
    int M, int N, int K)
{
    extern __shared__ bf16 smb[];
    constexpr int P = 40;
    constexpr int TILE = 128 * P;

    const int tid  = threadIdx.x;
    const int wid  = tid >> 5;
    const int lane = tid & 31;
    const int wm = wid & 3;
    const int wn = wid >> 2;
    const int m0 = blockIdx.y * 128;
    const int n0 = blockIdx.x * 128;
    const int r  = lane >> 2;
    const int cq = lane & 3;

    const int aOff = (wm * 32 + (lane & 15)) * P + ((lane >> 4) << 3);
    const int bOff = (wn * 64 + (lane & 7) + ((lane & 16) >> 1)) * P + (((lane >> 3) & 1) << 3);

    float acc[2][8][4] = {};
    const int nsteps = (K + 31) >> 5;

    auto load_stage = [&](int stage, int k0) {
        bf16* base = smb + stage * 4 * TILE;
        int row  = tid >> 1;
        int half = (tid & 1) * 16;
        {
            int gm = m0 + row;
            size_t so = (size_t)(gm < M ? gm : 0) * lda + k0 + half;
            bf16* dH = base + 0 * TILE + row * P + half;
            bf16* dL = base + 1 * TILE + row * P + half;
#pragma unroll
            for (int c = 0; c < 16; c += 8) {
                int sz = (gm < M && (k0 + half + c) < K) ? 16 : 0;
                cpa16(s2u(dH + c), Ahi + so + c, sz);
                cpa16(s2u(dL + c), Alo + so + c, sz);
            }
        }
        {
            int gn = n0 + row;
            size_t so = (size_t)(gn < N ? gn : 0) * ldb + k0 + half;
            bf16* dH = base + 2 * TILE + row * P + half;
            bf16* dL = base + 3 * TILE + row * P + half;
#pragma unroll
            for (int c = 0; c < 16; c += 8) {
                int sz = (gn < N && (k0 + half + c) < K) ? 16 : 0;
                cpa16(s2u(dH + c), Bhi + so + c, sz);
                cpa16(s2u(dL + c), Blo + so + c, sz);
            }
        }
    };

    load_stage(0, 0);
    CP_COMMIT();

    for (int s = 0; s < nsteps; s++) {
        if (s + 1 < nsteps) load_stage((s + 1) & 1, (s + 1) * 32);
        CP_COMMIT();
        CP_WAIT1();
        __syncthreads();

        const bf16* base = smb + (s & 1) * 4 * TILE;
        uint32_t aAH = s2u(base + 0 * TILE + aOff);
        uint32_t aAL = s2u(base + 1 * TILE + aOff);
        uint32_t aBH = s2u(base + 2 * TILE + bOff);
        uint32_t aBL = s2u(base + 3 * TILE + bOff);

#pragma unroll
        for (int ks = 0; ks < 32; ks += 16) {
            uint32_t aH[2][4], aL[2][4];
#pragma unroll
            for (int i = 0; i < 2; i++) {
                uint32_t ao = (uint32_t)((i * 16 * P + ks) * 2);
                ldsm4(aH[i][0], aH[i][1], aH[i][2], aH[i][3], aAH + ao);
                ldsm4(aL[i][0], aL[i][1], aL[i][2], aL[i][3], aAL + ao);
            }
#pragma unroll
            for (int j2 = 0; j2 < 4; j2++) {
                uint32_t bo = (uint32_t)((j2 * 16 * P + ks) * 2);
                uint32_t bh[4], bl[4];
                ldsm4(bh[0], bh[1], bh[2], bh[3], aBH + bo);
                ldsm4(bl[0], bl[1], bl[2], bl[3], aBL + bo);
#pragma unroll
                for (int jj = 0; jj < 2; jj++) {
                    int j = j2 * 2 + jj;
                    uint32_t bH0 = bh[jj*2], bH1 = bh[jj*2+1];
                    uint32_t bL0 = bl[jj*2], bL1 = bl[jj*2+1];
#pragma unroll
                    for (int i = 0; i < 2; i++) {
                        asm volatile(
                            "mma.sync.aligned.m16n8k16.row.col.f32.bf16.bf16.f32 "
                            "{%0,%1,%2,%3}, {%4,%5,%6,%7}, {%8,%9}, {%0,%1,%2,%3};"
                            : "+f"(acc[i][j][0]), "+f"(acc[i][j][1]),
                              "+f"(acc[i][j][2]), "+f"(acc[i][j][3])
                            : "r"(aH[i][0]), "r"(aH[i][1]), "r"(aH[i][2]), "r"(aH[i][3]),
                              "r"(bL0), "r"(bL1));
                        asm volatile(
                            "mma.sync.aligned.m16n8k16.row.col.f32.bf16.bf16.f32 "
                            "{%0,%1,%2,%3}, {%4,%5,%6,%7}, {%8,%9}, {%0,%1,%2,%3};"
                            : "+f"(acc[i][j][0]), "+f"(acc[i][j][1]),
                              "+f"(acc[i][j][2]), "+f"(acc[i][j][3])
                            : "r"(aL[i][0]), "r"(aL[i][1]), "r"(aL[i][2]), "r"(aL[i][3]),
                              "r"(bH0), "r"(bH1));
                        asm volatile(
                            "mma.sync.aligned.m16n8k16.row.col.f32.bf16.bf16.f32 "
                            "{%0,%1,%2,%3}, {%4,%5,%6,%7}, {%8,%9}, {%0,%1,%2,%3};"
                            : "+f"(acc[i][j][0]), "+f"(acc[i][j][1]),
                              "+f"(acc[i][j][2]), "+f"(acc[i][j][3])
                            : "r"(aH[i][0]), "r"(aH[i][1]), "r"(aH[i][2]), "r"(aH[i][3]),
                              "r"(bH0), "r"(bH1));
                    }
                }
            }
        }
        __syncthreads();
    }

    // ---- epilogue (packed column pairs, alignment-guarded) ----
#pragma unroll
    for (int i = 0; i < 2; i++) {
        int row0 = m0 + wm * 32 + i * 16 + r;
#pragma unroll
        for (int j = 0; j < 8; j++) {
            int col0 = n0 + wn * 64 + j * 8 + cq * 2;
#pragma unroll
            for (int tr = 0; tr < 2; tr++) {
                int row = row0 + tr * 8;
                if (row >= M || col0 >= N) continue;
                float v0 = acc[i][j][tr*2+0];
                float v1 = acc[i][j][tr*2+1];
                bool has1 = (col0 + 1) < N;
                if (bias) { v0 += bias[col0]; if (has1) v1 += bias[col0+1]; }
                if (EPI == 1 || EPI == 4 || EPI == 6 || EPI == 7) { v0 = softp_(v0); v1 = softp_(v1); }
                else if (EPI == 2) { v0 = fmaxf(v0, 0.0f); v1 = fmaxf(v1, 0.0f); }
                else if (EPI == 3) {
                    v0 *= (-expm1f(-100.0f * join2(Mhi, Mlo, (size_t)row * ldh + col0)));
                    if (has1) v1 *= (-expm1f(-100.0f * join2(Mhi, Mlo, (size_t)row * ldh + col0 + 1)));
                }

                size_t ci = (size_t)row * ldc + col0;
                bool aligned = ((ci & 1) == 0);
                if (EPI == 0) {
                    if (has1 && aligned) *(float2*)((float*)C0 + ci) = make_float2(v0, v1);
                    else {
                        ((float*)C0)[ci] = v0;
                        if (has1) ((float*)C0)[ci + 1] = v1;
                    }
                } else if (EPI == 1 || EPI == 2 || EPI == 3) {
                    if (has1 && aligned) store2x2(C0, C1, ci, v0, v1);
                    else {
                        store2(C0, C1, ci, v0);
                        if (has1) store2(C0, C1, ci + 1, v1);
                    }
                } else if (EPI == 4) {
                    float d0 = W8[(size_t)col0 * 257] * (-expm1f(-100.0f * v0));
                    size_t di = (size_t)row * ldd + col0;
                    if (has1 && aligned) {
                        float d1 = W8[(size_t)(col0+1) * 257] * (-expm1f(-100.0f * v1));
                        store2x2(C0, C1, ci, v0, v1);
                        store2x2(D0, D1, di, d0, d1);
                    } else {
                        store2(C0, C1, ci, v0); store2(D0, D1, di, d0);
                        if (has1) {
                            float d1 = W8[(size_t)(col0+1) * 257] * (-expm1f(-100.0f * v1));
                            store2(C0, C1, ci + 1, v1); store2(D0, D1, di + 1, d1);
                        }
                    }
                } else if (EPI == 5) {
                    if (col0 == 0) {
                        ((float*)C0)[row] = v0;
                        if (has1) store2(D0, D1, (size_t)row * ldd + 9, v1);
                    } else {
                        size_t di = (size_t)row * ldd + 8 + col0;
                        if (has1 && ((di & 1) == 0)) store2x2(D0, D1, di, v0, v1);
                        else {
                            store2(D0, D1, di, v0);
                            if (has1) store2(D0, D1, di + 1, v1);
                        }
                    }
                } else if (EPI == 6) {
                    size_t di = (size_t)row * ldd + col0;
                    if (has1 && aligned) {
                        store2x2(C0, C1, ci, v0, v1);
                        store2x2(D0, D1, di, v0 * 0.7071067811865476f, v1 * 0.7071067811865476f);
                    } else {
                        store2(C0, C1, ci, v0);
                        store2(D0, D1, di, v0 * 0.7071067811865476f);
                        if (has1) {
                            store2(C0, C1, ci + 1, v1);
                            store2(D0, D1, di + 1, v1 * 0.7071067811865476f);
                        }
                    }
                } else if (EPI == 7) {
                    size_t di = (size_t)row * ldd + col0;
                    if (has1 && ((di & 1) == 0))
                        store2x2(D0, D1, di, v0 * 0.7071067811865476f, v1 * 0.7071067811865476f);
                    else {
                        store2(D0, D1, di, v0 * 0.7071067811865476f);
                        if (has1) store2(D0, D1, di + 1, v1 * 0.7071067811865476f);
                    }
                } else if (EPI == 8) {
#pragma unroll
                    for (int u = 0; u < 2; u++) {
                        int col = col0 + u;
                        if (col >= N) continue;
                        float vs = (u ? v1 : v0) * 0.7071067811865476f;
                        if (col < 217) {
                            store2(C0, C1, (size_t)row * 224 + col,
                                   vs * (-expm1f(-100.0f * join2(Mhi, Mlo, (size_t)row * ldh + col))));
                        } else {
                            if (col < 224) store2(C0, C1, (size_t)row * 224 + col, 0.0f);
                            GE[(size_t)row * 39 + col - 217] = vs;
                        }
                    }
                }
            }
        }
    }
}

// ===================== small kernels =====================

__global__ void k_ray_init(const float* __restrict__ ro, const float* __restrict__ rd,
                           float* __restrict__ Z)
{
    int r = blockIdx.x * blockDim.x + threadIdx.x;
    if (r >= R_RAYS) return;
    float ox = ro[r*3], oy = ro[r*3+1], oz = ro[r*3+2];
    float dx = rd[r*3], dy = rd[r*3+1], dz = rd[r*3+2];
    float a = dx*dx + dy*dy + dz*dz;
    float b = 2.0f * (ox*dx + oy*dy + oz*dz);
    float mid = -b / (2.0f * a);
    float nv = fmaxf(mid - 1.0f, 0.05f);
    float fv = mid + 1.0f;
    for (int s = 0; s < 64; s++)
        Z[r*64 + s] = nv + (fv - nv) * ((float)s * (1.0f/63.0f));
}

__global__ void k_dist_mid_pts(const float* __restrict__ Z, const float* __restrict__ ro,
                               const float* __restrict__ rd, float* __restrict__ P,
                               float* __restrict__ D)
{
    int m = blockIdx.x * blockDim.x + threadIdx.x;
    if (m >= (int)NPTS) return;
    int s = m & 127, r = m >> 7;
    float z = Z[m];
    float d = (s < 127) ? (Z[m+1] - z) : 0.03125f;
    D[m] = d;
    float mz = fmaf(0.5f, d, z);
#pragma unroll
    for (int j = 0; j < 3; j++)
        P[(size_t)m*3 + j] = fmaf(rd[r*3+j], mz, ro[r*3+j]);
}

// coalesced embed: idx -> (m, c); PSRC=0: p from Z/ro/rd; PSRC=1: p from P
template <int PSRC>
__global__ void k_embed_c(const float* __restrict__ ZorP,
                          const float* __restrict__ ro, const float* __restrict__ rd,
                          bf16* __restrict__ Eh, bf16* __restrict__ El,
                          bf16* __restrict__ Th, bf16* __restrict__ Tl,
                          int tp, int S, int M)
{
    int idx = blockIdx.x * blockDim.x + threadIdx.x;
    if (idx >= M * 40) return;
    int m = idx / 40, c = idx - m * 40;
    if (c == 39) { store2(Eh, El, (size_t)m*40 + 39, 0.0f); return; }

    float v;
    if (c < 3) {
        if (PSRC) v = ZorP[(size_t)m*3 + c];
        else { int r = m / S; v = fmaf(rd[r*3+c], ZorP[m], ro[r*3+c]); }
    } else {
        int cc = c - 3;
        int k = cc / 6, rem = cc - k * 6;
        int jdim = rem % 3;
        float p;
        if (PSRC) p = ZorP[(size_t)m*3 + jdim];
        else { int r = m / S; p = fmaf(rd[r*3+jdim], ZorP[m], ro[r*3+jdim]); }
        float f = (float)(1 << k);
        float sv, cv;
        sincosf(f * p, &sv, &cv);
        v = (rem < 3) ? sv : cv;
    }
    store2(Eh, El, (size_t)m*40 + c, v);
    store2(Th, Tl, (size_t)m*tp + 217 + c, v * 0.7071067811865476f);
}

__global__ void k_sdf_head(const bf16* __restrict__ Hh, const bf16* __restrict__ Hl,
                           const float* __restrict__ W8, const float* __restrict__ b8,
                           float* __restrict__ out, int M)
{
    int gw = (blockIdx.x * blockDim.x + threadIdx.x) >> 5;
    int lane = threadIdx.x & 31;
    if (gw >= M) return;
    size_t b = (size_t)gw * 256;
    float s = 0.0f;
#pragma unroll
    for (int k = lane; k < 256; k += 32) s = fmaf(join2(Hh, Hl, b + k), W8[(size_t)k*257], s);
#pragma unroll
    for (int o = 16; o; o >>= 1) s += __shfl_xor_sync(0xffffffffu, s, o);
    if (!lane) out[gw] = s + b8[0];
}

__global__ void k_upsample(const float* __restrict__ ro, const float* __restrict__ rd,
                           const float* __restrict__ Z, const float* __restrict__ SD,
                           float* __restrict__ ZN, int S, float inv_s)
{
    int r = blockIdx.x * blockDim.x + threadIdx.x;
    if (r >= R_RAYS) return;
    float ox = ro[r*3], oy = ro[r*3+1], oz = ro[r*3+2];
    float dx = rd[r*3], dy = rd[r*3+1], dz = rd[r*3+2];
    const float* zr = Z + (size_t)r * S;
    const float* sr = SD + (size_t)r * S;

    float w[128], cdf[129];
    float prev_raw = 0.0f, T = 1.0f, wsum = 0.0f;
    float z_i = zr[0];
    float px = fmaf(dx,z_i,ox), py = fmaf(dy,z_i,oy), pz = fmaf(dz,z_i,oz);
    float rad_i = sqrtf(px*px + py*py + pz*pz);
    float sdf_i = sr[0];

    for (int i = 0; i < S - 1; i++) {
        float z_n = zr[i+1], sdf_n = sr[i+1];
        float qx = fmaf(dx,z_n,ox), qy = fmaf(dy,z_n,oy), qz = fmaf(dz,z_n,oz);
        float rad_n = sqrtf(qx*qx + qy*qy + qz*qz);
        bool inside = (rad_i < 1.0f) || (rad_n < 1.0f);
        float mid_sdf = 0.5f * (sdf_i + sdf_n);
        float raw = (sdf_n - sdf_i) / (z_n - z_i + 1e-5f);
        float cosv = fminf(raw, prev_raw);
        prev_raw = raw;
        cosv = fminf(fmaxf(cosv, -1000.0f), 0.0f);
        if (!inside) cosv = 0.0f;
        float dist = z_n - z_i;
        float pc = sigmoidf_((mid_sdf - cosv*dist*0.5f) * inv_s);
        float nc = sigmoidf_((mid_sdf + cosv*dist*0.5f) * inv_s);
        float alpha = (pc - nc + 1e-5f) / (pc + 1e-5f);
        float wi = alpha * T;
        T *= (1.0f - alpha + 1e-7f);
        wi += 1e-5f;
        w[i] = wi; wsum += wi;
        z_i = z_n; rad_i = rad_n; sdf_i = sdf_n;
    }

    cdf[0] = 0.0f;
    float invsum = 1.0f / wsum;
    for (int i = 0; i < S - 1; i++) cdf[i+1] = cdf[i] + w[i] * invsum;

    for (int j = 0; j < 16; j++) {
        float u = 0.03125f + (float)j * 0.0625f;
        int lo = 0, hi = S;
        while (lo < hi) { int md = (lo + hi) >> 1; if (cdf[md] <= u) lo = md + 1; else hi = md; }
        int below = lo - 1; if (below < 0) below = 0; if (below > S-1) below = S-1;
        int above = lo;     if (above > S-1) above = S-1;
        float c0 = cdf[below], c1 = cdf[above];
        float b0 = zr[below],  b1 = zr[above];
        float den = (c1 - c0) < 1e-5f ? 1.0f : (c1 - c0);
        ZN[r*16 + j] = b0 + (u - c0) / den * (b1 - b0);
    }
}

__global__ void k_merge(const float* __restrict__ Z, const float* __restrict__ SD,
                        const float* __restrict__ ZN, const float* __restrict__ SN,
                        float* __restrict__ ZT, float* __restrict__ ST, int S)
{
    int r = blockIdx.x * blockDim.x + threadIdx.x;
    if (r >= R_RAYS) return;
    const float* zo = Z + (size_t)r*S;  const float* so = SD + (size_t)r*S;
    const float* zn = ZN + r*16;        const float* sn = SN + r*16;
    float* zt = ZT + (size_t)r*(S+16);  float* st = ST + (size_t)r*(S+16);
    int i = 0, j = 0;
    for (int k = 0; k < S + 16; k++) {
        bool useOld = (i < S) && ((j >= 16) || (zo[i] <= zn[j]));
        if (useOld) { zt[k] = zo[i]; st[k] = so[i]; i++; }
        else        { zt[k] = zn[j]; st[k] = sn[j]; j++; }
    }
}

__global__ void k_copy(float* __restrict__ dst, const float* __restrict__ src, int n)
{
    int i = blockIdx.x * blockDim.x + threadIdx.x;
    if (i < n) dst[i] = src[i];
}

__global__ void k_gradpts(const float* __restrict__ GEm, const float* __restrict__ GEs,
                          const float* __restrict__ P, float* __restrict__ GR, int M)
{
    int m = blockIdx.x * blockDim.x + threadIdx.x;
    if (m >= M) return;
    const float* ga = GEm + (size_t)m*39;
    const float* gb = GEs + (size_t)m*39;
    float p[3] = {P[(size_t)m*3], P[(size_t)m*3+1], P[(size_t)m*3+2]};
    float g[3];
#pragma unroll
    for (int j = 0; j < 3; j++) g[j] = ga[j] + gb[j];
    float f = 1.0f;
#pragma unroll
    for (int k = 0; k < 6; k++) {
#pragma unroll
        for (int j = 0; j < 3; j++) {
            float s, c;
            sincosf(f * p[j], &s, &c);
            float gs = ga[3+6*k+j]   + gb[3+6*k+j];
            float gc = ga[3+6*k+3+j] + gb[3+6*k+3+j];
            g[j] = fmaf( f * c, gs, g[j]);
            g[j] = fmaf(-f * s, gc, g[j]);
        }
        f *= 2.0f;
    }
#pragma unroll
    for (int j = 0; j < 3; j++) GR[(size_t)m*3 + j] = g[j];
}

__global__ void k_alpha(const float* __restrict__ SDFO, const float* __restrict__ GR,
                        const float* __restrict__ D, const float* __restrict__ rd,
                        const float* __restrict__ var, float* __restrict__ A, int M)
{
    int m = blockIdx.x * blockDim.x + threadIdx.x;
    if (m >= M) return;
    int r = m >> 7;
    float tc = rd[r*3]*GR[(size_t)m*3] + rd[r*3+1]*GR[(size_t)m*3+1] + rd[r*3+2]*GR[(size_t)m*3+2];
    float ic = fminf(tc, 0.0f);
    float sdf = SDFO[m];
    float dist = D[m];
    float inv_s = fminf(fmaxf(expf(10.0f * var[0]), 1e-6f), 1e6f);
    float pc = sigmoidf_((sdf - ic*dist*0.5f) * inv_s);
    float nc = sigmoidf_((sdf + ic*dist*0.5f) * inv_s);
    float a = (pc - nc + 1e-5f) / (pc + 1e-5f);
    A[m] = fminf(fmaxf(a, 0.0f), 1.0f);
}

__global__ void k_ray_weights(const float* __restrict__ A, float* __restrict__ W)
{
    int r = blockIdx.x * blockDim.x + threadIdx.x;
    if (r >= R_RAYS) return;
    float T = 1.0f;
    for (int s = 0; s < 128; s++) {
        int m = r*128 + s;
        float a = A[m];
        W[m] = a * T;
        T *= (1.0f - a + 1e-7f);
    }
}

__global__ void k_cin9(const float* __restrict__ P, const float* __restrict__ rd,
                       const float* __restrict__ GR, bf16* __restrict__ Ch,
                       bf16* __restrict__ Cl, int M)
{
    int idx = blockIdx.x * blockDim.x + threadIdx.x;
    if (idx >= M * 16) return;
    int m = idx >> 4, c = idx & 15;
    if (c < 9) {
        float v;
        if (c < 3) v = P[(size_t)m*3 + c];
        else if (c < 6) { int r = m >> 7; v = rd[r*3 + (c-3)]; }
        else {
            float g0 = GR[(size_t)m*3], g1 = GR[(size_t)m*3+1], g2 = GR[(size_t)m*3+2];
            float n = fmaxf(sqrtf(g0*g0 + g1*g1 + g2*g2), 1e-6f);
            v = GR[(size_t)m*3 + (c-6)] / n;
        }
        store2(Ch, Cl, (size_t)m*272 + c, v);
    } else {
        store2(Ch, Cl, (size_t)m*272 + 265 + (c - 9), 0.0f);
    }
}

__global__ void k_color_head(const bf16* __restrict__ Hh, const bf16* __restrict__ Hl,
                             const float* __restrict__ W, const float* __restrict__ b,
                             float* __restrict__ rgbs, int M)
{
    int gw = (blockIdx.x * blockDim.x + threadIdx.x) >> 5;
    int lane = threadIdx.x & 31;
    if (gw >= M) return;
    size_t hb = (size_t)gw * 256;
    float a0 = 0.f, a1 = 0.f, a2 = 0.f;
#pragma unroll
    for (int k = lane; k < 256; k += 32) {
        float hv = join2(Hh, Hl, hb + k);
        a0 = fmaf(hv, W[k*3+0], a0);
        a1 = fmaf(hv, W[k*3+1], a1);
        a2 = fmaf(hv, W[k*3+2], a2);
    }
#pragma unroll
    for (int o = 16; o; o >>= 1) {
        a0 += __shfl_xor_sync(0xffffffffu, a0, o);
        a1 += __shfl_xor_sync(0xffffffffu, a1, o);
        a2 += __shfl_xor_sync(0xffffffffu, a2, o);
    }
    if (!lane) {
        rgbs[(size_t)gw*3+0] = sigmoidf_(a0 + b[0]);
        rgbs[(size_t)gw*3+1] = sigmoidf_(a1 + b[1]);
        rgbs[(size_t)gw*3+2] = sigmoidf_(a2 + b[2]);
    }
}

__global__ void k_reduce(const float* __restrict__ W, const float* __restrict__ rgbs,
                         float* __restrict__ out)
{
    int r = blockIdx.x * blockDim.x + threadIdx.x;
    if (r >= R_RAYS) return;
    float s0 = 0.f, s1 = 0.f, s2 = 0.f;
    for (int s = 0; s < 128; s++) {
        int m = r*128 + s;
        float w = W[m];
        s0 = fmaf(w, rgbs[(size_t)m*3+0], s0);
        s1 = fmaf(w, rgbs[(size_t)m*3+1], s1);
        s2 = fmaf(w, rgbs[(size_t)m*3+2], s2);
    }
    out[r*3+0] = s0; out[r*3+1] = s1; out[r*3+2] = s2;
}

// ===================== host orchestration =====================

static const int GEMM_SHM = 81920;

struct Plane { bf16* hi; bf16* lo; };
static Plane PNONE = {nullptr, nullptr};

template <int EPI>
static void launch_bf3(Plane A, int lda, Plane B, int ldb, const float* bias,
                       Plane Hm, int ldh, void* C0, void* C1, int ldc,
                       Plane D, int ldd, const float* W8, float* GE,
                       int M, int N, int K)
{
    dim3 g((N + 127) / 128, (M + 127) / 128);
    cudaFuncSetAttribute(gemm_bf3<EPI>, cudaFuncAttributeMaxDynamicSharedMemorySize, GEMM_SHM);
    gemm_bf3<EPI><<<g, 256, GEMM_SHM>>>(A.hi, A.lo, lda, B.hi, B.lo, ldb, bias,
                                        Hm.hi, Hm.lo, ldh, C0, C1, ldc,
                                        D.hi, D.lo, ldd, W8, GE, M, N, K);
}

struct Ctx {
    Plane act[13];
    Plane wb[19];
    const float* sb[9]; const float* cb[3];
    const float* sw8raw; const float* cw2raw;
};
enum { E_=0, H0_, H1_, H2_, H3_, I4_, A4_, A5_, A6_, A7_, GP_, GQ_, CIN_ };

static void sdf_forward_nostore(int M, int S, const float* Z,
                                const float* ro, const float* rd,
                                const Ctx& X, float* sdf_dest)
{
    Plane E = X.act[E_], GP = X.act[GP_], GQ = X.act[GQ_], CIN = X.act[CIN_];
    k_embed_c<0><<<(M*40+255)/256, 256>>>(Z, ro, rd, E.hi, E.lo, CIN.hi, CIN.lo, 272, S, M);
    launch_bf3<1>(E, 40,   X.wb[0], 40,  X.sb[0], PNONE,0, GP.hi,GP.lo,256, PNONE,0,nullptr,nullptr, M,256,40);
    launch_bf3<1>(GP, 256, X.wb[1], 256, X.sb[1], PNONE,0, GQ.hi,GQ.lo,256, PNONE,0,nullptr,nullptr, M,256,256);
    launch_bf3<1>(GQ, 256, X.wb[2], 256, X.sb[2], PNONE,0, GP.hi,GP.lo,256, PNONE,0,nullptr,nullptr, M,256,256);
    launch_bf3<7>(GP, 256, X.wb[3], 256, X.sb[3], PNONE,0, nullptr,nullptr,0, CIN,272,nullptr,nullptr, M,217,256);
    launch_bf3<1>(CIN, 272, X.wb[4], 256, X.sb[4], PNONE,0, GQ.hi,GQ.lo,256, PNONE,0,nullptr,nullptr, M,256,256);
    launch_bf3<1>(GQ, 256, X.wb[5], 256, X.sb[5], PNONE,0, GP.hi,GP.lo,256, PNONE,0,nullptr,nullptr, M,256,256);
    launch_bf3<1>(GP, 256, X.wb[6], 256, X.sb[6], PNONE,0, GQ.hi,GQ.lo,256, PNONE,0,nullptr,nullptr, M,256,256);
    launch_bf3<1>(GQ, 256, X.wb[7], 256, X.sb[7], PNONE,0, GP.hi,GP.lo,256, PNONE,0,nullptr,nullptr, M,256,256);
    k_sdf_head<<<(M*32+255)/256, 256>>>(GP.hi, GP.lo, X.sw8raw, X.sb[8], sdf_dest, M);
}

extern "C" void kernel_launch(void* const* d_in, const int* in_sizes, int n_in,
                              void* d_out, int out_size)
{
    const float* ro = (const float*)d_in[0];
    const float* rd = (const float*)d_in[1];
    const float* sw[9]; const float* sb[9];
    const float* cw[3]; const float* cb[3];
    const float* var;

    bool interleaved = (in_sizes[3] < 1024);
    if (interleaved) {
        for (int l = 0; l < 9; l++) { sw[l] = (const float*)d_in[2 + 2*l]; sb[l] = (const float*)d_in[3 + 2*l]; }
        for (int l = 0; l < 3; l++) { cw[l] = (const float*)d_in[20 + 2*l]; cb[l] = (const float*)d_in[21 + 2*l]; }
        var = (const float*)d_in[26];
    } else {
        for (int l = 0; l < 9; l++) { sw[l] = (const float*)d_in[2 + l]; sb[l] = (const float*)d_in[11 + l]; }
        for (int l = 0; l < 3; l++) { cw[l] = (const float*)d_in[20 + l]; cb[l] = (const float*)d_in[23 + l]; }
        var = (const float*)d_in[26];
    }
    float* out = (float*)d_out;

    float* fbase = nullptr;
    bf16* bbase = nullptr;
    cudaGetSymbolAddress((void**)&fbase, d_F32);
    cudaGetSymbolAddress((void**)&bbase, d_BF);

    float* PZ = fbase+O_Z;     float* PSDF = fbase+O_SDF;
    float* PZT = fbase+O_ZT;   float* PSDFT = fbase+O_SDFT;
    float* PZN = fbase+O_ZNEW; float* PSDFN = fbase+O_SDFNEW;
    float* PP = fbase+O_PTS;   float* PD = fbase+O_DIST;
    float* PSDFO = fbase+O_SDFO; float* PGE = fbase+O_GE; float* PGEM = fbase+O_GEM;
    float* PGR = fbase+O_GRAD; float* PA = fbase+O_ALPHA;
    float* PW = fbase+O_WT;    float* PRGB = fbase+O_RGBS;

    Ctx X;
    for (int i = 0; i < 13; i++) {
        X.act[i].hi = bbase + aoff(i);
        X.act[i].lo = bbase + aoff(i) + NPTS * AW[i];
    }
    bf16* wb0 = bbase + BF_ACT_TOTAL;
    for (int i = 0; i < 19; i++) {
        X.wb[i].hi = wb0 + woff(i);
        X.wb[i].lo = wb0 + woff(i) + WN[i] * WK[i];
    }
    for (int l = 0; l < 9; l++) X.sb[l] = sb[l];
    for (int l = 0; l < 3; l++) X.cb[l] = cb[l];
    X.sw8raw = sw[8]; X.cw2raw = cw[2];

    // ---- fused weight plane prep ----
    {
        WSrc ws;
        const float* wsrc[19] = { sw[0],sw[1],sw[2],sw[3],sw[4],sw[5],sw[6],sw[7],sw[8],
                                  cw[0],cw[1],
                                  sw[7],sw[6],sw[5],sw[4],sw[3],sw[2],sw[1],sw[0] };
        for (int i = 0; i < 19; i++) ws.p[i] = wsrc[i];
        int total = (int)(BF_W_TOTAL / 2);
        k_wprep_all<<<(total+255)/256, 256>>>(ws, wb0, total);
    }

    Plane E = X.act[E_], H0 = X.act[H0_], H1 = X.act[H1_], H2 = X.act[H2_];
    Plane H3 = X.act[H3_], I4 = X.act[I4_], A4 = X.act[A4_], A5 = X.act[A5_];
    Plane A6 = X.act[A6_], A7 = X.act[A7_], GP = X.act[GP_], GQ = X.act[GQ_];
    Plane CIN = X.act[CIN_];

    // ---- initial 64 samples + sdf ----
    k_ray_init<<<4, 256>>>(ro, rd, PZ);
    int S = 64;
    int M = R_RAYS * S;
    sdf_forward_nostore(M, S, PZ, ro, rd, X, PSDF);

    // ---- 4 importance-sampling rounds ----
    for (int i = 0; i < 4; i++) {
        float inv_s = 64.0f * (float)(1 << i);
        k_upsample<<<4, 256>>>(ro, rd, PZ, PSDF, PZN, S, inv_s);
        int Mn = R_RAYS * 16;
        sdf_forward_nostore(Mn, 16, PZN, ro, rd, X, PSDFN);
        k_merge<<<4, 256>>>(PZ, PSDF, PZN, PSDFN, PZT, PSDFT, S);
        S += 16;
        int n = R_RAYS * S;
        k_copy<<<(n+255)/256, 256>>>(PZ, PZT, n);
        k_copy<<<(n+255)/256, 256>>>(PSDF, PSDFT, n);
    }

    // ---- final forward ----
    M = (int)NPTS;
    k_dist_mid_pts<<<(M+255)/256, 256>>>(PZ, ro, rd, PP, PD);
    k_embed_c<1><<<(M*40+255)/256, 256>>>(PP, ro, rd, E.hi, E.lo, I4.hi, I4.lo, 256, 0, M);
    launch_bf3<1>(E, 40,   X.wb[0], 40,  sb[0], PNONE,0, H0.hi,H0.lo,256, PNONE,0,nullptr,nullptr, M,256,40);
    launch_bf3<1>(H0, 256, X.wb[1], 256, sb[1], PNONE,0, H1.hi,H1.lo,256, PNONE,0,nullptr,nullptr, M,256,256);
    launch_bf3<1>(H1, 256, X.wb[2], 256, sb[2], PNONE,0, H2.hi,H2.lo,256, PNONE,0,nullptr,nullptr, M,256,256);
    launch_bf3<6>(H2, 256, X.wb[3], 256, sb[3], PNONE,0, H3.hi,H3.lo,224, I4,256,nullptr,nullptr, M,217,256);
    launch_bf3<1>(I4, 256, X.wb[4], 256, sb[4], PNONE,0, A4.hi,A4.lo,256, PNONE,0,nullptr,nullptr, M,256,256);
    launch_bf3<1>(A4, 256, X.wb[5], 256, sb[5], PNONE,0, A5.hi,A5.lo,256, PNONE,0,nullptr,nullptr, M,256,256);
    launch_bf3<1>(A5, 256, X.wb[6], 256, sb[6], PNONE,0, A6.hi,A6.lo,256, PNONE,0,nullptr,nullptr, M,256,256);
    launch_bf3<4>(A6, 256, X.wb[7], 256, sb[7], PNONE,0, A7.hi,A7.lo,256, GP,256, sw[8],nullptr, M,256,256);
    launch_bf3<5>(A7, 256, X.wb[8], 256, sb[8], PNONE,0, PSDFO,nullptr,0, CIN,272,nullptr,nullptr, M,257,256);

    // ---- backward VJP ----
    launch_bf3<3>(GP, 256, X.wb[11], 256, nullptr, A6,256, GQ.hi,GQ.lo,256, PNONE,0,nullptr,nullptr, M,256,256);
    launch_bf3<3>(GQ, 256, X.wb[12], 256, nullptr, A5,256, GP.hi,GP.lo,256, PNONE,0,nullptr,nullptr, M,256,256);
    launch_bf3<3>(GP, 256, X.wb[13], 256, nullptr, A4,256, GQ.hi,GQ.lo,256, PNONE,0,nullptr,nullptr, M,256,256);
    launch_bf3<8>(GQ, 256, X.wb[14], 256, nullptr, H3,224, GP.hi,GP.lo,224, PNONE,0,nullptr,PGE, M,256,256);
    launch_bf3<3>(GP, 224, X.wb[15], 224, nullptr, H2,256, GQ.hi,GQ.lo,256, PNONE,0,nullptr,nullptr, M,256,224);
    launch_bf3<3>(GQ, 256, X.wb[16], 256, nullptr, H1,256, GP.hi,GP.lo,256, PNONE,0,nullptr,nullptr, M,256,256);
    launch_bf3<3>(GP, 256, X.wb[17], 256, nullptr, H0,256, GQ.hi,GQ.lo,256, PNONE,0,nullptr,nullptr, M,256,256);
    launch_bf3<0>(GQ, 256, X.wb[18], 256, nullptr, PNONE,0, PGEM,nullptr,39, PNONE,0,nullptr,nullptr, M,39,256);
    k_gradpts<<<(M+255)/256, 256>>>(PGEM, PGE, PP, PGR, M);

    // ---- color net + compositing ----
    k_alpha<<<(M+255)/256, 256>>>(PSDFO, PGR, PD, rd, var, PA, M);
    k_ray_weights<<<4, 256>>>(PA, PW);
    k_cin9<<<(M*16+255)/256, 256>>>(PP, rd, PGR, CIN.hi, CIN.lo, M);
    launch_bf3<2>(CIN, 272, X.wb[9], 272, cb[0], PNONE,0, GP.hi,GP.lo,256, PNONE,0,nullptr,nullptr, M,256,272);
    launch_bf3<2>(GP, 256, X.wb[10], 256, cb[1], PNONE,0, GQ.hi,GQ.lo,256, PNONE,0,nullptr,nullptr, M,256,256);
    k_color_head<<<(M*32+255)/256, 256>>>(GQ.hi, GQ.lo, cw[2], cb[2], PRGB, M);
    k_reduce<<<4, 256>>>(PW, PRGB, out);
}

// round 16
// speedup vs baseline: 2.1647x; 1.0216x over previous
#include <cuda_runtime.h>
#include <cuda_bf16.h>
#include <math.h>
#include <stdint.h>
#include <stddef.h>

typedef __nv_bfloat16 bf16;

#define R_RAYS 1024
static constexpr size_t NPTS = 131072;

// ================= f32 scratch =================
constexpr size_t O_Z      = 0;
constexpr size_t O_SDF    = O_Z + NPTS;
constexpr size_t O_ZT     = O_SDF + NPTS;
constexpr size_t O_SDFT   = O_ZT + NPTS;
constexpr size_t O_ZNEW   = O_SDFT + NPTS;
constexpr size_t O_SDFNEW = O_ZNEW + 16384;
constexpr size_t O_PTS    = O_SDFNEW + 16384;
constexpr size_t O_DIST   = O_PTS + NPTS * 3;
constexpr size_t O_SDFO   = O_DIST + NPTS;
constexpr size_t O_GE     = O_SDFO + NPTS;
constexpr size_t O_GEM    = O_GE + NPTS * 39;
constexpr size_t O_GRAD   = O_GEM + NPTS * 39;
constexpr size_t O_WT     = O_GRAD + NPTS * 3;
constexpr size_t O_RGBS   = O_WT + NPTS;
constexpr size_t F32_TOTAL = O_RGBS + NPTS * 3;
__device__ __align__(256) float d_F32[F32_TOTAL];

// ================= bf16 plane scratch =================
constexpr size_t AW[13] = {40,256,256,256,224,256,256,256,256,256,256,256,272};
constexpr size_t aoff(int i) { size_t o = 0; for (int j = 0; j < i; j++) o += AW[j] * 2; return o * NPTS; }
constexpr size_t BF_ACT_TOTAL = aoff(13);
constexpr size_t WN[19] = {256,256,256,217,256,256,256,256,257, 256,256, 256,256,256,256,256,256,256, 39};
constexpr size_t WK[19] = {40, 256,256,256,256,256,256,256,256, 272,256, 256,256,256,256,224,256,256, 256};
constexpr size_t woff(int i) { size_t o = 0; for (int j = 0; j < i; j++) o += WN[j] * WK[j] * 2; return o; }
constexpr size_t BF_W_TOTAL = woff(19);
__device__ __align__(256) bf16 d_BF[BF_ACT_TOTAL + BF_W_TOTAL];

__device__ __forceinline__ float sigmoidf_(float x) { return 1.0f / (1.0f + expf(-x)); }
__device__ __forceinline__ void store2(void* hi, void* lo, size_t i, float v) {
    bf16 h = __float2bfloat16(v);
    ((bf16*)hi)[i] = h;
    ((bf16*)lo)[i] = __float2bfloat16(v - __bfloat162float(h));
}
__device__ __forceinline__ void store2x2(void* hi, void* lo, size_t i, float v0, float v1) {
    bf16 h0 = __float2bfloat16(v0), h1 = __float2bfloat16(v1);
    __nv_bfloat162 hh; hh.x = h0; hh.y = h1;
    *(__nv_bfloat162*)((bf16*)hi + i) = hh;
    __nv_bfloat162 ll;
    ll.x = __float2bfloat16(v0 - __bfloat162float(h0));
    ll.y = __float2bfloat16(v1 - __bfloat162float(h1));
    *(__nv_bfloat162*)((bf16*)lo + i) = ll;
}
__device__ __forceinline__ float join2(const bf16* hi, const bf16* lo, size_t i) {
    return __bfloat162float(hi[i]) + __bfloat162float(lo[i]);
}
__device__ __forceinline__ float softp_(float v) {
    float s = 100.0f * v;
    return (fmaxf(s, 0.0f) + log1pf(expf(-fabsf(s)))) * 0.01f;
}

__device__ __forceinline__ uint32_t s2u(const void* p) {
    return (uint32_t)__cvta_generic_to_shared(p);
}
__device__ __forceinline__ void cpa16(uint32_t d, const void* s, int sz) {
    asm volatile("cp.async.ca.shared.global [%0], [%1], 16, %2;" :: "r"(d), "l"(s), "r"(sz));
}
#define CP_COMMIT() asm volatile("cp.async.commit_group;")
#define CP_WAIT1()  asm volatile("cp.async.wait_group 1;")

__device__ __forceinline__ void ldsm4(uint32_t& r0, uint32_t& r1, uint32_t& r2, uint32_t& r3,
                                      uint32_t addr) {
    asm volatile("ldmatrix.sync.aligned.m8n8.x4.shared.b16 {%0,%1,%2,%3}, [%4];"
                 : "=r"(r0), "=r"(r1), "=r"(r2), "=r"(r3) : "r"(addr));
}

// ---- fused weight prep ----
struct WSrc { const float* p[19]; };
__global__ void k_wprep_all(WSrc ws, bf16* __restrict__ wb, int total)
{
    const int wn[19] = {256,256,256,217,256,256,256,256,257, 256,256, 256,256,256,256,256,256,256, 39};
    const int wk[19] = {40, 256,256,256,256,256,256,256,256, 272,256, 256,256,256,256,224,256,256, 256};
    const int wr[19] = {39,256,256,256,256,256,256,256,256, 265,256, 256,256,256,256,256,256,256, 39};
    const int wc[19] = {256,256,256,217,256,256,256,256,257, 256,256, 256,256,256,256,217,256,256, 256};

    int idx = blockIdx.x * blockDim.x + threadIdx.x;
    if (idx >= total) return;
    size_t off = (size_t)idx;
    int bi = 0;
    size_t base = 0;
#pragma unroll
    for (int i = 0; i < 19; i++) {
        size_t sz = (size_t)wn[i] * wk[i];
        if (off < sz) { bi = i; break; }
        off -= sz;
        base += 2 * sz;
    }
    int Kp = wk[bi];
    int n = (int)(off / Kp), k = (int)(off % Kp);
    const float* W = ws.p[bi];
    float v = 0.0f;
    if (bi <= 10) { if (k < wr[bi] && n < wc[bi]) v = W[(size_t)k * wc[bi] + n]; }
    else          { if (n < wr[bi] && k < wc[bi]) v = W[(size_t)n * wc[bi] + k]; }
    bf16 h = __float2bfloat16(v);
    wb[base + off] = h;
    wb[base + (size_t)wn[bi] * wk[bi] + off] = __float2bfloat16(v - __bfloat162float(h));
}

// ============================================================================
// bf16x3 GEMM, ldmatrix loads, packed epilogue stores.
// EPI: 0 f32 lin | 1 sp->planes | 2 relu->planes | 3 mask-mul->planes
//      4 sp->planes + bwinit->D | 5 out8: col0->f32 sdf, col>=1 ->CIN planes
//      6 sp->planes + concat->D | 7 sp->concat->D only | 8 split: Gz+GE
//      9 sp + dot(W8 col0) -> atomicAdd GE[row]   (sampling sdf head)
//     10 relu + dot(W8[.][0..2]) -> atomicAdd GE[row*3+c] (color head, pre-sigmoid)
// ============================================================================
template <int EPI>
__global__ void __launch_bounds__(256, 2) gemm_bf3(
    const bf16* __restrict__ Ahi, const bf16* __restrict__ Alo, int lda,
    const bf16* __restrict__ Bhi, const bf16* __restrict__ Blo, int ldb,
    const float* __restrict__ bias,
    const bf16* __restrict__ Mhi, const bf16* __restrict__ Mlo, int ldh,
    void* __restrict__ C0, void* __restrict__ C1, int ldc,
    bf16* __restrict__ D0, bf16* __restrict__ D1, int ldd,
    const float* __restrict__ W8, float* __restrict__ GE,
    int M, int N, int K)
{
    extern __shared__ bf16 smb[];
    constexpr int P = 40;
    constexpr int TILE = 128 * P;

    const int tid  = threadIdx.x;
    const int wid  = tid >> 5;
    const int lane = tid & 31;
    const int wm = wid & 3;
    const int wn = wid >> 2;
    const int m0 = blockIdx.y * 128;
    const int n0 = blockIdx.x * 128;
    const int r  = lane >> 2;
    const int cq = lane & 3;

    const int aOff = (wm * 32 + (lane & 15)) * P + ((lane >> 4) << 3);
    const int bOff = (wn * 64 + (lane & 7) + ((lane & 16) >> 1)) * P + (((lane >> 3) & 1) << 3);

    float acc[2][8][4] = {};
    const int nsteps = (K + 31) >> 5;

    auto load_stage = [&](int stage, int k0) {
        bf16* base = smb + stage * 4 * TILE;
        int row  = tid >> 1;
        int half = (tid & 1) * 16;
        {
            int gm = m0 + row;
            size_t so = (size_t)(gm < M ? gm : 0) * lda + k0 + half;
            bf16* dH = base + 0 * TILE + row * P + half;
            bf16* dL = base + 1 * TILE + row * P + half;
#pragma unroll
            for (int c = 0; c < 16; c += 8) {
                int sz = (gm < M && (k0 + half + c) < K) ? 16 : 0;
                cpa16(s2u(dH + c), Ahi + so + c, sz);
                cpa16(s2u(dL + c), Alo + so + c, sz);
            }
        }
        {
            int gn = n0 + row;
            size_t so = (size_t)(gn < N ? gn : 0) * ldb + k0 + half;
            bf16* dH = base + 2 * TILE + row * P + half;
            bf16* dL = base + 3 * TILE + row * P + half;
#pragma unroll
            for (int c = 0; c < 16; c += 8) {
                int sz = (gn < N && (k0 + half + c) < K) ? 16 : 0;
                cpa16(s2u(dH + c), Bhi + so + c, sz);
                cpa16(s2u(dL + c), Blo + so + c, sz);
            }
        }
    };

    load_stage(0, 0);
    CP_COMMIT();

    for (int s = 0; s < nsteps; s++) {
        if (s + 1 < nsteps) load_stage((s + 1) & 1, (s + 1) * 32);
        CP_COMMIT();
        CP_WAIT1();
        __syncthreads();

        const bf16* base = smb + (s & 1) * 4 * TILE;
        uint32_t aAH = s2u(base + 0 * TILE + aOff);
        uint32_t aAL = s2u(base + 1 * TILE + aOff);
        uint32_t aBH = s2u(base + 2 * TILE + bOff);
        uint32_t aBL = s2u(base + 3 * TILE + bOff);

#pragma unroll
        for (int ks = 0; ks < 32; ks += 16) {
            uint32_t aH[2][4], aL[2][4];
#pragma unroll
            for (int i = 0; i < 2; i++) {
                uint32_t ao = (uint32_t)((i * 16 * P + ks) * 2);
                ldsm4(aH[i][0], aH[i][1], aH[i][2], aH[i][3], aAH + ao);
                ldsm4(aL[i][0], aL[i][1], aL[i][2], aL[i][3], aAL + ao);
            }
#pragma unroll
            for (int j2 = 0; j2 < 4; j2++) {
                uint32_t bo = (uint32_t)((j2 * 16 * P + ks) * 2);
                uint32_t bh[4], bl[4];
                ldsm4(bh[0], bh[1], bh[2], bh[3], aBH + bo);
                ldsm4(bl[0], bl[1], bl[2], bl[3], aBL + bo);
#pragma unroll
                for (int jj = 0; jj < 2; jj++) {
                    int j = j2 * 2 + jj;
                    uint32_t bH0 = bh[jj*2], bH1 = bh[jj*2+1];
                    uint32_t bL0 = bl[jj*2], bL1 = bl[jj*2+1];
#pragma unroll
                    for (int i = 0; i < 2; i++) {
                        asm volatile(
                            "mma.sync.aligned.m16n8k16.row.col.f32.bf16.bf16.f32 "
                            "{%0,%1,%2,%3}, {%4,%5,%6,%7}, {%8,%9}, {%0,%1,%2,%3};"
                            : "+f"(acc[i][j][0]), "+f"(acc[i][j][1]),
                              "+f"(acc[i][j][2]), "+f"(acc[i][j][3])
                            : "r"(aH[i][0]), "r"(aH[i][1]), "r"(aH[i][2]), "r"(aH[i][3]),
                              "r"(bL0), "r"(bL1));
                        asm volatile(
                            "mma.sync.aligned.m16n8k16.row.col.f32.bf16.bf16.f32 "
                            "{%0,%1,%2,%3}, {%4,%5,%6,%7}, {%8,%9}, {%0,%1,%2,%3};"
                            : "+f"(acc[i][j][0]), "+f"(acc[i][j][1]),
                              "+f"(acc[i][j][2]), "+f"(acc[i][j][3])
                            : "r"(aL[i][0]), "r"(aL[i][1]), "r"(aL[i][2]), "r"(aL[i][3]),
                              "r"(bH0), "r"(bH1));
                        asm volatile(
                            "mma.sync.aligned.m16n8k16.row.col.f32.bf16.bf16.f32 "
                            "{%0,%1,%2,%3}, {%4,%5,%6,%7}, {%8,%9}, {%0,%1,%2,%3};"
                            : "+f"(acc[i][j][0]), "+f"(acc[i][j][1]),
                              "+f"(acc[i][j][2]), "+f"(acc[i][j][3])
                            : "r"(aH[i][0]), "r"(aH[i][1]), "r"(aH[i][2]), "r"(aH[i][3]),
                              "r"(bH0), "r"(bH1));
                    }
                }
            }
        }
        __syncthreads();
    }

    // ---- EPI 9/10: fused head reductions (N must be 256) ----
    if (EPI == 9 || EPI == 10) {
#pragma unroll
        for (int i = 0; i < 2; i++) {
#pragma unroll
            for (int tr = 0; tr < 2; tr++) {
                int row = m0 + wm * 32 + i * 16 + r + tr * 8;
                float p0 = 0.f, p1 = 0.f, p2 = 0.f;
#pragma unroll
                for (int j = 0; j < 8; j++) {
                    int col0 = n0 + wn * 64 + j * 8 + cq * 2;
                    float v0 = acc[i][j][tr*2+0] + bias[col0];
                    float v1 = acc[i][j][tr*2+1] + bias[col0+1];
                    if (EPI == 9) {
                        v0 = softp_(v0); v1 = softp_(v1);
                        p0 = fmaf(v0, W8[(size_t)col0 * 257],
                             fmaf(v1, W8[(size_t)(col0+1) * 257], p0));
                    } else {
                        v0 = fmaxf(v0, 0.f); v1 = fmaxf(v1, 0.f);
                        p0 = fmaf(v0, W8[col0*3+0], fmaf(v1, W8[(col0+1)*3+0], p0));
                        p1 = fmaf(v0, W8[col0*3+1], fmaf(v1, W8[(col0+1)*3+1], p1));
                        p2 = fmaf(v0, W8[col0*3+2], fmaf(v1, W8[(col0+1)*3+2], p2));
                    }
                }
                p0 += __shfl_xor_sync(0xffffffffu, p0, 1);
                p0 += __shfl_xor_sync(0xffffffffu, p0, 2);
                if (EPI == 10) {
                    p1 += __shfl_xor_sync(0xffffffffu, p1, 1);
                    p1 += __shfl_xor_sync(0xffffffffu, p1, 2);
                    p2 += __shfl_xor_sync(0xffffffffu, p2, 1);
                    p2 += __shfl_xor_sync(0xffffffffu, p2, 2);
                }
                if (cq == 0 && row < M) {
                    if (EPI == 9) atomicAdd(&GE[row], p0);
                    else {
                        atomicAdd(&GE[(size_t)row*3+0], p0);
                        atomicAdd(&GE[(size_t)row*3+1], p1);
                        atomicAdd(&GE[(size_t)row*3+2], p2);
                    }
                }
            }
        }
        return;
    }

    // ---- generic epilogue (packed column pairs, alignment-guarded) ----
#pragma unroll
    for (int i = 0; i < 2; i++) {
        int row0 = m0 + wm * 32 + i * 16 + r;
#pragma unroll
        for (int j = 0; j < 8; j++) {
            int col0 = n0 + wn * 64 + j * 8 + cq * 2;
#pragma unroll
            for (int tr = 0; tr < 2; tr++) {
                int row = row0 + tr * 8;
                if (row >= M || col0 >= N) continue;
                float v0 = acc[i][j][tr*2+0];
                float v1 = acc[i][j][tr*2+1];
                bool has1 = (col0 + 1) < N;
                if (bias) { v0 += bias[col0]; if (has1) v1 += bias[col0+1]; }
                if (EPI == 1 || EPI == 4 || EPI == 6 || EPI == 7) { v0 = softp_(v0); v1 = softp_(v1); }
                else if (EPI == 2) { v0 = fmaxf(v0, 0.0f); v1 = fmaxf(v1, 0.0f); }
                else if (EPI == 3) {
                    v0 *= (-expm1f(-100.0f * join2(Mhi, Mlo, (size_t)row * ldh + col0)));
                    if (has1) v1 *= (-expm1f(-100.0f * join2(Mhi, Mlo, (size_t)row * ldh + col0 + 1)));
                }

                size_t ci = (size_t)row * ldc + col0;
                bool aligned = ((ci & 1) == 0);
                if (EPI == 0) {
                    if (has1 && aligned) *(float2*)((float*)C0 + ci) = make_float2(v0, v1);
                    else {
                        ((float*)C0)[ci] = v0;
                        if (has1) ((float*)C0)[ci + 1] = v1;
                    }
                } else if (EPI == 1 || EPI == 2 || EPI == 3) {
                    if (has1 && aligned) store2x2(C0, C1, ci, v0, v1);
                    else {
                        store2(C0, C1, ci, v0);
                        if (has1) store2(C0, C1, ci + 1, v1);
                    }
                } else if (EPI == 4) {
                    float d0 = W8[(size_t)col0 * 257] * (-expm1f(-100.0f * v0));
                    size_t di = (size_t)row * ldd + col0;
                    if (has1 && aligned) {
                        float d1 = W8[(size_t)(col0+1) * 257] * (-expm1f(-100.0f * v1));
                        store2x2(C0, C1, ci, v0, v1);
                        store2x2(D0, D1, di, d0, d1);
                    } else {
                        store2(C0, C1, ci, v0); store2(D0, D1, di, d0);
                        if (has1) {
                            float d1 = W8[(size_t)(col0+1) * 257] * (-expm1f(-100.0f * v1));
                            store2(C0, C1, ci + 1, v1); store2(D0, D1, di + 1, d1);
                        }
                    }
                } else if (EPI == 5) {
                    if (col0 == 0) {
                        ((float*)C0)[row] = v0;
                        if (has1) store2(D0, D1, (size_t)row * ldd + 9, v1);
                    } else {
                        size_t di = (size_t)row * ldd + 8 + col0;
                        if (has1 && ((di & 1) == 0)) store2x2(D0, D1, di, v0, v1);
                        else {
                            store2(D0, D1, di, v0);
                            if (has1) store2(D0, D1, di + 1, v1);
                        }
                    }
                } else if (EPI == 6) {
                    size_t di = (size_t)row * ldd + col0;
                    if (has1 && aligned) {
                        store2x2(C0, C1, ci, v0, v1);
                        store2x2(D0, D1, di, v0 * 0.7071067811865476f, v1 * 0.7071067811865476f);
                    } else {
                        store2(C0, C1, ci, v0);
                        store2(D0, D1, di, v0 * 0.7071067811865476f);
                        if (has1) {
                            store2(C0, C1, ci + 1, v1);
                            store2(D0, D1, di + 1, v1 * 0.7071067811865476f);
                        }
                    }
                } else if (EPI == 7) {
                    size_t di = (size_t)row * ldd + col0;
                    if (has1 && ((di & 1) == 0))
                        store2x2(D0, D1, di, v0 * 0.7071067811865476f, v1 * 0.7071067811865476f);
                    else {
                        store2(D0, D1, di, v0 * 0.7071067811865476f);
                        if (has1) store2(D0, D1, di + 1, v1 * 0.7071067811865476f);
                    }
                } else if (EPI == 8) {
#pragma unroll
                    for (int u = 0; u < 2; u++) {
                        int col = col0 + u;
                        if (col >= N) continue;
                        float vs = (u ? v1 : v0) * 0.7071067811865476f;
                        if (col < 217) {
                            store2(C0, C1, (size_t)row * 224 + col,
                                   vs * (-expm1f(-100.0f * join2(Mhi, Mlo, (size_t)row * ldh + col))));
                        } else {
                            if (col < 224) store2(C0, C1, (size_t)row * 224 + col, 0.0f);
                            GE[(size_t)row * 39 + col - 217] = vs;
                        }
                    }
                }
            }
        }
    }
}

// ===================== small kernels =====================

__global__ void k_ray_init(const float* __restrict__ ro, const float* __restrict__ rd,
                           float* __restrict__ Z)
{
    int r = blockIdx.x * blockDim.x + threadIdx.x;
    if (r >= R_RAYS) return;
    float ox = ro[r*3], oy = ro[r*3+1], oz = ro[r*3+2];
    float dx = rd[r*3], dy = rd[r*3+1], dz = rd[r*3+2];
    float a = dx*dx + dy*dy + dz*dz;
    float b = 2.0f * (ox*dx + oy*dy + oz*dz);
    float mid = -b / (2.0f * a);
    float nv = fmaxf(mid - 1.0f, 0.05f);
    float fv = mid + 1.0f;
    for (int s = 0; s < 64; s++)
        Z[r*64 + s] = nv + (fv - nv) * ((float)s * (1.0f/63.0f));
}

__global__ void k_dist_mid_pts(const float* __restrict__ Z, const float* __restrict__ ro,
                               const float* __restrict__ rd, float* __restrict__ P,
                               float* __restrict__ D)
{
    int m = blockIdx.x * blockDim.x + threadIdx.x;
    if (m >= (int)NPTS) return;
    int s = m & 127, r = m >> 7;
    float z = Z[m];
    float d = (s < 127) ? (Z[m+1] - z) : 0.03125f;
    D[m] = d;
    float mz = fmaf(0.5f, d, z);
#pragma unroll
    for (int j = 0; j < 3; j++)
        P[(size_t)m*3 + j] = fmaf(rd[r*3+j], mz, ro[r*3+j]);
}

// coalesced embed; also initializes sdf accumulator with bias when sdfini != 0
template <int PSRC>
__global__ void k_embed_c(const float* __restrict__ ZorP,
                          const float* __restrict__ ro, const float* __restrict__ rd,
                          bf16* __restrict__ Eh, bf16* __restrict__ El,
                          bf16* __restrict__ Th, bf16* __restrict__ Tl,
                          int tp, int S, int M,
                          const float* __restrict__ b8, float* __restrict__ sdfini)
{
    int idx = blockIdx.x * blockDim.x + threadIdx.x;
    if (idx >= M * 40) return;
    int m = idx / 40, c = idx - m * 40;
    if (c == 39) {
        store2(Eh, El, (size_t)m*40 + 39, 0.0f);
        if (sdfini) sdfini[m] = b8[0];
        return;
    }

    float v;
    if (c < 3) {
        if (PSRC) v = ZorP[(size_t)m*3 + c];
        else { int r = m / S; v = fmaf(rd[r*3+c], ZorP[m], ro[r*3+c]); }
    } else {
        int cc = c - 3;
        int k = cc / 6, rem = cc - k * 6;
        int jdim = rem % 3;
        float p;
        if (PSRC) p = ZorP[(size_t)m*3 + jdim];
        else { int r = m / S; p = fmaf(rd[r*3+jdim], ZorP[m], ro[r*3+jdim]); }
        float f = (float)(1 << k);
        float sv, cv;
        sincosf(f * p, &sv, &cv);
        v = (rem < 3) ? sv : cv;
    }
    store2(Eh, El, (size_t)m*40 + c, v);
    store2(Th, Tl, (size_t)m*tp + 217 + c, v * 0.7071067811865476f);
}

__global__ void k_upsample(const float* __restrict__ ro, const float* __restrict__ rd,
                           const float* __restrict__ Z, const float* __restrict__ SD,
                           float* __restrict__ ZN, int S, float inv_s)
{
    int r = blockIdx.x * blockDim.x + threadIdx.x;
    if (r >= R_RAYS) return;
    float ox = ro[r*3], oy = ro[r*3+1], oz = ro[r*3+2];
    float dx = rd[r*3], dy = rd[r*3+1], dz = rd[r*3+2];
    const float* zr = Z + (size_t)r * S;
    const float* sr = SD + (size_t)r * S;

    float w[128], cdf[129];
    float prev_raw = 0.0f, T = 1.0f, wsum = 0.0f;
    float z_i = zr[0];
    float px = fmaf(dx,z_i,ox), py = fmaf(dy,z_i,oy), pz = fmaf(dz,z_i,oz);
    float rad_i = sqrtf(px*px + py*py + pz*pz);
    float sdf_i = sr[0];

    for (int i = 0; i < S - 1; i++) {
        float z_n = zr[i+1], sdf_n = sr[i+1];
        float qx = fmaf(dx,z_n,ox), qy = fmaf(dy,z_n,oy), qz = fmaf(dz,z_n,oz);
        float rad_n = sqrtf(qx*qx + qy*qy + qz*qz);
        bool inside = (rad_i < 1.0f) || (rad_n < 1.0f);
        float mid_sdf = 0.5f * (sdf_i + sdf_n);
        float raw = (sdf_n - sdf_i) / (z_n - z_i + 1e-5f);
        float cosv = fminf(raw, prev_raw);
        prev_raw = raw;
        cosv = fminf(fmaxf(cosv, -1000.0f), 0.0f);
        if (!inside) cosv = 0.0f;
        float dist = z_n - z_i;
        float pc = sigmoidf_((mid_sdf - cosv*dist*0.5f) * inv_s);
        float nc = sigmoidf_((mid_sdf + cosv*dist*0.5f) * inv_s);
        float alpha = (pc - nc + 1e-5f) / (pc + 1e-5f);
        float wi = alpha * T;
        T *= (1.0f - alpha + 1e-7f);
        wi += 1e-5f;
        w[i] = wi; wsum += wi;
        z_i = z_n; rad_i = rad_n; sdf_i = sdf_n;
    }

    cdf[0] = 0.0f;
    float invsum = 1.0f / wsum;
    for (int i = 0; i < S - 1; i++) cdf[i+1] = cdf[i] + w[i] * invsum;

    for (int j = 0; j < 16; j++) {
        float u = 0.03125f + (float)j * 0.0625f;
        int lo = 0, hi = S;
        while (lo < hi) { int md = (lo + hi) >> 1; if (cdf[md] <= u) lo = md + 1; else hi = md; }
        int below = lo - 1; if (below < 0) below = 0; if (below > S-1) below = S-1;
        int above = lo;     if (above > S-1) above = S-1;
        float c0 = cdf[below], c1 = cdf[above];
        float b0 = zr[below],  b1 = zr[above];
        float den = (c1 - c0) < 1e-5f ? 1.0f : (c1 - c0);
        ZN[r*16 + j] = b0 + (u - c0) / den * (b1 - b0);
    }
}

__global__ void k_merge(const float* __restrict__ Z, const float* __restrict__ SD,
                        const float* __restrict__ ZN, const float* __restrict__ SN,
                        float* __restrict__ ZT, float* __restrict__ ST, int S)
{
    int r = blockIdx.x * blockDim.x + threadIdx.x;
    if (r >= R_RAYS) return;
    const float* zo = Z + (size_t)r*S;  const float* so = SD + (size_t)r*S;
    const float* zn = ZN + r*16;        const float* sn = SN + r*16;
    float* zt = ZT + (size_t)r*(S+16);  float* st = ST + (size_t)r*(S+16);
    int i = 0, j = 0;
    for (int k = 0; k < S + 16; k++) {
        bool useOld = (i < S) && ((j >= 16) || (zo[i] <= zn[j]));
        if (useOld) { zt[k] = zo[i]; st[k] = so[i]; i++; }
        else        { zt[k] = zn[j]; st[k] = sn[j]; j++; }
    }
}

__global__ void k_gradpts(const float* __restrict__ GEm, const float* __restrict__ GEs,
                          const float* __restrict__ P, float* __restrict__ GR, int M)
{
    int m = blockIdx.x * blockDim.x + threadIdx.x;
    if (m >= M) return;
    const float* ga = GEm + (size_t)m*39;
    const float* gb = GEs + (size_t)m*39;
    float p[3] = {P[(size_t)m*3], P[(size_t)m*3+1], P[(size_t)m*3+2]};
    float g[3];
#pragma unroll
    for (int j = 0; j < 3; j++) g[j] = ga[j] + gb[j];
    float f = 1.0f;
#pragma unroll
    for (int k = 0; k < 6; k++) {
#pragma unroll
        for (int j = 0; j < 3; j++) {
            float s, c;
            sincosf(f * p[j], &s, &c);
            float gs = ga[3+6*k+j]   + gb[3+6*k+j];
            float gc = ga[3+6*k+3+j] + gb[3+6*k+3+j];
            g[j] = fmaf( f * c, gs, g[j]);
            g[j] = fmaf(-f * s, gc, g[j]);
        }
        f *= 2.0f;
    }
#pragma unroll
    for (int j = 0; j < 3; j++) GR[(size_t)m*3 + j] = g[j];
}

// fused alpha + transmittance scan (per ray)
__global__ void k_ray_weights(const float* __restrict__ SDFO, const float* __restrict__ GR,
                              const float* __restrict__ D, const float* __restrict__ rd,
                              const float* __restrict__ var, float* __restrict__ W)
{
    int rr = blockIdx.x * blockDim.x + threadIdx.x;
    if (rr >= R_RAYS) return;
    float dx = rd[rr*3], dy = rd[rr*3+1], dz = rd[rr*3+2];
    float inv_s = fminf(fmaxf(expf(10.0f * var[0]), 1e-6f), 1e6f);
    float T = 1.0f;
    for (int s = 0; s < 128; s++) {
        int m = rr*128 + s;
        float tc = dx*GR[(size_t)m*3] + dy*GR[(size_t)m*3+1] + dz*GR[(size_t)m*3+2];
        float ic = fminf(tc, 0.0f);
        float sdf = SDFO[m], dist = D[m];
        float pc = sigmoidf_((sdf - ic*dist*0.5f) * inv_s);
        float nc = sigmoidf_((sdf + ic*dist*0.5f) * inv_s);
        float a = fminf(fmaxf((pc - nc + 1e-5f) / (pc + 1e-5f), 0.0f), 1.0f);
        W[m] = a * T;
        T *= (1.0f - a + 1e-7f);
    }
}

// CIN cols 0..8 + pads 265..271 + rgb accumulator init (cb2)
__global__ void k_cin9(const float* __restrict__ P, const float* __restrict__ rd,
                       const float* __restrict__ GR, bf16* __restrict__ Ch,
                       bf16* __restrict__ Cl, const float* __restrict__ cb2,
                       float* __restrict__ RGB, int M)
{
    int idx = blockIdx.x * blockDim.x + threadIdx.x;
    if (idx >= M * 20) return;
    int m = idx / 20, c = idx - m * 20;
    if (c < 9) {
        float v;
        if (c < 3) v = P[(size_t)m*3 + c];
        else if (c < 6) { int r = m >> 7; v = rd[r*3 + (c-3)]; }
        else {
            float g0 = GR[(size_t)m*3], g1 = GR[(size_t)m*3+1], g2 = GR[(size_t)m*3+2];
            float n = fmaxf(sqrtf(g0*g0 + g1*g1 + g2*g2), 1e-6f);
            v = GR[(size_t)m*3 + (c-6)] / n;
        }
        store2(Ch, Cl, (size_t)m*272 + c, v);
    } else if (c < 16) {
        store2(Ch, Cl, (size_t)m*272 + 265 + (c - 9), 0.0f);
    } else if (c < 19) {
        RGB[(size_t)m*3 + (c - 16)] = cb2[c - 16];
    }
}

__global__ void k_reduce(const float* __restrict__ W, const float* __restrict__ rgbs,
                         float* __restrict__ out)
{
    int r = blockIdx.x * blockDim.x + threadIdx.x;
    if (r >= R_RAYS) return;
    float s0 = 0.f, s1 = 0.f, s2 = 0.f;
    for (int s = 0; s < 128; s++) {
        int m = r*128 + s;
        float w = W[m];
        s0 = fmaf(w, sigmoidf_(rgbs[(size_t)m*3+0]), s0);
        s1 = fmaf(w, sigmoidf_(rgbs[(size_t)m*3+1]), s1);
        s2 = fmaf(w, sigmoidf_(rgbs[(size_t)m*3+2]), s2);
    }
    out[r*3+0] = s0; out[r*3+1] = s1; out[r*3+2] = s2;
}

// ===================== host orchestration =====================

static const int GEMM_SHM = 81920;

struct Plane { bf16* hi; bf16* lo; };
static Plane PNONE = {nullptr, nullptr};

template <int EPI>
static void launch_bf3(Plane A, int lda, Plane B, int ldb, const float* bias,
                       Plane Hm, int ldh, void* C0, void* C1, int ldc,
                       Plane D, int ldd, const float* W8, float* GE,
                       int M, int N, int K)
{
    dim3 g((N + 127) / 128, (M + 127) / 128);
    cudaFuncSetAttribute(gemm_bf3<EPI>, cudaFuncAttributeMaxDynamicSharedMemorySize, GEMM_SHM);
    gemm_bf3<EPI><<<g, 256, GEMM_SHM>>>(A.hi, A.lo, lda, B.hi, B.lo, ldb, bias,
                                        Hm.hi, Hm.lo, ldh, C0, C1, ldc,
                                        D.hi, D.lo, ldd, W8, GE, M, N, K);
}

struct Ctx {
    Plane act[13];
    Plane wb[19];
    const float* sb[9]; const float* cb[3];
    const float* sw8raw; const float* cw2raw;
};
enum { E_=0, H0_, H1_, H2_, H3_, I4_, A4_, A5_, A6_, A7_, GP_, GQ_, CIN_ };

static void sdf_forward_nostore(int M, int S, const float* Z,
                                const float* ro, const float* rd,
                                const Ctx& X, float* sdf_dest)
{
    Plane E = X.act[E_], GP = X.act[GP_], GQ = X.act[GQ_], CIN = X.act[CIN_];
    k_embed_c<0><<<(M*40+255)/256, 256>>>(Z, ro, rd, E.hi, E.lo, CIN.hi, CIN.lo, 272, S, M,
                                          X.sb[8], sdf_dest);
    launch_bf3<1>(E, 40,   X.wb[0], 40,  X.sb[0], PNONE,0, GP.hi,GP.lo,256, PNONE,0,nullptr,nullptr, M,256,40);
    launch_bf3<1>(GP, 256, X.wb[1], 256, X.sb[1], PNONE,0, GQ.hi,GQ.lo,256, PNONE,0,nullptr,nullptr, M,256,256);
    launch_bf3<1>(GQ, 256, X.wb[2], 256, X.sb[2], PNONE,0, GP.hi,GP.lo,256, PNONE,0,nullptr,nullptr, M,256,256);
    launch_bf3<7>(GP, 256, X.wb[3], 256, X.sb[3], PNONE,0, nullptr,nullptr,0, CIN,272,nullptr,nullptr, M,217,256);
    launch_bf3<1>(CIN, 272, X.wb[4], 256, X.sb[4], PNONE,0, GQ.hi,GQ.lo,256, PNONE,0,nullptr,nullptr, M,256,256);
    launch_bf3<1>(GQ, 256, X.wb[5], 256, X.sb[5], PNONE,0, GP.hi,GP.lo,256, PNONE,0,nullptr,nullptr, M,256,256);
    launch_bf3<1>(GP, 256, X.wb[6], 256, X.sb[6], PNONE,0, GQ.hi,GQ.lo,256, PNONE,0,nullptr,nullptr, M,256,256);
    // layer 7 + sdf head fused (EPI 9): atomics into sdf_dest
    launch_bf3<9>(GQ, 256, X.wb[7], 256, X.sb[7], PNONE,0, nullptr,nullptr,0, PNONE,0,
                  X.sw8raw, sdf_dest, M,256,256);
}

extern "C" void kernel_launch(void* const* d_in, const int* in_sizes, int n_in,
                              void* d_out, int out_size)
{
    const float* ro = (const float*)d_in[0];
    const float* rd = (const float*)d_in[1];
    const float* sw[9]; const float* sb[9];
    const float* cw[3]; const float* cb[3];
    const float* var;

    bool interleaved = (in_sizes[3] < 1024);
    if (interleaved) {
        for (int l = 0; l < 9; l++) { sw[l] = (const float*)d_in[2 + 2*l]; sb[l] = (const float*)d_in[3 + 2*l]; }
        for (int l = 0; l < 3; l++) { cw[l] = (const float*)d_in[20 + 2*l]; cb[l] = (const float*)d_in[21 + 2*l]; }
        var = (const float*)d_in[26];
    } else {
        for (int l = 0; l < 9; l++) { sw[l] = (const float*)d_in[2 + l]; sb[l] = (const float*)d_in[11 + l]; }
        for (int l = 0; l < 3; l++) { cw[l] = (const float*)d_in[20 + l]; cb[l] = (const float*)d_in[23 + l]; }
        var = (const float*)d_in[26];
    }
    float* out = (float*)d_out;

    float* fbase = nullptr;
    bf16* bbase = nullptr;
    cudaGetSymbolAddress((void**)&fbase, d_F32);
    cudaGetSymbolAddress((void**)&bbase, d_BF);

    float* PZN = fbase+O_ZNEW; float* PSDFN = fbase+O_SDFNEW;
    float* PP = fbase+O_PTS;   float* PD = fbase+O_DIST;
    float* PSDFO = fbase+O_SDFO; float* PGE = fbase+O_GE; float* PGEM = fbase+O_GEM;
    float* PGR = fbase+O_GRAD;
    float* PW = fbase+O_WT;    float* PRGB = fbase+O_RGBS;

    float* zbuf[2] = { fbase+O_Z, fbase+O_ZT };
    float* sbuf[2] = { fbase+O_SDF, fbase+O_SDFT };

    Ctx X;
    for (int i = 0; i < 13; i++) {
        X.act[i].hi = bbase + aoff(i);
        X.act[i].lo = bbase + aoff(i) + NPTS * AW[i];
    }
    bf16* wb0 = bbase + BF_ACT_TOTAL;
    for (int i = 0; i < 19; i++) {
        X.wb[i].hi = wb0 + woff(i);
        X.wb[i].lo = wb0 + woff(i) + WN[i] * WK[i];
    }
    for (int l = 0; l < 9; l++) X.sb[l] = sb[l];
    for (int l = 0; l < 3; l++) X.cb[l] = cb[l];
    X.sw8raw = sw[8]; X.cw2raw = cw[2];

    // ---- fused weight plane prep ----
    {
        WSrc ws;
        const float* wsrc[19] = { sw[0],sw[1],sw[2],sw[3],sw[4],sw[5],sw[6],sw[7],sw[8],
                                  cw[0],cw[1],
                                  sw[7],sw[6],sw[5],sw[4],sw[3],sw[2],sw[1],sw[0] };
        for (int i = 0; i < 19; i++) ws.p[i] = wsrc[i];
        int total = (int)(BF_W_TOTAL / 2);
        k_wprep_all<<<(total+255)/256, 256>>>(ws, wb0, total);
    }

    Plane E = X.act[E_], H0 = X.act[H0_], H1 = X.act[H1_], H2 = X.act[H2_];
    Plane H3 = X.act[H3_], I4 = X.act[I4_], A4 = X.act[A4_], A5 = X.act[A5_];
    Plane A6 = X.act[A6_], A7 = X.act[A7_], GP = X.act[GP_], GQ = X.act[GQ_];
    Plane CIN = X.act[CIN_];

    // ---- initial 64 samples + sdf ----
    int cur = 0;
    k_ray_init<<<4, 256>>>(ro, rd, zbuf[cur]);
    int S = 64;
    int M = R_RAYS * S;
    sdf_forward_nostore(M, S, zbuf[cur], ro, rd, X, sbuf[cur]);

    // ---- 4 importance-sampling rounds (ping-pong buffers) ----
    for (int i = 0; i < 4; i++) {
        float inv_s = 64.0f * (float)(1 << i);
        k_upsample<<<4, 256>>>(ro, rd, zbuf[cur], sbuf[cur], PZN, S, inv_s);
        int Mn = R_RAYS * 16;
        sdf_forward_nostore(Mn, 16, PZN, ro, rd, X, PSDFN);
        k_merge<<<4, 256>>>(zbuf[cur], sbuf[cur], PZN, PSDFN, zbuf[1-cur], sbuf[1-cur], S);
        cur = 1 - cur;
        S += 16;
    }

    // ---- final forward ----
    M = (int)NPTS;
    k_dist_mid_pts<<<(M+255)/256, 256>>>(zbuf[cur], ro, rd, PP, PD);
    k_embed_c<1><<<(M*40+255)/256, 256>>>(PP, ro, rd, E.hi, E.lo, I4.hi, I4.lo, 256, 0, M,
                                          nullptr, nullptr);
    launch_bf3<1>(E, 40,   X.wb[0], 40,  sb[0], PNONE,0, H0.hi,H0.lo,256, PNONE,0,nullptr,nullptr, M,256,40);
    launch_bf3<1>(H0, 256, X.wb[1], 256, sb[1], PNONE,0, H1.hi,H1.lo,256, PNONE,0,nullptr,nullptr, M,256,256);
    launch_bf3<1>(H1, 256, X.wb[2], 256, sb[2], PNONE,0, H2.hi,H2.lo,256, PNONE,0,nullptr,nullptr, M,256,256);
    launch_bf3<6>(H2, 256, X.wb[3], 256, sb[3], PNONE,0, H3.hi,H3.lo,224, I4,256,nullptr,nullptr, M,217,256);
    launch_bf3<1>(I4, 256, X.wb[4], 256, sb[4], PNONE,0, A4.hi,A4.lo,256, PNONE,0,nullptr,nullptr, M,256,256);
    launch_bf3<1>(A4, 256, X.wb[5], 256, sb[5], PNONE,0, A5.hi,A5.lo,256, PNONE,0,nullptr,nullptr, M,256,256);
    launch_bf3<1>(A5, 256, X.wb[6], 256, sb[6], PNONE,0, A6.hi,A6.lo,256, PNONE,0,nullptr,nullptr, M,256,256);
    launch_bf3<4>(A6, 256, X.wb[7], 256, sb[7], PNONE,0, A7.hi,A7.lo,256, GP,256, sw[8],nullptr, M,256,256);
    launch_bf3<5>(A7, 256, X.wb[8], 256, sb[8], PNONE,0, PSDFO,nullptr,0, CIN,272,nullptr,nullptr, M,257,256);

    // ---- backward VJP (g_z7 already in GP from EPI4) ----
    launch_bf3<3>(GP, 256, X.wb[11], 256, nullptr, A6,256, GQ.hi,GQ.lo,256, PNONE,0,nullptr,nullptr, M,256,256);
    launch_bf3<3>(GQ, 256, X.wb[12], 256, nullptr, A5,256, GP.hi,GP.lo,256, PNONE,0,nullptr,nullptr, M,256,256);
    launch_bf3<3>(GP, 256, X.wb[13], 256, nullptr, A4,256, GQ.hi,GQ.lo,256, PNONE,0,nullptr,nullptr, M,256,256);
    launch_bf3<8>(GQ, 256, X.wb[14], 256, nullptr, H3,224, GP.hi,GP.lo,224, PNONE,0,nullptr,PGE, M,256,256);
    launch_bf3<3>(GP, 224, X.wb[15], 224, nullptr, H2,256, GQ.hi,GQ.lo,256, PNONE,0,nullptr,nullptr, M,256,224);
    launch_bf3<3>(GQ, 256, X.wb[16], 256, nullptr, H1,256, GP.hi,GP.lo,256, PNONE,0,nullptr,nullptr, M,256,256);
    launch_bf3<3>(GP, 256, X.wb[17], 256, nullptr, H0,256, GQ.hi,GQ.lo,256, PNONE,0,nullptr,nullptr, M,256,256);
    launch_bf3<0>(GQ, 256, X.wb[18], 256, nullptr, PNONE,0, PGEM,nullptr,39, PNONE,0,nullptr,nullptr, M,39,256);
    k_gradpts<<<(M+255)/256, 256>>>(PGEM, PGE, PP, PGR, M);

    // ---- compositing weights (alpha fused) ----
    k_ray_weights<<<4, 256>>>(PSDFO, PGR, PD, rd, var, PW);

    // ---- color net: cin -> relu GEMM -> fused rgb head (EPI 10) ----
    k_cin9<<<(M*20+255)/256, 256>>>(PP, rd, PGR, CIN.hi, CIN.lo, cb[2], PRGB, M);
    launch_bf3<2>(CIN, 272, X.wb[9], 272, cb[0], PNONE,0, GP.hi,GP.lo,256, PNONE,0,nullptr,nullptr, M,256,272);
    launch_bf3<10>(GP, 256, X.wb[10], 256, cb[1], PNONE,0, nullptr,nullptr,0, PNONE,0,
                   X.cw2raw, PRGB, M,256,256);
    k_reduce<<<4, 256>>>(PW, PRGB, out);
}

// round 17
// speedup vs baseline: 2.3331x; 1.0778x over previous
#include <cuda_runtime.h>
#include <cuda_bf16.h>
#include <math.h>
#include <stdint.h>
#include <stddef.h>

typedef __nv_bfloat16 bf16;

#define R_RAYS 1024
static constexpr size_t NPTS = 131072;

// ================= f32 scratch =================
constexpr size_t O_Z      = 0;
constexpr size_t O_SDF    = O_Z + NPTS;
constexpr size_t O_ZT     = O_SDF + NPTS;
constexpr size_t O_SDFT   = O_ZT + NPTS;
constexpr size_t O_ZNEW   = O_SDFT + NPTS;
constexpr size_t O_SDFNEW = O_ZNEW + 16384;
constexpr size_t O_PTS    = O_SDFNEW + 16384;
constexpr size_t O_DIST   = O_PTS + NPTS * 3;
constexpr size_t O_SDFO   = O_DIST + NPTS;
constexpr size_t O_GE     = O_SDFO + NPTS;
constexpr size_t O_GEM    = O_GE + NPTS * 39;
constexpr size_t O_GRAD   = O_GEM + NPTS * 39;
constexpr size_t O_WT     = O_GRAD + NPTS * 3;
constexpr size_t O_RGBS   = O_WT + NPTS;
constexpr size_t F32_TOTAL = O_RGBS + NPTS * 3;
__device__ __align__(256) float d_F32[F32_TOTAL];

// ================= bf16 plane scratch =================
constexpr size_t AW[13] = {40,256,256,256,224,256,256,256,256,256,256,256,272};
constexpr size_t aoff(int i) { size_t o = 0; for (int j = 0; j < i; j++) o += AW[j] * 2; return o * NPTS; }
constexpr size_t BF_ACT_TOTAL = aoff(13);
constexpr size_t WN[19] = {256,256,256,217,256,256,256,256,257, 256,256, 256,256,256,256,256,256,256, 39};
constexpr size_t WK[19] = {40, 256,256,256,256,256,256,256,256, 272,256, 256,256,256,256,224,256,256, 256};
constexpr size_t woff(int i) { size_t o = 0; for (int j = 0; j < i; j++) o += WN[j] * WK[j] * 2; return o; }
constexpr size_t BF_W_TOTAL = woff(19);
__device__ __align__(256) bf16 d_BF[BF_ACT_TOTAL + BF_W_TOTAL];

// fast-math helpers (error ~2^-21, far below bf16 plane storage noise 2^-16)
__device__ __forceinline__ float sigmoidf_(float x) {
    return __fdividef(1.0f, 1.0f + __expf(-x));
}
__device__ __forceinline__ float softp_(float v) {
    float s = 100.0f * v;
    float e = __expf(-fabsf(s));
    return (fmaxf(s, 0.0f) + __logf(1.0f + e)) * 0.01f;
}
// mask = -expm1(-100*h) with h >= 0 (softplus output)
__device__ __forceinline__ float maskf_(float h) {
    return 1.0f - __expf(-100.0f * h);
}

__device__ __forceinline__ void store2(void* hi, void* lo, size_t i, float v) {
    bf16 h = __float2bfloat16(v);
    ((bf16*)hi)[i] = h;
    ((bf16*)lo)[i] = __float2bfloat16(v - __bfloat162float(h));
}
__device__ __forceinline__ void store2x2(void* hi, void* lo, size_t i, float v0, float v1) {
    bf16 h0 = __float2bfloat16(v0), h1 = __float2bfloat16(v1);
    __nv_bfloat162 hh; hh.x = h0; hh.y = h1;
    *(__nv_bfloat162*)((bf16*)hi + i) = hh;
    __nv_bfloat162 ll;
    ll.x = __float2bfloat16(v0 - __bfloat162float(h0));
    ll.y = __float2bfloat16(v1 - __bfloat162float(h1));
    *(__nv_bfloat162*)((bf16*)lo + i) = ll;
}
__device__ __forceinline__ float join2(const bf16* hi, const bf16* lo, size_t i) {
    return __bfloat162float(hi[i]) + __bfloat162float(lo[i]);
}

__device__ __forceinline__ uint32_t s2u(const void* p) {
    return (uint32_t)__cvta_generic_to_shared(p);
}
__device__ __forceinline__ void cpa16(uint32_t d, const void* s, int sz) {
    asm volatile("cp.async.ca.shared.global [%0], [%1], 16, %2;" :: "r"(d), "l"(s), "r"(sz));
}
#define CP_COMMIT() asm volatile("cp.async.commit_group;")
#define CP_WAIT1()  asm volatile("cp.async.wait_group 1;")

__device__ __forceinline__ void ldsm4(uint32_t& r0, uint32_t& r1, uint32_t& r2, uint32_t& r3,
                                      uint32_t addr) {
    asm volatile("ldmatrix.sync.aligned.m8n8.x4.shared.b16 {%0,%1,%2,%3}, [%4];"
                 : "=r"(r0), "=r"(r1), "=r"(r2), "=r"(r3) : "r"(addr));
}

// ---- fused weight prep ----
struct WSrc { const float* p[19]; };
__global__ void k_wprep_all(WSrc ws, bf16* __restrict__ wb, int total)
{
    const int wn[19] = {256,256,256,217,256,256,256,256,257, 256,256, 256,256,256,256,256,256,256, 39};
    const int wk[19] = {40, 256,256,256,256,256,256,256,256, 272,256, 256,256,256,256,224,256,256, 256};
    const int wr[19] = {39,256,256,256,256,256,256,256,256, 265,256, 256,256,256,256,256,256,256, 39};
    const int wc[19] = {256,256,256,217,256,256,256,256,257, 256,256, 256,256,256,256,217,256,256, 256};

    int idx = blockIdx.x * blockDim.x + threadIdx.x;
    if (idx >= total) return;
    size_t off = (size_t)idx;
    int bi = 0;
    size_t base = 0;
#pragma unroll
    for (int i = 0; i < 19; i++) {
        size_t sz = (size_t)wn[i] * wk[i];
        if (off < sz) { bi = i; break; }
        off -= sz;
        base += 2 * sz;
    }
    int Kp = wk[bi];
    int n = (int)(off / Kp), k = (int)(off % Kp);
    const float* W = ws.p[bi];
    float v = 0.0f;
    if (bi <= 10) { if (k < wr[bi] && n < wc[bi]) v = W[(size_t)k * wc[bi] + n]; }
    else          { if (n < wr[bi] && k < wc[bi]) v = W[(size_t)n * wc[bi] + k]; }
    bf16 h = __float2bfloat16(v);
    wb[base + off] = h;
    wb[base + (size_t)wn[bi] * wk[bi] + off] = __float2bfloat16(v - __bfloat162float(h));
}

// ============================================================================
// bf16x3 GEMM, ldmatrix loads, packed epilogue stores, fast-math epilogues.
// EPI: 0 f32 lin | 1 sp->planes | 2 relu->planes | 3 mask-mul->planes
//      4 sp->planes + bwinit->D | 5 out8: col0->f32 sdf, col>=1 ->CIN planes
//      6 sp->planes + concat->D | 7 sp->concat->D only | 8 split: Gz+GE
//      9 sp + dot(W8 col0) -> atomicAdd GE[row]
//     10 relu + dot(W8[.][0..2]) -> atomicAdd GE[row*3+c]
// ============================================================================
template <int EPI>
__global__ void __launch_bounds__(256, 2) gemm_bf3(
    const bf16* __restrict__ Ahi, const bf16* __restrict__ Alo, int lda,
    const bf16* __restrict__ Bhi, const bf16* __restrict__ Blo, int ldb,
    const float* __restrict__ bias,
    const bf16* __restrict__ Mhi, const bf16* __restrict__ Mlo, int ldh,
    void* __restrict__ C0, void* __restrict__ C1, int ldc,
    bf16* __restrict__ D0, bf16* __restrict__ D1, int ldd,
    const float* __restrict__ W8, float* __restrict__ GE,
    int M, int N, int K)
{
    extern __shared__ bf16 smb[];
    constexpr int P = 40;
    constexpr int TILE = 128 * P;

    const int tid  = threadIdx.x;
    const int wid  = tid >> 5;
    const int lane = tid & 31;
    const int wm = wid & 3;
    const int wn = wid >> 2;
    const int m0 = blockIdx.y * 128;
    const int n0 = blockIdx.x * 128;
    const int r  = lane >> 2;
    const int cq = lane & 3;

    const int aOff = (wm * 32 + (lane & 15)) * P + ((lane >> 4) << 3);
    const int bOff = (wn * 64 + (lane & 7) + ((lane & 16) >> 1)) * P + (((lane >> 3) & 1) << 3);

    float acc[2][8][4] = {};
    const int nsteps = (K + 31) >> 5;

    auto load_stage = [&](int stage, int k0) {
        bf16* base = smb + stage * 4 * TILE;
        int row  = tid >> 1;
        int half = (tid & 1) * 16;
        {
            int gm = m0 + row;
            size_t so = (size_t)(gm < M ? gm : 0) * lda + k0 + half;
            bf16* dH = base + 0 * TILE + row * P + half;
            bf16* dL = base + 1 * TILE + row * P + half;
#pragma unroll
            for (int c = 0; c < 16; c += 8) {
                int sz = (gm < M && (k0 + half + c) < K) ? 16 : 0;
                cpa16(s2u(dH + c), Ahi + so + c, sz);
                cpa16(s2u(dL + c), Alo + so + c, sz);
            }
        }
        {
            int gn = n0 + row;
            size_t so = (size_t)(gn < N ? gn : 0) * ldb + k0 + half;
            bf16* dH = base + 2 * TILE + row * P + half;
            bf16* dL = base + 3 * TILE + row * P + half;
#pragma unroll
            for (int c = 0; c < 16; c += 8) {
                int sz = (gn < N && (k0 + half + c) < K) ? 16 : 0;
                cpa16(s2u(dH + c), Bhi + so + c, sz);
                cpa16(s2u(dL + c), Blo + so + c, sz);
            }
        }
    };

    load_stage(0, 0);
    CP_COMMIT();

    for (int s = 0; s < nsteps; s++) {
        if (s + 1 < nsteps) load_stage((s + 1) & 1, (s + 1) * 32);
        CP_COMMIT();
        CP_WAIT1();
        __syncthreads();

        const bf16* base = smb + (s & 1) * 4 * TILE;
        uint32_t aAH = s2u(base + 0 * TILE + aOff);
        uint32_t aAL = s2u(base + 1 * TILE + aOff);
        uint32_t aBH = s2u(base + 2 * TILE + bOff);
        uint32_t aBL = s2u(base + 3 * TILE + bOff);

#pragma unroll
        for (int ks = 0; ks < 32; ks += 16) {
            uint32_t aH[2][4], aL[2][4];
#pragma unroll
            for (int i = 0; i < 2; i++) {
                uint32_t ao = (uint32_t)((i * 16 * P + ks) * 2);
                ldsm4(aH[i][0], aH[i][1], aH[i][2], aH[i][3], aAH + ao);
                ldsm4(aL[i][0], aL[i][1], aL[i][2], aL[i][3], aAL + ao);
            }
#pragma unroll
            for (int j2 = 0; j2 < 4; j2++) {
                uint32_t bo = (uint32_t)((j2 * 16 * P + ks) * 2);
                uint32_t bh[4], bl[4];
                ldsm4(bh[0], bh[1], bh[2], bh[3], aBH + bo);
                ldsm4(bl[0], bl[1], bl[2], bl[3], aBL + bo);
#pragma unroll
                for (int jj = 0; jj < 2; jj++) {
                    int j = j2 * 2 + jj;
                    uint32_t bH0 = bh[jj*2], bH1 = bh[jj*2+1];
                    uint32_t bL0 = bl[jj*2], bL1 = bl[jj*2+1];
#pragma unroll
                    for (int i = 0; i < 2; i++) {
                        asm volatile(
                            "mma.sync.aligned.m16n8k16.row.col.f32.bf16.bf16.f32 "
                            "{%0,%1,%2,%3}, {%4,%5,%6,%7}, {%8,%9}, {%0,%1,%2,%3};"
                            : "+f"(acc[i][j][0]), "+f"(acc[i][j][1]),
                              "+f"(acc[i][j][2]), "+f"(acc[i][j][3])
                            : "r"(aH[i][0]), "r"(aH[i][1]), "r"(aH[i][2]), "r"(aH[i][3]),
                              "r"(bL0), "r"(bL1));
                        asm volatile(
                            "mma.sync.aligned.m16n8k16.row.col.f32.bf16.bf16.f32 "
                            "{%0,%1,%2,%3}, {%4,%5,%6,%7}, {%8,%9}, {%0,%1,%2,%3};"
                            : "+f"(acc[i][j][0]), "+f"(acc[i][j][1]),
                              "+f"(acc[i][j][2]), "+f"(acc[i][j][3])
                            : "r"(aL[i][0]), "r"(aL[i][1]), "r"(aL[i][2]), "r"(aL[i][3]),
                              "r"(bH0), "r"(bH1));
                        asm volatile(
                            "mma.sync.aligned.m16n8k16.row.col.f32.bf16.bf16.f32 "
                            "{%0,%1,%2,%3}, {%4,%5,%6,%7}, {%8,%9}, {%0,%1,%2,%3};"
                            : "+f"(acc[i][j][0]), "+f"(acc[i][j][1]),
                              "+f"(acc[i][j][2]), "+f"(acc[i][j][3])
                            : "r"(aH[i][0]), "r"(aH[i][1]), "r"(aH[i][2]), "r"(aH[i][3]),
                              "r"(bH0), "r"(bH1));
                    }
                }
            }
        }
        __syncthreads();
    }

    // ---- EPI 9/10: fused head reductions (N must be 256) ----
    if (EPI == 9 || EPI == 10) {
#pragma unroll
        for (int i = 0; i < 2; i++) {
#pragma unroll
            for (int tr = 0; tr < 2; tr++) {
                int row = m0 + wm * 32 + i * 16 + r + tr * 8;
                float p0 = 0.f, p1 = 0.f, p2 = 0.f;
#pragma unroll
                for (int j = 0; j < 8; j++) {
                    int col0 = n0 + wn * 64 + j * 8 + cq * 2;
                    float v0 = acc[i][j][tr*2+0] + bias[col0];
                    float v1 = acc[i][j][tr*2+1] + bias[col0+1];
                    if (EPI == 9) {
                        v0 = softp_(v0); v1 = softp_(v1);
                        p0 = fmaf(v0, W8[(size_t)col0 * 257],
                             fmaf(v1, W8[(size_t)(col0+1) * 257], p0));
                    } else {
                        v0 = fmaxf(v0, 0.f); v1 = fmaxf(v1, 0.f);
                        p0 = fmaf(v0, W8[col0*3+0], fmaf(v1, W8[(col0+1)*3+0], p0));
                        p1 = fmaf(v0, W8[col0*3+1], fmaf(v1, W8[(col0+1)*3+1], p1));
                        p2 = fmaf(v0, W8[col0*3+2], fmaf(v1, W8[(col0+1)*3+2], p2));
                    }
                }
                p0 += __shfl_xor_sync(0xffffffffu, p0, 1);
                p0 += __shfl_xor_sync(0xffffffffu, p0, 2);
                if (EPI == 10) {
                    p1 += __shfl_xor_sync(0xffffffffu, p1, 1);
                    p1 += __shfl_xor_sync(0xffffffffu, p1, 2);
                    p2 += __shfl_xor_sync(0xffffffffu, p2, 1);
                    p2 += __shfl_xor_sync(0xffffffffu, p2, 2);
                }
                if (cq == 0 && row < M) {
                    if (EPI == 9) atomicAdd(&GE[row], p0);
                    else {
                        atomicAdd(&GE[(size_t)row*3+0], p0);
                        atomicAdd(&GE[(size_t)row*3+1], p1);
                        atomicAdd(&GE[(size_t)row*3+2], p2);
                    }
                }
            }
        }
        return;
    }

    // ---- generic epilogue (packed column pairs, alignment-guarded) ----
#pragma unroll
    for (int i = 0; i < 2; i++) {
        int row0 = m0 + wm * 32 + i * 16 + r;
#pragma unroll
        for (int j = 0; j < 8; j++) {
            int col0 = n0 + wn * 64 + j * 8 + cq * 2;
#pragma unroll
            for (int tr = 0; tr < 2; tr++) {
                int row = row0 + tr * 8;
                if (row >= M || col0 >= N) continue;
                float v0 = acc[i][j][tr*2+0];
                float v1 = acc[i][j][tr*2+1];
                bool has1 = (col0 + 1) < N;
                if (bias) { v0 += bias[col0]; if (has1) v1 += bias[col0+1]; }
                if (EPI == 1 || EPI == 4 || EPI == 6 || EPI == 7) { v0 = softp_(v0); v1 = softp_(v1); }
                else if (EPI == 2) { v0 = fmaxf(v0, 0.0f); v1 = fmaxf(v1, 0.0f); }
                else if (EPI == 3) {
                    v0 *= maskf_(join2(Mhi, Mlo, (size_t)row * ldh + col0));
                    if (has1) v1 *= maskf_(join2(Mhi, Mlo, (size_t)row * ldh + col0 + 1));
                }

                size_t ci = (size_t)row * ldc + col0;
                bool aligned = ((ci & 1) == 0);
                if (EPI == 0) {
                    if (has1 && aligned) *(float2*)((float*)C0 + ci) = make_float2(v0, v1);
                    else {
                        ((float*)C0)[ci] = v0;
                        if (has1) ((float*)C0)[ci + 1] = v1;
                    }
                } else if (EPI == 1 || EPI == 2 || EPI == 3) {
                    if (has1 && aligned) store2x2(C0, C1, ci, v0, v1);
                    else {
                        store2(C0, C1, ci, v0);
                        if (has1) store2(C0, C1, ci + 1, v1);
                    }
                } else if (EPI == 4) {
                    float d0 = W8[(size_t)col0 * 257] * maskf_(v0);
                    size_t di = (size_t)row * ldd + col0;
                    if (has1 && aligned) {
                        float d1 = W8[(size_t)(col0+1) * 257] * maskf_(v1);
                        store2x2(C0, C1, ci, v0, v1);
                        store2x2(D0, D1, di, d0, d1);
                    } else {
                        store2(C0, C1, ci, v0); store2(D0, D1, di, d0);
                        if (has1) {
                            float d1 = W8[(size_t)(col0+1) * 257] * maskf_(v1);
                            store2(C0, C1, ci + 1, v1); store2(D0, D1, di + 1, d1);
                        }
                    }
                } else if (EPI == 5) {
                    if (col0 == 0) {
                        ((float*)C0)[row] = v0;
                        if (has1) store2(D0, D1, (size_t)row * ldd + 9, v1);
                    } else {
                        size_t di = (size_t)row * ldd + 8 + col0;
                        if (has1 && ((di & 1) == 0)) store2x2(D0, D1, di, v0, v1);
                        else {
                            store2(D0, D1, di, v0);
                            if (has1) store2(D0, D1, di + 1, v1);
                        }
                    }
                } else if (EPI == 6) {
                    size_t di = (size_t)row * ldd + col0;
                    if (has1 && aligned) {
                        store2x2(C0, C1, ci, v0, v1);
                        store2x2(D0, D1, di, v0 * 0.7071067811865476f, v1 * 0.7071067811865476f);
                    } else {
                        store2(C0, C1, ci, v0);
                        store2(D0, D1, di, v0 * 0.7071067811865476f);
                        if (has1) {
                            store2(C0, C1, ci + 1, v1);
                            store2(D0, D1, di + 1, v1 * 0.7071067811865476f);
                        }
                    }
                } else if (EPI == 7) {
                    size_t di = (size_t)row * ldd + col0;
                    if (has1 && ((di & 1) == 0))
                        store2x2(D0, D1, di, v0 * 0.7071067811865476f, v1 * 0.7071067811865476f);
                    else {
                        store2(D0, D1, di, v0 * 0.7071067811865476f);
                        if (has1) store2(D0, D1, di + 1, v1 * 0.7071067811865476f);
                    }
                } else if (EPI == 8) {
#pragma unroll
                    for (int u = 0; u < 2; u++) {
                        int col = col0 + u;
                        if (col >= N) continue;
                        float vs = (u ? v1 : v0) * 0.7071067811865476f;
                        if (col < 217) {
                            store2(C0, C1, (size_t)row * 224 + col,
                                   vs * maskf_(join2(Mhi, Mlo, (size_t)row * ldh + col)));
                        } else {
                            if (col < 224) store2(C0, C1, (size_t)row * 224 + col, 0.0f);
                            GE[(size_t)row * 39 + col - 217] = vs;
                        }
                    }
                }
            }
        }
    }
}

// ===================== small kernels =====================

__global__ void k_ray_init(const float* __restrict__ ro, const float* __restrict__ rd,
                           float* __restrict__ Z)
{
    int r = blockIdx.x * blockDim.x + threadIdx.x;
    if (r >= R_RAYS) return;
    float ox = ro[r*3], oy = ro[r*3+1], oz = ro[r*3+2];
    float dx = rd[r*3], dy = rd[r*3+1], dz = rd[r*3+2];
    float a = dx*dx + dy*dy + dz*dz;
    float b = 2.0f * (ox*dx + oy*dy + oz*dz);
    float mid = -b / (2.0f * a);
    float nv = fmaxf(mid - 1.0f, 0.05f);
    float fv = mid + 1.0f;
    for (int s = 0; s < 64; s++)
        Z[r*64 + s] = nv + (fv - nv) * ((float)s * (1.0f/63.0f));
}

__global__ void k_dist_mid_pts(const float* __restrict__ Z, const float* __restrict__ ro,
                               const float* __restrict__ rd, float* __restrict__ P,
                               float* __restrict__ D)
{
    int m = blockIdx.x * blockDim.x + threadIdx.x;
    if (m >= (int)NPTS) return;
    int s = m & 127, r = m >> 7;
    float z = Z[m];
    float d = (s < 127) ? (Z[m+1] - z) : 0.03125f;
    D[m] = d;
    float mz = fmaf(0.5f, d, z);
#pragma unroll
    for (int j = 0; j < 3; j++)
        P[(size_t)m*3 + j] = fmaf(rd[r*3+j], mz, ro[r*3+j]);
}

// coalesced embed; also initializes sdf accumulator with bias when sdfini != 0
template <int PSRC>
__global__ void k_embed_c(const float* __restrict__ ZorP,
                          const float* __restrict__ ro, const float* __restrict__ rd,
                          bf16* __restrict__ Eh, bf16* __restrict__ El,
                          bf16* __restrict__ Th, bf16* __restrict__ Tl,
                          int tp, int S, int M,
                          const float* __restrict__ b8, float* __restrict__ sdfini)
{
    int idx = blockIdx.x * blockDim.x + threadIdx.x;
    if (idx >= M * 40) return;
    int m = idx / 40, c = idx - m * 40;
    if (c == 39) {
        store2(Eh, El, (size_t)m*40 + 39, 0.0f);
        if (sdfini) sdfini[m] = b8[0];
        return;
    }

    float v;
    if (c < 3) {
        if (PSRC) v = ZorP[(size_t)m*3 + c];
        else { int r = m / S; v = fmaf(rd[r*3+c], ZorP[m], ro[r*3+c]); }
    } else {
        int cc = c - 3;
        int k = cc / 6, rem = cc - k * 6;
        int jdim = rem % 3;
        float p;
        if (PSRC) p = ZorP[(size_t)m*3 + jdim];
        else { int r = m / S; p = fmaf(rd[r*3+jdim], ZorP[m], ro[r*3+jdim]); }
        float f = (float)(1 << k);
        float sv, cv;
        sincosf(f * p, &sv, &cv);
        v = (rem < 3) ? sv : cv;
    }
    store2(Eh, El, (size_t)m*40 + c, v);
    store2(Th, Tl, (size_t)m*tp + 217 + c, v * 0.7071067811865476f);
}

__global__ void k_upsample(const float* __restrict__ ro, const float* __restrict__ rd,
                           const float* __restrict__ Z, const float* __restrict__ SD,
                           float* __restrict__ ZN, int S, float inv_s)
{
    int r = blockIdx.x * blockDim.x + threadIdx.x;
    if (r >= R_RAYS) return;
    float ox = ro[r*3], oy = ro[r*3+1], oz = ro[r*3+2];
    float dx = rd[r*3], dy = rd[r*3+1], dz = rd[r*3+2];
    const float* zr = Z + (size_t)r * S;
    const float* sr = SD + (size_t)r * S;

    float w[128], cdf[129];
    float prev_raw = 0.0f, T = 1.0f, wsum = 0.0f;
    float z_i = zr[0];
    float px = fmaf(dx,z_i,ox), py = fmaf(dy,z_i,oy), pz = fmaf(dz,z_i,oz);
    float rad_i = sqrtf(px*px + py*py + pz*pz);
    float sdf_i = sr[0];

    for (int i = 0; i < S - 1; i++) {
        float z_n = zr[i+1], sdf_n = sr[i+1];
        float qx = fmaf(dx,z_n,ox), qy = fmaf(dy,z_n,oy), qz = fmaf(dz,z_n,oz);
        float rad_n = sqrtf(qx*qx + qy*qy + qz*qz);
        bool inside = (rad_i < 1.0f) || (rad_n < 1.0f);
        float mid_sdf = 0.5f * (sdf_i + sdf_n);
        float raw = (sdf_n - sdf_i) / (z_n - z_i + 1e-5f);
        float cosv = fminf(raw, prev_raw);
        prev_raw = raw;
        cosv = fminf(fmaxf(cosv, -1000.0f), 0.0f);
        if (!inside) cosv = 0.0f;
        float dist = z_n - z_i;
        float pc = sigmoidf_((mid_sdf - cosv*dist*0.5f) * inv_s);
        float nc = sigmoidf_((mid_sdf + cosv*dist*0.5f) * inv_s);
        float alpha = (pc - nc + 1e-5f) / (pc + 1e-5f);
        float wi = alpha * T;
        T *= (1.0f - alpha + 1e-7f);
        wi += 1e-5f;
        w[i] = wi; wsum += wi;
        z_i = z_n; rad_i = rad_n; sdf_i = sdf_n;
    }

    cdf[0] = 0.0f;
    float invsum = 1.0f / wsum;
    for (int i = 0; i < S - 1; i++) cdf[i+1] = cdf[i] + w[i] * invsum;

    for (int j = 0; j < 16; j++) {
        float u = 0.03125f + (float)j * 0.0625f;
        int lo = 0, hi = S;
        while (lo < hi) { int md = (lo + hi) >> 1; if (cdf[md] <= u) lo = md + 1; else hi = md; }
        int below = lo - 1; if (below < 0) below = 0; if (below > S-1) below = S-1;
        int above = lo;     if (above > S-1) above = S-1;
        float c0 = cdf[below], c1 = cdf[above];
        float b0 = zr[below],  b1 = zr[above];
        float den = (c1 - c0) < 1e-5f ? 1.0f : (c1 - c0);
        ZN[r*16 + j] = b0 + (u - c0) / den * (b1 - b0);
    }
}

__global__ void k_merge(const float* __restrict__ Z, const float* __restrict__ SD,
                        const float* __restrict__ ZN, const float* __restrict__ SN,
                        float* __restrict__ ZT, float* __restrict__ ST, int S)
{
    int r = blockIdx.x * blockDim.x + threadIdx.x;
    if (r >= R_RAYS) return;
    const float* zo = Z + (size_t)r*S;  const float* so = SD + (size_t)r*S;
    const float* zn = ZN + r*16;        const float* sn = SN + r*16;
    float* zt = ZT + (size_t)r*(S+16);  float* st = ST + (size_t)r*(S+16);
    int i = 0, j = 0;
    for (int k = 0; k < S + 16; k++) {
        bool useOld = (i < S) && ((j >= 16) || (zo[i] <= zn[j]));
        if (useOld) { zt[k] = zo[i]; st[k] = so[i]; i++; }
        else        { zt[k] = zn[j]; st[k] = sn[j]; j++; }
    }
}

__global__ void k_gradpts(const float* __restrict__ GEm, const float* __restrict__ GEs,
                          const float* __restrict__ P, float* __restrict__ GR, int M)
{
    int m = blockIdx.x * blockDim.x + threadIdx.x;
    if (m >= M) return;
    const float* ga = GEm + (size_t)m*39;
    const float* gb = GEs + (size_t)m*39;
    float p[3] = {P[(size_t)m*3], P[(size_t)m*3+1], P[(size_t)m*3+2]};
    float g[3];
#pragma unroll
    for (int j = 0; j < 3; j++) g[j] = ga[j] + gb[j];
    float f = 1.0f;
#pragma unroll
    for (int k = 0; k < 6; k++) {
#pragma unroll
        for (int j = 0; j < 3; j++) {
            float s, c;
            sincosf(f * p[j], &s, &c);
            float gs = ga[3+6*k+j]   + gb[3+6*k+j];
            float gc = ga[3+6*k+3+j] + gb[3+6*k+3+j];
            g[j] = fmaf( f * c, gs, g[j]);
            g[j] = fmaf(-f * s, gc, g[j]);
        }
        f *= 2.0f;
    }
#pragma unroll
    for (int j = 0; j < 3; j++) GR[(size_t)m*3 + j] = g[j];
}

// fused alpha + transmittance scan (per ray)
__global__ void k_ray_weights(const float* __restrict__ SDFO, const float* __restrict__ GR,
                              const float* __restrict__ D, const float* __restrict__ rd,
                              const float* __restrict__ var, float* __restrict__ W)
{
    int rr = blockIdx.x * blockDim.x + threadIdx.x;
    if (rr >= R_RAYS) return;
    float dx = rd[rr*3], dy = rd[rr*3+1], dz = rd[rr*3+2];
    float inv_s = fminf(fmaxf(__expf(10.0f * var[0]), 1e-6f), 1e6f);
    float T = 1.0f;
    for (int s = 0; s < 128; s++) {
        int m = rr*128 + s;
        float tc = dx*GR[(size_t)m*3] + dy*GR[(size_t)m*3+1] + dz*GR[(size_t)m*3+2];
        float ic = fminf(tc, 0.0f);
        float sdf = SDFO[m], dist = D[m];
        float pc = sigmoidf_((sdf - ic*dist*0.5f) * inv_s);
        float nc = sigmoidf_((sdf + ic*dist*0.5f) * inv_s);
        float a = fminf(fmaxf((pc - nc + 1e-5f) / (pc + 1e-5f), 0.0f), 1.0f);
        W[m] = a * T;
        T *= (1.0f - a + 1e-7f);
    }
}

// CIN cols 0..8 + pads 265..271 + rgb accumulator init (cb2)
__global__ void k_cin9(const float* __restrict__ P, const float* __restrict__ rd,
                       const float* __restrict__ GR, bf16* __restrict__ Ch,
                       bf16* __restrict__ Cl, const float* __restrict__ cb2,
                       float* __restrict__ RGB, int M)
{
    int idx = blockIdx.x * blockDim.x + threadIdx.x;
    if (idx >= M * 20) return;
    int m = idx / 20, c = idx - m * 20;
    if (c < 9) {
        float v;
        if (c < 3) v = P[(size_t)m*3 + c];
        else if (c < 6) { int r = m >> 7; v = rd[r*3 + (c-3)]; }
        else {
            float g0 = GR[(size_t)m*3], g1 = GR[(size_t)m*3+1], g2 = GR[(size_t)m*3+2];
            float n = fmaxf(sqrtf(g0*g0 + g1*g1 + g2*g2), 1e-6f);
            v = GR[(size_t)m*3 + (c-6)] / n;
        }
        store2(Ch, Cl, (size_t)m*272 + c, v);
    } else if (c < 16) {
        store2(Ch, Cl, (size_t)m*272 + 265 + (c - 9), 0.0f);
    } else if (c < 19) {
        RGB[(size_t)m*3 + (c - 16)] = cb2[c - 16];
    }
}

__global__ void k_reduce(const float* __restrict__ W, const float* __restrict__ rgbs,
                         float* __restrict__ out)
{
    int r = blockIdx.x * blockDim.x + threadIdx.x;
    if (r >= R_RAYS) return;
    float s0 = 0.f, s1 = 0.f, s2 = 0.f;
    for (int s = 0; s < 128; s++) {
        int m = r*128 + s;
        float w = W[m];
        s0 = fmaf(w, sigmoidf_(rgbs[(size_t)m*3+0]), s0);
        s1 = fmaf(w, sigmoidf_(rgbs[(size_t)m*3+1]), s1);
        s2 = fmaf(w, sigmoidf_(rgbs[(size_t)m*3+2]), s2);
    }
    out[r*3+0] = s0; out[r*3+1] = s1; out[r*3+2] = s2;
}

// ===================== host orchestration =====================

static const int GEMM_SHM = 81920;

struct Plane { bf16* hi; bf16* lo; };
static Plane PNONE = {nullptr, nullptr};

template <int EPI>
static void launch_bf3(Plane A, int lda, Plane B, int ldb, const float* bias,
                       Plane Hm, int ldh, void* C0, void* C1, int ldc,
                       Plane D, int ldd, const float* W8, float* GE,
                       int M, int N, int K)
{
    dim3 g((N + 127) / 128, (M + 127) / 128);
    cudaFuncSetAttribute(gemm_bf3<EPI>, cudaFuncAttributeMaxDynamicSharedMemorySize, GEMM_SHM);
    gemm_bf3<EPI><<<g, 256, GEMM_SHM>>>(A.hi, A.lo, lda, B.hi, B.lo, ldb, bias,
                                        Hm.hi, Hm.lo, ldh, C0, C1, ldc,
                                        D.hi, D.lo, ldd, W8, GE, M, N, K);
}

struct Ctx {
    Plane act[13];
    Plane wb[19];
    const float* sb[9]; const float* cb[3];
    const float* sw8raw; const float* cw2raw;
};
enum { E_=0, H0_, H1_, H2_, H3_, I4_, A4_, A5_, A6_, A7_, GP_, GQ_, CIN_ };

static void sdf_forward_nostore(int M, int S, const float* Z,
                                const float* ro, const float* rd,
                                const Ctx& X, float* sdf_dest)
{
    Plane E = X.act[E_], GP = X.act[GP_], GQ = X.act[GQ_], CIN = X.act[CIN_];
    k_embed_c<0><<<(M*40+255)/256, 256>>>(Z, ro, rd, E.hi, E.lo, CIN.hi, CIN.lo, 272, S, M,
                                          X.sb[8], sdf_dest);
    launch_bf3<1>(E, 40,   X.wb[0], 40,  X.sb[0], PNONE,0, GP.hi,GP.lo,256, PNONE,0,nullptr,nullptr, M,256,40);
    launch_bf3<1>(GP, 256, X.wb[1], 256, X.sb[1], PNONE,0, GQ.hi,GQ.lo,256, PNONE,0,nullptr,nullptr, M,256,256);
    launch_bf3<1>(GQ, 256, X.wb[2], 256, X.sb[2], PNONE,0, GP.hi,GP.lo,256, PNONE,0,nullptr,nullptr, M,256,256);
    launch_bf3<7>(GP, 256, X.wb[3], 256, X.sb[3], PNONE,0, nullptr,nullptr,0, CIN,272,nullptr,nullptr, M,217,256);
    launch_bf3<1>(CIN, 272, X.wb[4], 256, X.sb[4], PNONE,0, GQ.hi,GQ.lo,256, PNONE,0,nullptr,nullptr, M,256,256);
    launch_bf3<1>(GQ, 256, X.wb[5], 256, X.sb[5], PNONE,0, GP.hi,GP.lo,256, PNONE,0,nullptr,nullptr, M,256,256);
    launch_bf3<1>(GP, 256, X.wb[6], 256, X.sb[6], PNONE,0, GQ.hi,GQ.lo,256, PNONE,0,nullptr,nullptr, M,256,256);
    launch_bf3<9>(GQ, 256, X.wb[7], 256, X.sb[7], PNONE,0, nullptr,nullptr,0, PNONE,0,
                  X.sw8raw, sdf_dest, M,256,256);
}

extern "C" void kernel_launch(void* const* d_in, const int* in_sizes, int n_in,
                              void* d_out, int out_size)
{
    const float* ro = (const float*)d_in[0];
    const float* rd = (const float*)d_in[1];
    const float* sw[9]; const float* sb[9];
    const float* cw[3]; const float* cb[3];
    const float* var;

    bool interleaved = (in_sizes[3] < 1024);
    if (interleaved) {
        for (int l = 0; l < 9; l++) { sw[l] = (const float*)d_in[2 + 2*l]; sb[l] = (const float*)d_in[3 + 2*l]; }
        for (int l = 0; l < 3; l++) { cw[l] = (const float*)d_in[20 + 2*l]; cb[l] = (const float*)d_in[21 + 2*l]; }
        var = (const float*)d_in[26];
    } else {
        for (int l = 0; l < 9; l++) { sw[l] = (const float*)d_in[2 + l]; sb[l] = (const float*)d_in[11 + l]; }
        for (int l = 0; l < 3; l++) { cw[l] = (const float*)d_in[20 + l]; cb[l] = (const float*)d_in[23 + l]; }
        var = (const float*)d_in[26];
    }
    float* out = (float*)d_out;

    float* fbase = nullptr;
    bf16* bbase = nullptr;
    cudaGetSymbolAddress((void**)&fbase, d_F32);
    cudaGetSymbolAddress((void**)&bbase, d_BF);

    float* PZN = fbase+O_ZNEW; float* PSDFN = fbase+O_SDFNEW;
    float* PP = fbase+O_PTS;   float* PD = fbase+O_DIST;
    float* PSDFO = fbase+O_SDFO; float* PGE = fbase+O_GE; float* PGEM = fbase+O_GEM;
    float* PGR = fbase+O_GRAD;
    float* PW = fbase+O_WT;    float* PRGB = fbase+O_RGBS;

    float* zbuf[2] = { fbase+O_Z, fbase+O_ZT };
    float* sbuf[2] = { fbase+O_SDF, fbase+O_SDFT };

    Ctx X;
    for (int i = 0; i < 13; i++) {
        X.act[i].hi = bbase + aoff(i);
        X.act[i].lo = bbase + aoff(i) + NPTS * AW[i];
    }
    bf16* wb0 = bbase + BF_ACT_TOTAL;
    for (int i = 0; i < 19; i++) {
        X.wb[i].hi = wb0 + woff(i);
        X.wb[i].lo = wb0 + woff(i) + WN[i] * WK[i];
    }
    for (int l = 0; l < 9; l++) X.sb[l] = sb[l];
    for (int l = 0; l < 3; l++) X.cb[l] = cb[l];
    X.sw8raw = sw[8]; X.cw2raw = cw[2];

    // ---- fused weight plane prep ----
    {
        WSrc ws;
        const float* wsrc[19] = { sw[0],sw[1],sw[2],sw[3],sw[4],sw[5],sw[6],sw[7],sw[8],
                                  cw[0],cw[1],
                                  sw[7],sw[6],sw[5],sw[4],sw[3],sw[2],sw[1],sw[0] };
        for (int i = 0; i < 19; i++) ws.p[i] = wsrc[i];
        int total = (int)(BF_W_TOTAL / 2);
        k_wprep_all<<<(total+255)/256, 256>>>(ws, wb0, total);
    }

    Plane E = X.act[E_], H0 = X.act[H0_], H1 = X.act[H1_], H2 = X.act[H2_];
    Plane H3 = X.act[H3_], I4 = X.act[I4_], A4 = X.act[A4_], A5 = X.act[A5_];
    Plane A6 = X.act[A6_], A7 = X.act[A7_], GP = X.act[GP_], GQ = X.act[GQ_];
    Plane CIN = X.act[CIN_];

    // ---- initial 64 samples + sdf ----
    int cur = 0;
    k_ray_init<<<4, 256>>>(ro, rd, zbuf[cur]);
    int S = 64;
    int M = R_RAYS * S;
    sdf_forward_nostore(M, S, zbuf[cur], ro, rd, X, sbuf[cur]);

    // ---- 4 importance-sampling rounds (ping-pong buffers) ----
    for (int i = 0; i < 4; i++) {
        float inv_s = 64.0f * (float)(1 << i);
        k_upsample<<<4, 256>>>(ro, rd, zbuf[cur], sbuf[cur], PZN, S, inv_s);
        int Mn = R_RAYS * 16;
        sdf_forward_nostore(Mn, 16, PZN, ro, rd, X, PSDFN);
        k_merge<<<4, 256>>>(zbuf[cur], sbuf[cur], PZN, PSDFN, zbuf[1-cur], sbuf[1-cur], S);
        cur = 1 - cur;
        S += 16;
    }

    // ---- final forward ----
    M = (int)NPTS;
    k_dist_mid_pts<<<(M+255)/256, 256>>>(zbuf[cur], ro, rd, PP, PD);
    k_embed_c<1><<<(M*40+255)/256, 256>>>(PP, ro, rd, E.hi, E.lo, I4.hi, I4.lo, 256, 0, M,
                                          nullptr, nullptr);
    launch_bf3<1>(E, 40,   X.wb[0], 40,  sb[0], PNONE,0, H0.hi,H0.lo,256, PNONE,0,nullptr,nullptr, M,256,40);
    launch_bf3<1>(H0, 256, X.wb[1], 256, sb[1], PNONE,0, H1.hi,H1.lo,256, PNONE,0,nullptr,nullptr, M,256,256);
    launch_bf3<1>(H1, 256, X.wb[2], 256, sb[2], PNONE,0, H2.hi,H2.lo,256, PNONE,0,nullptr,nullptr, M,256,256);
    launch_bf3<6>(H2, 256, X.wb[3], 256, sb[3], PNONE,0, H3.hi,H3.lo,224, I4,256,nullptr,nullptr, M,217,256);
    launch_bf3<1>(I4, 256, X.wb[4], 256, sb[4], PNONE,0, A4.hi,A4.lo,256, PNONE,0,nullptr,nullptr, M,256,256);
    launch_bf3<1>(A4, 256, X.wb[5], 256, sb[5], PNONE,0, A5.hi,A5.lo,256, PNONE,0,nullptr,nullptr, M,256,256);
    launch_bf3<1>(A5, 256, X.wb[6], 256, sb[6], PNONE,0, A6.hi,A6.lo,256, PNONE,0,nullptr,nullptr, M,256,256);
    launch_bf3<4>(A6, 256, X.wb[7], 256, sb[7], PNONE,0, A7.hi,A7.lo,256, GP,256, sw[8],nullptr, M,256,256);
    launch_bf3<5>(A7, 256, X.wb[8], 256, sb[8], PNONE,0, PSDFO,nullptr,0, CIN,272,nullptr,nullptr, M,257,256);

    // ---- backward VJP (g_z7 already in GP from EPI4) ----
    launch_bf3<3>(GP, 256, X.wb[11], 256, nullptr, A6,256, GQ.hi,GQ.lo,256, PNONE,0,nullptr,nullptr, M,256,256);
    launch_bf3<3>(GQ, 256, X.wb[12], 256, nullptr, A5,256, GP.hi,GP.lo,256, PNONE,0,nullptr,nullptr, M,256,256);
    launch_bf3<3>(GP, 256, X.wb[13], 256, nullptr, A4,256, GQ.hi,GQ.lo,256, PNONE,0,nullptr,nullptr, M,256,256);
    launch_bf3<8>(GQ, 256, X.wb[14], 256, nullptr, H3,224, GP.hi,GP.lo,224, PNONE,0,nullptr,PGE, M,256,256);
    launch_bf3<3>(GP, 224, X.wb[15], 224, nullptr, H2,256, GQ.hi,GQ.lo,256, PNONE,0,nullptr,nullptr, M,256,224);
    launch_bf3<3>(GQ, 256, X.wb[16], 256, nullptr, H1,256, GP.hi,GP.lo,256, PNONE,0,nullptr,nullptr, M,256,256);
    launch_bf3<3>(GP, 256, X.wb[17], 256, nullptr, H0,256, GQ.hi,GQ.lo,256, PNONE,0,nullptr,nullptr, M,256,256);
    launch_bf3<0>(GQ, 256, X.wb[18], 256, nullptr, PNONE,0, PGEM,nullptr,39, PNONE,0,nullptr,nullptr, M,39,256);
    k_gradpts<<<(M+255)/256, 256>>>(PGEM, PGE, PP, PGR, M);

    // ---- compositing weights (alpha fused) ----
    k_ray_weights<<<4, 256>>>(PSDFO, PGR, PD, rd, var, PW);

    // ---- color net: cin -> relu GEMM -> fused rgb head (EPI 10) ----
    k_cin9<<<(M*20+255)/256, 256>>>(PP, rd, PGR, CIN.hi, CIN.lo, cb[2], PRGB, M);
    launch_bf3<2>(CIN, 272, X.wb[9], 272, cb[0], PNONE,0, GP.hi,GP.lo,256, PNONE,0,nullptr,nullptr, M,256,272);
    launch_bf3<10>(GP, 256, X.wb[10], 256, cb[1], PNONE,0, nullptr,nullptr,0, PNONE,0,
                   X.cw2raw, PRGB, M,256,256);
    k_reduce<<<4, 256>>>(PW, PRGB, out);
}